// round 4
// baseline (speedup 1.0000x reference)
#include <cuda_runtime.h>
#include <cuda_bf16.h>

#define BATCH 64
#define CH 8
#define NSTAGE 4

typedef unsigned long long u64;

__device__ __forceinline__ u64 pk2(float lo, float hi) {
    u64 r; asm("mov.b64 %0,{%1,%2};" : "=l"(r) : "f"(lo), "f"(hi)); return r;
}
__device__ __forceinline__ void fma2(u64& d, u64 a, u64 b) {
    asm("fma.rn.f32x2 %0,%1,%2,%0;" : "+l"(d) : "l"(a), "l"(b));
}
__device__ __forceinline__ float2 upk2(u64 v) {
    float2 r; asm("mov.b64 {%0,%1},%2;" : "=f"(r.x), "=f"(r.y) : "l"(v)); return r;
}

// ---------------- device scratch (static, no allocations) ----------------
__device__ float g_ctx[BATCH*32];
__device__ float g_wr[NSTAGE*BATCH*CH*CH*9];
__device__ float g_wt[NSTAGE*BATCH*CH*CH*16];
__device__ float g_wm[NSTAGE*BATCH*CH*CH*25];
__device__ float g_wo[BATCH*3*CH];
__device__ float g_br[NSTAGE*BATCH*CH];
__device__ float g_bt[NSTAGE*BATCH*CH];
__device__ float g_bm[NSTAGE*BATCH*CH];
__device__ float g_bo[BATCH*3];
__device__ float g_xA[BATCH*CH*128*128];
__device__ float g_xB[BATCH*CH*128*128];
__device__ float g_pos[BATCH*CH*128*128];
__device__ float g_neg[BATCH*CH*256*256];
__device__ float g_mul[BATCH*CH*256*256];
__device__ unsigned g_minpos[NSTAGE*BATCH*CH];
__device__ unsigned g_minneg[NSTAGE*BATCH*CH];
__device__ unsigned g_minmul[NSTAGE*BATCH*CH];

__device__ __forceinline__ float dln_f(float v, float mn) {
    float s = (v > 0.0f) ? 1.0f : -1.0f;
    float a = fabsf(v) - mn;
    return s * __logf(__logf(a + 2.718281828459045f) + 0.01f);
}

// ---------------- gather: ctx + initial x ----------------
__global__ void k_gather(const int* __restrict__ ids,
                         const float* __restrict__ cc,
                         const float* __restrict__ lat) {
    int t = blockIdx.x * blockDim.x + threadIdx.x;
    int T = gridDim.x * blockDim.x;
    for (int i = t; i < BATCH * 32; i += T) {
        int b = i >> 5;
        g_ctx[i] = cc[ids[b] * 32 + (i & 31)];
    }
    for (int i = t; i < BATCH * CH * 16 * 16; i += T) {
        int b = i >> 11;
        g_xA[i] = lat[ids[b] * (CH * 16 * 16) + (i & 2047)];
    }
}

// ---------------- min init (all stages at once) ----------------
__global__ void k_mininit() {
    int t = blockIdx.x * blockDim.x + threadIdx.x;
    if (t < NSTAGE * BATCH * CH) {
        g_minpos[t] = 0x7F800000u;
        g_minneg[t] = 0x7F800000u;
        g_minmul[t] = 0x7F800000u;
    }
}

// ---------------- dynamic weight computation ----------------
__global__ void k_weights(
    const float* __restrict__ Wr, const float* __restrict__ Ur, const float* __restrict__ Vr, const float* __restrict__ Br,
    const float* __restrict__ Wt, const float* __restrict__ Ut, const float* __restrict__ Vt, const float* __restrict__ Bt,
    const float* __restrict__ Wm, const float* __restrict__ Um, const float* __restrict__ Vm, const float* __restrict__ Bm,
    const float* __restrict__ Wo, const float* __restrict__ Uo, const float* __restrict__ Vo, const float* __restrict__ Bo)
{
    int inst = blockIdx.x, b = blockIdx.y, tid = threadIdx.x;
    __shared__ float sctx[32];
    __shared__ float su[128];
    __shared__ float sv[3200];
    if (tid < 32) sctx[tid] = g_ctx[b * 32 + tid];
    __syncthreads();

    int O, KK;
    const float *U, *V, *W, *Bb;
    float *gw, *gb;
    if (inst < 12) {
        int type = inst >> 2, stage = inst & 3;
        O = CH;
        if (type == 0)      { KK = 9;  U = Ur; V = Vr; W = Wr; Bb = Br; gw = g_wr; gb = g_br; }
        else if (type == 1) { KK = 16; U = Ut; V = Vt; W = Wt; Bb = Bt; gw = g_wt; gb = g_bt; }
        else                { KK = 25; U = Um; V = Vm; W = Wm; Bb = Bm; gw = g_wm; gb = g_bm; }
        int uLen = 16 * O, vLen = 16 * CH * KK;
        U  += (size_t)stage * 32 * uLen;
        V  += (size_t)stage * 32 * vLen;
        W  += (size_t)stage * O * CH * KK;
        Bb += (size_t)stage * 32 * O;
        gw += (size_t)(stage * BATCH + b) * O * CH * KK;
        gb += (size_t)(stage * BATCH + b) * O;
    } else {
        O = 3; KK = 1;
        U = Uo; V = Vo; W = Wo; Bb = Bo;
        gw = g_wo + b * 3 * CH;
        gb = g_bo + b * 3;
    }
    int uLen = 16 * O, vLen = 16 * CH * KK, IKK = CH * KK, wN = O * IKK;

    for (int j = tid; j < uLen; j += blockDim.x) {
        float s = 0.f;
        #pragma unroll
        for (int l = 0; l < 32; l++) s += sctx[l] * U[l * uLen + j];
        su[j] = s;
    }
    for (int j = tid; j < vLen; j += blockDim.x) {
        float s = 0.f;
        #pragma unroll
        for (int l = 0; l < 32; l++) s += sctx[l] * V[l * vLen + j];
        sv[j] = s;
    }
    __syncthreads();

    for (int widx = tid; widx < wN; widx += blockDim.x) {
        int o = widx / IKK, k = widx - o * IKK;
        float m = 0.f;
        #pragma unroll
        for (int r = 0; r < 16; r++) m += su[r * O + o] * sv[r * IKK + k];
        gw[widx] = W[widx] * (1.0f + m + 1e-3f);
    }
    if (tid < O) {
        float s = 0.f;
        #pragma unroll
        for (int l = 0; l < 32; l++) s += sctx[l] * Bb[l * O + tid];
        gb[tid] = s;
    }
}

// ---------------- conv3 packed: 3x3 s1 p1, tile (2*TWP)x8, f32x2 ----------------
template<int H, int TWP>
__device__ __forceinline__ void conv3p_body(char* smraw, const float* xb, int b,
                                            int bx, int by, int tid, int stage) {
    constexpr int TW = 2 * TWP;
    constexpr int IW = TW + 2;
    constexpr int IH = 10;
    float* sIn = (float*)smraw;                     // CH*IH*IW
    float2* sW2 = (float2*)(sIn + CH * IH * IW);    // CH*CH*9
    float* sB = (float*)(sW2 + CH * CH * 9);
    int x0t = bx * TW, y0 = by * 8;
    const float* wsrc = g_wr + (size_t)(stage * BATCH + b) * CH * CH * 9;
    for (int j = tid; j < CH * CH * 9; j += 256) { float w = wsrc[j]; sW2[j] = make_float2(w, w); }
    if (tid < CH) sB[tid] = g_br[(stage * BATCH + b) * CH + tid];
    for (int j = tid; j < CH * IH * IW; j += 256) {
        int i = j / (IH * IW);
        int rem = j - i * IH * IW;
        int r = rem / IW, c = rem - r * IW;
        int gy = y0 - 1 + r, gx = x0t - 1 + c;
        float v = 0.f;
        if ((unsigned)gy < (unsigned)H && (unsigned)gx < (unsigned)H)
            v = xb[i * H * H + gy * H + gx];
        sIn[j] = v;
    }
    __syncthreads();
    int lane = tid & 31, o = tid >> 5;
    float mn = 3.4e38f;
    if (lane < TWP) {
        u64 acc[8];
        float bias = sB[o];
        u64 pb = pk2(bias, bias);
        #pragma unroll
        for (int y = 0; y < 8; y++) acc[y] = pb;
        #pragma unroll
        for (int i = 0; i < CH; i++) {
            u64 ww[9];
            const u64* pw = (const u64*)(sW2 + (o * CH + i) * 9);
            #pragma unroll
            for (int k = 0; k < 9; k++) ww[k] = pw[k];
            #pragma unroll
            for (int r = 0; r < IH; r++) {
                const float2* row = (const float2*)(sIn + (i * IH + r) * IW) + lane;
                float2 e0 = row[0], e1 = row[1];
                u64 p0 = pk2(e0.x, e0.y), p1 = pk2(e0.y, e1.x), p2 = pk2(e1.x, e1.y);
                #pragma unroll
                for (int ky = 0; ky < 3; ky++) {
                    int y = r - ky;
                    if (y >= 0 && y < 8) {
                        fma2(acc[y], p0, ww[ky * 3 + 0]);
                        fma2(acc[y], p1, ww[ky * 3 + 1]);
                        fma2(acc[y], p2, ww[ky * 3 + 2]);
                    }
                }
            }
        }
        int bo = b * CH + o;
        float* outp = g_pos + (size_t)bo * H * H;
        #pragma unroll
        for (int y = 0; y < 8; y++) {
            float2 v = upk2(acc[y]);
            ((float2*)(outp + (y0 + y) * H))[(x0t >> 1) + lane] = v;
            mn = fminf(mn, fminf(fabsf(v.x), fabsf(v.y)));
        }
    }
    #pragma unroll
    for (int off = 16; off > 0; off >>= 1)
        mn = fminf(mn, __shfl_down_sync(0xFFFFFFFFu, mn, off));
    if (lane == 0) atomicMin(&g_minpos[stage * BATCH * CH + b * CH + o], __float_as_uint(mn));
}

// ---------------- convT 4x4 s2 p1 on -x, parity-decomposed (scalar) ----------------
template<int H>
__device__ __forceinline__ void convt_body(float* sm, const float* x, int b,
                                           int x0, int y0, int tid, int stage) {
    constexpr int OH = 2 * H;
    constexpr int TW = 32, TH = 8;
    constexpr int IWT = TW / 2 + 2;   // 18
    constexpr int IHT = TH / 2 + 2;   // 6
    float* sIn = sm;
    float* sW  = sm + CH * IHT * IWT;
    float* sB  = sW + CH * CH * 16;
    const float* wsrc = g_wt + (size_t)(stage * BATCH + b) * CH * CH * 16;
    if (tid < CH) sB[tid] = g_bt[(stage * BATCH + b) * CH + tid];
    for (int j = tid; j < CH * CH * 16; j += 256) sW[j] = wsrc[j];
    int ix0 = x0 / 2 - 1, iy0 = y0 / 2 - 1;
    for (int j = tid; j < CH * IHT * IWT; j += 256) {
        int i = j / (IHT * IWT);
        int rem = j - i * IHT * IWT;
        int r = rem / IWT, c = rem - r * IWT;
        int gy = iy0 + r, gx = ix0 + c;
        float v = 0.f;
        if ((unsigned)gy < (unsigned)H && (unsigned)gx < (unsigned)H)
            v = x[i * H * H + gy * H + gx];
        sIn[j] = v;
    }
    __syncthreads();

    int tx = tid & 31, o = tid >> 5;
    int px = tx & 1;
    int cA = (tx >> 1) + px;
    float acc[TH];
    float bias = sB[o];
    #pragma unroll
    for (int y = 0; y < TH; y++) acc[y] = bias;

    #pragma unroll
    for (int i = 0; i < CH; i++) {
        float wA[4], wB[4];
        #pragma unroll
        for (int ky = 0; ky < 4; ky++) {
            wA[ky] = sW[(o * CH + i) * 16 + ky * 4 + (3 - px)];
            wB[ky] = sW[(o * CH + i) * 16 + ky * 4 + (1 - px)];
        }
        float vA[IHT], vB[IHT];
        #pragma unroll
        for (int r = 0; r < IHT; r++) {
            vA[r] = sIn[(i * IHT + r) * IWT + cA];
            vB[r] = sIn[(i * IHT + r) * IWT + cA + 1];
        }
        #pragma unroll
        for (int ty = 0; ty < TH; ty++) {
            const int py = ty & 1;
            const int r = (ty >> 1) + py;
            acc[ty] -= vA[r]     * wA[3 - py]
                     + vB[r]     * wB[3 - py]
                     + vA[r + 1] * wA[1 - py]
                     + vB[r + 1] * wB[1 - py];
        }
    }

    int bo = b * CH + o;
    float* outp = g_neg + (size_t)bo * OH * OH;
    float mn = 3.4e38f;
    #pragma unroll
    for (int y = 0; y < TH; y++) {
        outp[(y0 + y) * OH + x0 + tx] = acc[y];
        mn = fminf(mn, fabsf(acc[y]));
    }
    #pragma unroll
    for (int off = 16; off > 0; off >>= 1)
        mn = fminf(mn, __shfl_down_sync(0xFFFFFFFFu, mn, off));
    if (tx == 0) atomicMin(&g_minneg[stage * BATCH * CH + bo], __float_as_uint(mn));
}

// ---------------- conv5 packed: 5x5 s1 p2 on fused bilinear(log(|x|+1)) ----------------
template<int H, int TWP>
__device__ __forceinline__ void conv5p_body(char* smraw, const float* xb, int b,
                                            int bx, int by, int tid, int stage) {
    constexpr int OH = 2 * H;
    constexpr int TW = 2 * TWP;
    constexpr int IW = TW + 4, IH = 12;
    constexpr int LW = TWP + 4, LH = 8;
    float* sLx = (float*)smraw;                      // CH*LH*LW
    float* sXu = sLx + CH * LH * LW;                 // CH*IH*IW
    float2* sW2 = (float2*)(sXu + CH * IH * IW);     // CH*CH*25
    float* sB = (float*)(sW2 + CH * CH * 25);
    int x0 = bx * TW, y0 = by * 8;
    const float* wsrc = g_wm + (size_t)(stage * BATCH + b) * CH * CH * 25;
    for (int j = tid; j < CH * CH * 25; j += 256) { float w = wsrc[j]; sW2[j] = make_float2(w, w); }
    if (tid < CH) sB[tid] = g_bm[(stage * BATCH + b) * CH + tid];

    int gyLo = ((y0 - 2) >> 1) - 1;
    int gxLo = ((x0 - 2) >> 1) - 1;
    for (int j = tid; j < CH * LH * LW; j += 256) {
        int i = j / (LH * LW);
        int rem = j - i * LH * LW;
        int r = rem / LW, c = rem - r * LW;
        int gy = gyLo + r, gx = gxLo + c;
        float v = 0.f;
        if ((unsigned)gy < (unsigned)H && (unsigned)gx < (unsigned)H)
            v = __logf(fabsf(xb[i * H * H + gy * H + gx]) + 1.0f);
        sLx[j] = v;
    }
    __syncthreads();
    for (int j = tid; j < CH * IH * IW; j += 256) {
        int i = j / (IH * IW);
        int rem = j - i * IH * IW;
        int r = rem / IW, c = rem - r * IW;
        int Y = y0 - 2 + r, X = x0 - 2 + c;
        float v = 0.f;
        if ((unsigned)Y < (unsigned)OH && (unsigned)X < (unsigned)OH) {
            int iy = Y >> 1, ix = X >> 1;
            int yo = (Y & 1) ? min(iy + 1, H - 1) : max(iy - 1, 0);
            int xo = (X & 1) ? min(ix + 1, H - 1) : max(ix - 1, 0);
            const float* L = sLx + i * LH * LW;
            int ry = iy - gyLo, ryo = yo - gyLo;
            int cx = ix - gxLo, cxo = xo - gxLo;
            v = 0.5625f * L[ry * LW + cx] + 0.1875f * L[ry * LW + cxo]
              + 0.1875f * L[ryo * LW + cx] + 0.0625f * L[ryo * LW + cxo];
        }
        sXu[j] = v;
    }
    __syncthreads();

    int lane = tid & 31, o = tid >> 5;
    float mn = 3.4e38f;
    if (lane < TWP) {
        u64 acc[8];
        float bias = sB[o];
        u64 pb = pk2(bias, bias);
        #pragma unroll
        for (int y = 0; y < 8; y++) acc[y] = pb;
        #pragma unroll
        for (int i = 0; i < CH; i++) {
            u64 ww[25];
            const u64* pw = (const u64*)(sW2 + (o * CH + i) * 25);
            #pragma unroll
            for (int k = 0; k < 25; k++) ww[k] = pw[k];
            #pragma unroll
            for (int r = 0; r < IH; r++) {
                const float2* row = (const float2*)(sXu + (i * IH + r) * IW) + lane;
                float2 e0 = row[0], e1 = row[1], e2 = row[2];
                u64 p0 = pk2(e0.x, e0.y), p1 = pk2(e0.y, e1.x), p2 = pk2(e1.x, e1.y);
                u64 p3 = pk2(e1.y, e2.x), p4 = pk2(e2.x, e2.y);
                #pragma unroll
                for (int ky = 0; ky < 5; ky++) {
                    int y = r - ky;
                    if (y >= 0 && y < 8) {
                        fma2(acc[y], p0, ww[ky * 5 + 0]);
                        fma2(acc[y], p1, ww[ky * 5 + 1]);
                        fma2(acc[y], p2, ww[ky * 5 + 2]);
                        fma2(acc[y], p3, ww[ky * 5 + 3]);
                        fma2(acc[y], p4, ww[ky * 5 + 4]);
                    }
                }
            }
        }
        int bo = b * CH + o;
        float* outp = g_mul + (size_t)bo * OH * OH;
        #pragma unroll
        for (int y = 0; y < 8; y++) {
            float2 v = upk2(acc[y]);
            ((float2*)(outp + (y0 + y) * OH))[(x0 >> 1) + lane] = v;
            mn = fminf(mn, fminf(fabsf(v.x), fabsf(v.y)));
        }
    }
    #pragma unroll
    for (int off = 16; off > 0; off >>= 1)
        mn = fminf(mn, __shfl_down_sync(0xFFFFFFFFu, mn, off));
    if (lane == 0) atomicMin(&g_minmul[stage * BATCH * CH + b * CH + o], __float_as_uint(mn));
}

// ---------------- per-stage superkernel ----------------
template<int STAGE>
__global__ __launch_bounds__(256) void k_stage(int srcA) {
    constexpr int H = 16 << STAGE;
    constexpr int OH = 2 * H;
    constexpr int TWP3 = (STAGE == 0) ? 8 : (STAGE == 1 ? 16 : 32);
    constexpr int TWP5 = (STAGE == 0) ? 16 : 32;
    __shared__ __align__(16) char smem[48256];
    int role = blockIdx.z >> 6;
    int b = blockIdx.z & 63;
    const float* xb = (srcA ? g_xA : g_xB) + (size_t)b * CH * H * H;
    if (role == 0) {
        if ((int)blockIdx.x >= H / (2 * TWP3) || (int)blockIdx.y >= H / 8) return;
        conv3p_body<H, TWP3>(smem, xb, b, blockIdx.x, blockIdx.y, threadIdx.x, STAGE);
    } else if (role == 1) {
        if ((int)blockIdx.x >= OH / 32) return;
        convt_body<H>((float*)smem, xb, b, blockIdx.x * 32, blockIdx.y * 8, threadIdx.x, STAGE);
    } else {
        if ((int)blockIdx.x >= OH / (2 * TWP5)) return;
        conv5p_body<H, TWP5>(smem, xb, b, blockIdx.x, blockIdx.y, threadIdx.x, STAGE);
    }
}

// ---------------- combine (stages 0-2): writes next x ----------------
template<int H>
__global__ __launch_bounds__(256) void k_combine(int stage, int dstA) {
    constexpr int OH = 2 * H;
    constexpr int NH = H * H;
    int t = blockIdx.x * 256 + threadIdx.x;
    if (t >= BATCH * CH * NH) return;
    int bc = t / NH;
    int rem = t - bc * NH;
    int y = rem / H, x = rem - y * H;
    float mnp = __uint_as_float(g_minpos[stage * BATCH * CH + bc]);
    float mnn = __uint_as_float(g_minneg[stage * BATCH * CH + bc]);
    float mnm = __uint_as_float(g_minmul[stage * BATCH * CH + bc]);
    float dp = dln_f(g_pos[(size_t)bc * NH + rem], mnp);
    const float2* neg2 = (const float2*)(g_neg + (size_t)bc * OH * OH);
    const float2* mul2 = (const float2*)(g_mul + (size_t)bc * OH * OH);
    float2* dst2 = (float2*)((dstA ? g_xA : g_xB) + (size_t)bc * OH * OH);
    #pragma unroll
    for (int dy = 0; dy < 2; dy++) {
        int row = 2 * y + dy;
        float2 n = neg2[row * (OH / 2) + x];
        float2 m = mul2[row * (OH / 2) + x];
        float2 r;
        r.x = (dp + dln_f(n.x, mnn)) * dln_f(m.x, mnm);
        r.y = (dp + dln_f(n.y, mnn)) * dln_f(m.y, mnm);
        dst2[row * (OH / 2) + x] = r;
    }
}

// ---------------- stage-3 combine fused with final 1x1 conv -> 3 ch ----------------
__global__ __launch_bounds__(256) void k_comfinal(float* __restrict__ out) {
    constexpr int H = 128, OH = 256, NH = H * H;
    constexpr int stage = 3;
    int t = blockIdx.x * 256 + threadIdx.x;
    int b = t / NH;
    int rem = t - b * NH;
    int y = rem / H, x = rem - y * H;

    float wo[3 * CH], bo3[3];
    #pragma unroll
    for (int k = 0; k < 3 * CH; k++) wo[k] = g_wo[b * 3 * CH + k];
    #pragma unroll
    for (int k = 0; k < 3; k++) bo3[k] = g_bo[b * 3 + k];

    float dp[CH], mnn[CH], mnm[CH];
    #pragma unroll
    for (int c = 0; c < CH; c++) {
        int bc = b * CH + c;
        float mnp = __uint_as_float(g_minpos[stage * BATCH * CH + bc]);
        mnn[c] = __uint_as_float(g_minneg[stage * BATCH * CH + bc]);
        mnm[c] = __uint_as_float(g_minmul[stage * BATCH * CH + bc]);
        dp[c] = dln_f(g_pos[(size_t)bc * NH + rem], mnp);
    }

    #pragma unroll
    for (int dy = 0; dy < 2; dy++) {
        int row = 2 * y + dy;
        float2 acc[3];
        #pragma unroll
        for (int o = 0; o < 3; o++) { acc[o].x = bo3[o]; acc[o].y = bo3[o]; }
        #pragma unroll
        for (int c = 0; c < CH; c++) {
            int bc = b * CH + c;
            const float2* neg2 = (const float2*)(g_neg + (size_t)bc * OH * OH);
            const float2* mul2 = (const float2*)(g_mul + (size_t)bc * OH * OH);
            float2 n = neg2[row * (OH / 2) + x];
            float2 m = mul2[row * (OH / 2) + x];
            float xv0 = (dp[c] + dln_f(n.x, mnn[c])) * dln_f(m.x, mnm[c]);
            float xv1 = (dp[c] + dln_f(n.y, mnn[c])) * dln_f(m.y, mnm[c]);
            #pragma unroll
            for (int o = 0; o < 3; o++) {
                acc[o].x += wo[o * CH + c] * xv0;
                acc[o].y += wo[o * CH + c] * xv1;
            }
        }
        #pragma unroll
        for (int o = 0; o < 3; o++) {
            float2* dst2 = (float2*)(out + ((size_t)b * 3 + o) * OH * OH);
            dst2[row * (OH / 2) + x] = acc[o];
        }
    }
}

// ---------------- launcher ----------------
extern "C" void kernel_launch(void* const* d_in, const int* in_sizes, int n_in,
                              void* d_out, int out_size) {
    const int*   ids = (const int*)  d_in[0];
    const float* cc  = (const float*)d_in[1];
    const float* lat = (const float*)d_in[2];
    const float* Wr = (const float*)d_in[3];
    const float* Ur = (const float*)d_in[4];
    const float* Vr = (const float*)d_in[5];
    const float* Br = (const float*)d_in[6];
    const float* Wt = (const float*)d_in[7];
    const float* Ut = (const float*)d_in[8];
    const float* Vt = (const float*)d_in[9];
    const float* Bt = (const float*)d_in[10];
    const float* Wm = (const float*)d_in[11];
    const float* Um = (const float*)d_in[12];
    const float* Vm = (const float*)d_in[13];
    const float* Bm = (const float*)d_in[14];
    const float* Wo = (const float*)d_in[15];
    const float* Uo = (const float*)d_in[16];
    const float* Vo = (const float*)d_in[17];
    const float* Bo = (const float*)d_in[18];

    k_gather<<<64, 256>>>(ids, cc, lat);
    k_weights<<<dim3(13, 64), 128>>>(Wr, Ur, Vr, Br, Wt, Ut, Vt, Bt,
                                     Wm, Um, Vm, Bm, Wo, Uo, Vo, Bo);
    k_mininit<<<(NSTAGE * BATCH * CH + 255) / 256, 256>>>();

    // stage 0: H=16, OH=32
    k_stage<0><<<dim3(1, 4, 192), 256>>>(1);
    k_combine<16><<<(BATCH * CH * 16 * 16 + 255) / 256, 256>>>(0, 0);
    // stage 1: H=32, OH=64
    k_stage<1><<<dim3(2, 8, 192), 256>>>(0);
    k_combine<32><<<(BATCH * CH * 32 * 32 + 255) / 256, 256>>>(1, 1);
    // stage 2: H=64, OH=128
    k_stage<2><<<dim3(4, 16, 192), 256>>>(1);
    k_combine<64><<<(BATCH * CH * 64 * 64 + 255) / 256, 256>>>(2, 0);
    // stage 3: H=128, OH=256 (combine fused with final 1x1)
    k_stage<3><<<dim3(8, 32, 192), 256>>>(0);
    k_comfinal<<<(BATCH * 128 * 128 + 255) / 256, 256>>>((float*)d_out);
}

// round 5
// speedup vs baseline: 1.1737x; 1.1737x over previous
#include <cuda_runtime.h>
#include <cuda_bf16.h>

#define BATCH 64
#define CH 8
#define NSTAGE 4

typedef unsigned long long u64;

__device__ __forceinline__ u64 pk2(float lo, float hi) {
    u64 r; asm("mov.b64 %0,{%1,%2};" : "=l"(r) : "f"(lo), "f"(hi)); return r;
}
__device__ __forceinline__ void fma2(u64& d, u64 a, u64 b) {
    asm("fma.rn.f32x2 %0,%1,%2,%0;" : "+l"(d) : "l"(a), "l"(b));
}
__device__ __forceinline__ float2 upk2(u64 v) {
    float2 r; asm("mov.b64 {%0,%1},%2;" : "=f"(r.x), "=f"(r.y) : "l"(v)); return r;
}

// ---------------- device scratch (static, no allocations) ----------------
__device__ float g_ctx[BATCH*32];
__device__ float g_wr[NSTAGE*BATCH*CH*CH*9];
__device__ float g_wt[NSTAGE*BATCH*CH*CH*16];
__device__ float g_wm[NSTAGE*BATCH*CH*CH*25];
__device__ float g_wo[BATCH*3*CH];
__device__ float g_br[NSTAGE*BATCH*CH];
__device__ float g_bt[NSTAGE*BATCH*CH];
__device__ float g_bm[NSTAGE*BATCH*CH];
__device__ float g_bo[BATCH*3];
__device__ __align__(16) float g_xA[BATCH*CH*128*128];
__device__ __align__(16) float g_xB[BATCH*CH*128*128];
__device__ __align__(16) float g_pos[BATCH*CH*128*128];
__device__ __align__(16) float g_neg[BATCH*CH*256*256];
__device__ __align__(16) float g_mul[BATCH*CH*256*256];
__device__ unsigned g_minpos[NSTAGE*BATCH*CH];
__device__ unsigned g_minneg[NSTAGE*BATCH*CH];
__device__ unsigned g_minmul[NSTAGE*BATCH*CH];

__device__ __forceinline__ float dln_f(float v, float mn) {
    float s = (v > 0.0f) ? 1.0f : -1.0f;
    float a = fabsf(v) - mn;
    return s * __logf(__logf(a + 2.718281828459045f) + 0.01f);
}

// ---------------- gather ----------------
__global__ void k_gather(const int* __restrict__ ids,
                         const float* __restrict__ cc,
                         const float* __restrict__ lat) {
    int t = blockIdx.x * blockDim.x + threadIdx.x;
    int T = gridDim.x * blockDim.x;
    for (int i = t; i < BATCH * 32; i += T) {
        int b = i >> 5;
        g_ctx[i] = cc[ids[b] * 32 + (i & 31)];
    }
    for (int i = t; i < BATCH * CH * 16 * 16; i += T) {
        int b = i >> 11;
        g_xA[i] = lat[ids[b] * (CH * 16 * 16) + (i & 2047)];
    }
}

__global__ void k_mininit() {
    int t = blockIdx.x * blockDim.x + threadIdx.x;
    if (t < NSTAGE * BATCH * CH) {
        g_minpos[t] = 0x7F800000u;
        g_minneg[t] = 0x7F800000u;
        g_minmul[t] = 0x7F800000u;
    }
}

// ---------------- dynamic weight computation ----------------
__global__ void k_weights(
    const float* __restrict__ Wr, const float* __restrict__ Ur, const float* __restrict__ Vr, const float* __restrict__ Br,
    const float* __restrict__ Wt, const float* __restrict__ Ut, const float* __restrict__ Vt, const float* __restrict__ Bt,
    const float* __restrict__ Wm, const float* __restrict__ Um, const float* __restrict__ Vm, const float* __restrict__ Bm,
    const float* __restrict__ Wo, const float* __restrict__ Uo, const float* __restrict__ Vo, const float* __restrict__ Bo)
{
    int inst = blockIdx.x, b = blockIdx.y, tid = threadIdx.x;
    __shared__ float sctx[32];
    __shared__ float su[128];
    __shared__ float sv[3200];
    if (tid < 32) sctx[tid] = g_ctx[b * 32 + tid];
    __syncthreads();

    int O, KK;
    const float *U, *V, *W, *Bb;
    float *gw, *gb;
    if (inst < 12) {
        int type = inst >> 2, stage = inst & 3;
        O = CH;
        if (type == 0)      { KK = 9;  U = Ur; V = Vr; W = Wr; Bb = Br; gw = g_wr; gb = g_br; }
        else if (type == 1) { KK = 16; U = Ut; V = Vt; W = Wt; Bb = Bt; gw = g_wt; gb = g_bt; }
        else                { KK = 25; U = Um; V = Vm; W = Wm; Bb = Bm; gw = g_wm; gb = g_bm; }
        int uLen = 16 * O, vLen = 16 * CH * KK;
        U  += (size_t)stage * 32 * uLen;
        V  += (size_t)stage * 32 * vLen;
        W  += (size_t)stage * O * CH * KK;
        Bb += (size_t)stage * 32 * O;
        gw += (size_t)(stage * BATCH + b) * O * CH * KK;
        gb += (size_t)(stage * BATCH + b) * O;
    } else {
        O = 3; KK = 1;
        U = Uo; V = Vo; W = Wo; Bb = Bo;
        gw = g_wo + b * 3 * CH;
        gb = g_bo + b * 3;
    }
    int uLen = 16 * O, vLen = 16 * CH * KK, IKK = CH * KK, wN = O * IKK;

    for (int j = tid; j < uLen; j += blockDim.x) {
        float s = 0.f;
        #pragma unroll
        for (int l = 0; l < 32; l++) s += sctx[l] * U[l * uLen + j];
        su[j] = s;
    }
    for (int j = tid; j < vLen; j += blockDim.x) {
        float s = 0.f;
        #pragma unroll
        for (int l = 0; l < 32; l++) s += sctx[l] * V[l * vLen + j];
        sv[j] = s;
    }
    __syncthreads();

    for (int widx = tid; widx < wN; widx += blockDim.x) {
        int o = widx / IKK, k = widx - o * IKK;
        float m = 0.f;
        #pragma unroll
        for (int r = 0; r < 16; r++) m += su[r * O + o] * sv[r * IKK + k];
        gw[widx] = W[widx] * (1.0f + m + 1e-3f);
    }
    if (tid < O) {
        float s = 0.f;
        #pragma unroll
        for (int l = 0; l < 32; l++) s += sctx[l] * Bb[l * O + tid];
        gb[tid] = s;
    }
}

// ---------------- conv3 packed f32x2, SPLIT-lane ----------------
template<int H, int TWP, int SPLIT>
__device__ __forceinline__ void conv3p_body(float* smraw, const float* xb, int b,
                                            int bx, int by, int tid, int stage) {
    constexpr int TW = 2 * TWP;
    constexpr int THT = 8 / SPLIT;
    constexpr int IW = TW + 2;
    constexpr int IH = 10;
    float* sIn = smraw;                              // CH*IH*IW
    float2* sW2 = (float2*)(sIn + CH * IH * IW);     // CH*CH*9
    float* sB = (float*)(sW2 + CH * CH * 9);
    int x0t = bx * TW, y0 = by * 8;
    const float* wsrc = g_wr + (size_t)(stage * BATCH + b) * CH * CH * 9;
    for (int j = tid; j < CH * CH * 9; j += 256) { float w = wsrc[j]; sW2[j] = make_float2(w, w); }
    if (tid < CH) sB[tid] = g_br[(stage * BATCH + b) * CH + tid];
    for (int j = tid; j < CH * IH * IW; j += 256) {
        int i = j / (IH * IW);
        int rem = j - i * IH * IW;
        int r = rem / IW, c = rem - r * IW;
        int gy = y0 - 1 + r, gx = x0t - 1 + c;
        float v = 0.f;
        if ((unsigned)gy < (unsigned)H && (unsigned)gx < (unsigned)H)
            v = xb[i * H * H + gy * H + gx];
        sIn[j] = v;
    }
    __syncthreads();
    int lane = tid & 31, o = tid >> 5;
    int xp = lane & (TWP - 1);
    int L0 = (lane / TWP) * THT;

    u64 acc[THT];
    float bias = sB[o];
    u64 pb = pk2(bias, bias);
    #pragma unroll
    for (int y = 0; y < THT; y++) acc[y] = pb;

    #pragma unroll
    for (int i = 0; i < CH; i++) {
        u64 ww[9];
        const u64* pw = (const u64*)(sW2 + (o * CH + i) * 9);
        #pragma unroll
        for (int k = 0; k < 9; k++) ww[k] = pw[k];
        #pragma unroll
        for (int rl = 0; rl < THT + 2; rl++) {
            const float2* row = (const float2*)(sIn + (i * IH + L0 + rl) * IW) + xp;
            float2 e0 = row[0], e1 = row[1];
            u64 p[3];
            p[0] = pk2(e0.x, e0.y); p[1] = pk2(e0.y, e1.x); p[2] = pk2(e1.x, e1.y);
            #pragma unroll
            for (int kx = 0; kx < 3; kx++) {
                #pragma unroll
                for (int ky = 0; ky < 3; ky++) {
                    int ly = rl - ky;
                    if (ly >= 0 && ly < THT)
                        fma2(acc[ly], p[kx], ww[ky * 3 + kx]);
                }
            }
        }
    }
    int bo = b * CH + o;
    float* outp = g_pos + (size_t)bo * H * H;
    float mn = 3.4e38f;
    #pragma unroll
    for (int y = 0; y < THT; y++) {
        float2 v = upk2(acc[y]);
        ((float2*)(outp + (y0 + L0 + y) * H))[(x0t >> 1) + xp] = v;
        mn = fminf(mn, fminf(fabsf(v.x), fabsf(v.y)));
    }
    #pragma unroll
    for (int off = 16; off > 0; off >>= 1)
        mn = fminf(mn, __shfl_down_sync(0xFFFFFFFFu, mn, off));
    if (lane == 0) atomicMin(&g_minpos[stage * BATCH * CH + bo], __float_as_uint(mn));
}

// ---------------- convT 4x4 s2 p1 on -x, parity-decomposed (scalar) ----------------
template<int H>
__device__ __forceinline__ void convt_body(float* sm, const float* x, int b,
                                           int x0, int y0, int tid, int stage) {
    constexpr int OH = 2 * H;
    constexpr int TW = 32, TH = 8;
    constexpr int IWT = TW / 2 + 2;
    constexpr int IHT = TH / 2 + 2;
    float* sIn = sm;
    float* sW  = sm + CH * IHT * IWT;
    float* sB  = sW + CH * CH * 16;
    const float* wsrc = g_wt + (size_t)(stage * BATCH + b) * CH * CH * 16;
    if (tid < CH) sB[tid] = g_bt[(stage * BATCH + b) * CH + tid];
    for (int j = tid; j < CH * CH * 16; j += 256) sW[j] = wsrc[j];
    int ix0 = x0 / 2 - 1, iy0 = y0 / 2 - 1;
    for (int j = tid; j < CH * IHT * IWT; j += 256) {
        int i = j / (IHT * IWT);
        int rem = j - i * IHT * IWT;
        int r = rem / IWT, c = rem - r * IWT;
        int gy = iy0 + r, gx = ix0 + c;
        float v = 0.f;
        if ((unsigned)gy < (unsigned)H && (unsigned)gx < (unsigned)H)
            v = x[i * H * H + gy * H + gx];
        sIn[j] = v;
    }
    __syncthreads();

    int tx = tid & 31, o = tid >> 5;
    int px = tx & 1;
    int cA = (tx >> 1) + px;
    float acc[TH];
    float bias = sB[o];
    #pragma unroll
    for (int y = 0; y < TH; y++) acc[y] = bias;

    #pragma unroll
    for (int i = 0; i < CH; i++) {
        float wA[4], wB[4];
        #pragma unroll
        for (int ky = 0; ky < 4; ky++) {
            wA[ky] = sW[(o * CH + i) * 16 + ky * 4 + (3 - px)];
            wB[ky] = sW[(o * CH + i) * 16 + ky * 4 + (1 - px)];
        }
        float vA[IHT], vB[IHT];
        #pragma unroll
        for (int r = 0; r < IHT; r++) {
            vA[r] = sIn[(i * IHT + r) * IWT + cA];
            vB[r] = sIn[(i * IHT + r) * IWT + cA + 1];
        }
        #pragma unroll
        for (int ty = 0; ty < TH; ty++) {
            const int py = ty & 1;
            const int r = (ty >> 1) + py;
            acc[ty] -= vA[r]     * wA[3 - py]
                     + vB[r]     * wB[3 - py]
                     + vA[r + 1] * wA[1 - py]
                     + vB[r + 1] * wB[1 - py];
        }
    }

    int bo = b * CH + o;
    float* outp = g_neg + (size_t)bo * OH * OH;
    float mn = 3.4e38f;
    #pragma unroll
    for (int y = 0; y < TH; y++) {
        outp[(y0 + y) * OH + x0 + tx] = acc[y];
        mn = fminf(mn, fabsf(acc[y]));
    }
    #pragma unroll
    for (int off = 16; off > 0; off >>= 1)
        mn = fminf(mn, __shfl_down_sync(0xFFFFFFFFu, mn, off));
    if (tx == 0) atomicMin(&g_minneg[stage * BATCH * CH + bo], __float_as_uint(mn));
}

// ---------------- conv5 packed f32x2, SPLIT=2 (TWP=16, TW=32), fused log+bilinear ----------------
template<int H>
__device__ __forceinline__ void conv5p_body(float* smraw, const float* xb, int b,
                                            int bx, int by, int tid, int stage) {
    constexpr int OH = 2 * H;
    constexpr int TWP = 16, THT = 4;
    constexpr int TW = 2 * TWP;
    constexpr int IW = TW + 4, IH = 12;
    constexpr int LW = TW / 2 + 4, LH = 8;
    float* sLx = smraw;                              // CH*LH*LW
    float* sXu = sLx + CH * LH * LW;                 // CH*IH*IW
    float2* sW2 = (float2*)(sXu + CH * IH * IW);     // CH*CH*25
    float* sB = (float*)(sW2 + CH * CH * 25);
    int x0 = bx * TW, y0 = by * 8;
    const float* wsrc = g_wm + (size_t)(stage * BATCH + b) * CH * CH * 25;
    for (int j = tid; j < CH * CH * 25; j += 256) { float w = wsrc[j]; sW2[j] = make_float2(w, w); }
    if (tid < CH) sB[tid] = g_bm[(stage * BATCH + b) * CH + tid];

    int gyLo = ((y0 - 2) >> 1) - 1;
    int gxLo = ((x0 - 2) >> 1) - 1;
    for (int j = tid; j < CH * LH * LW; j += 256) {
        int i = j / (LH * LW);
        int rem = j - i * LH * LW;
        int r = rem / LW, c = rem - r * LW;
        int gy = gyLo + r, gx = gxLo + c;
        float v = 0.f;
        if ((unsigned)gy < (unsigned)H && (unsigned)gx < (unsigned)H)
            v = __logf(fabsf(xb[i * H * H + gy * H + gx]) + 1.0f);
        sLx[j] = v;
    }
    __syncthreads();
    for (int j = tid; j < CH * IH * IW; j += 256) {
        int i = j / (IH * IW);
        int rem = j - i * IH * IW;
        int r = rem / IW, c = rem - r * IW;
        int Y = y0 - 2 + r, X = x0 - 2 + c;
        float v = 0.f;
        if ((unsigned)Y < (unsigned)OH && (unsigned)X < (unsigned)OH) {
            int iy = Y >> 1, ix = X >> 1;
            int yo = (Y & 1) ? min(iy + 1, H - 1) : max(iy - 1, 0);
            int xo = (X & 1) ? min(ix + 1, H - 1) : max(ix - 1, 0);
            const float* L = sLx + i * LH * LW;
            int ry = iy - gyLo, ryo = yo - gyLo;
            int cx = ix - gxLo, cxo = xo - gxLo;
            v = 0.5625f * L[ry * LW + cx] + 0.1875f * L[ry * LW + cxo]
              + 0.1875f * L[ryo * LW + cx] + 0.0625f * L[ryo * LW + cxo];
        }
        sXu[j] = v;
    }
    __syncthreads();

    int lane = tid & 31, o = tid >> 5;
    int xp = lane & (TWP - 1);
    int L0 = (lane / TWP) * THT;

    u64 acc[THT];
    float bias = sB[o];
    u64 pb = pk2(bias, bias);
    #pragma unroll
    for (int y = 0; y < THT; y++) acc[y] = pb;

    #pragma unroll
    for (int i = 0; i < CH; i++) {
        u64 ww[25];
        const u64* pw = (const u64*)(sW2 + (o * CH + i) * 25);
        #pragma unroll
        for (int k = 0; k < 25; k++) ww[k] = pw[k];
        #pragma unroll
        for (int rl = 0; rl < THT + 4; rl++) {
            const float2* row = (const float2*)(sXu + (i * IH + L0 + rl) * IW) + xp;
            float2 e0 = row[0], e1 = row[1], e2 = row[2];
            u64 p[5];
            p[0] = pk2(e0.x, e0.y); p[1] = pk2(e0.y, e1.x); p[2] = pk2(e1.x, e1.y);
            p[3] = pk2(e1.y, e2.x); p[4] = pk2(e2.x, e2.y);
            #pragma unroll
            for (int kx = 0; kx < 5; kx++) {
                #pragma unroll
                for (int ky = 0; ky < 5; ky++) {
                    int ly = rl - ky;
                    if (ly >= 0 && ly < THT)
                        fma2(acc[ly], p[kx], ww[ky * 5 + kx]);
                }
            }
        }
    }
    int bo = b * CH + o;
    float* outp = g_mul + (size_t)bo * OH * OH;
    float mn = 3.4e38f;
    #pragma unroll
    for (int y = 0; y < THT; y++) {
        float2 v = upk2(acc[y]);
        ((float2*)(outp + (y0 + L0 + y) * OH))[(x0 >> 1) + xp] = v;
        mn = fminf(mn, fminf(fabsf(v.x), fabsf(v.y)));
    }
    #pragma unroll
    for (int off = 16; off > 0; off >>= 1)
        mn = fminf(mn, __shfl_down_sync(0xFFFFFFFFu, mn, off));
    if (lane == 0) atomicMin(&g_minmul[stage * BATCH * CH + bo], __float_as_uint(mn));
}

// ---------------- per-stage superkernel ----------------
template<int STAGE>
__global__ __launch_bounds__(256) void k_stage(int srcA) {
    constexpr int H = 16 << STAGE;
    constexpr int OH = 2 * H;
    constexpr int TWP3 = (STAGE == 0) ? 8 : (STAGE == 1 ? 16 : 32);
    constexpr int SPL3 = 32 / TWP3 / ((STAGE >= 2) ? 1 : 1);   // TWP3*SPLIT=32
    constexpr int SPLIT3 = 32 / TWP3;
    constexpr int TW3 = 2 * TWP3;
    __shared__ __align__(16) float smem[7944];
    int role = blockIdx.z >> 6;
    int b = blockIdx.z & 63;
    (void)SPL3;
    const float* xb = (srcA ? g_xA : g_xB) + (size_t)b * CH * H * H;
    if (role == 0) {
        if ((int)blockIdx.x >= H / TW3 || (int)blockIdx.y >= H / 8) return;
        conv3p_body<H, TWP3, SPLIT3>(smem, xb, b, blockIdx.x, blockIdx.y, threadIdx.x, STAGE);
    } else if (role == 1) {
        convt_body<H>(smem, xb, b, blockIdx.x * 32, blockIdx.y * 8, threadIdx.x, STAGE);
    } else {
        conv5p_body<H>(smem, xb, b, blockIdx.x, blockIdx.y, threadIdx.x, STAGE);
    }
}

// ---------------- combine (stages 0-2) ----------------
template<int H>
__global__ __launch_bounds__(256) void k_combine(int stage, int dstA) {
    constexpr int OH = 2 * H;
    constexpr int NH = H * H;
    int t = blockIdx.x * 256 + threadIdx.x;
    if (t >= BATCH * CH * NH) return;
    int bc = t / NH;
    int rem = t - bc * NH;
    int y = rem / H, x = rem - y * H;
    float mnp = __uint_as_float(g_minpos[stage * BATCH * CH + bc]);
    float mnn = __uint_as_float(g_minneg[stage * BATCH * CH + bc]);
    float mnm = __uint_as_float(g_minmul[stage * BATCH * CH + bc]);
    float dp = dln_f(g_pos[(size_t)bc * NH + rem], mnp);
    const float2* neg2 = (const float2*)(g_neg + (size_t)bc * OH * OH);
    const float2* mul2 = (const float2*)(g_mul + (size_t)bc * OH * OH);
    float2* dst2 = (float2*)((dstA ? g_xA : g_xB) + (size_t)bc * OH * OH);
    #pragma unroll
    for (int dy = 0; dy < 2; dy++) {
        int row = 2 * y + dy;
        float2 n = neg2[row * (OH / 2) + x];
        float2 m = mul2[row * (OH / 2) + x];
        float2 r;
        r.x = (dp + dln_f(n.x, mnn)) * dln_f(m.x, mnm);
        r.y = (dp + dln_f(n.y, mnn)) * dln_f(m.y, mnm);
        dst2[row * (OH / 2) + x] = r;
    }
}

// ---------------- stage-3 combine fused with final 1x1 conv -> 3 ch ----------------
__global__ __launch_bounds__(256) void k_comfinal(float* __restrict__ out) {
    constexpr int H = 128, OH = 256, NH = H * H;
    constexpr int stage = 3;
    int t = blockIdx.x * 256 + threadIdx.x;
    int b = t / NH;
    int rem = t - b * NH;
    int y = rem / H, x = rem - y * H;

    float wo[3 * CH], bo3[3];
    #pragma unroll
    for (int k = 0; k < 3 * CH; k++) wo[k] = g_wo[b * 3 * CH + k];
    #pragma unroll
    for (int k = 0; k < 3; k++) bo3[k] = g_bo[b * 3 + k];

    float dp[CH], mnn[CH], mnm[CH];
    #pragma unroll
    for (int c = 0; c < CH; c++) {
        int bc = b * CH + c;
        float mnp = __uint_as_float(g_minpos[stage * BATCH * CH + bc]);
        mnn[c] = __uint_as_float(g_minneg[stage * BATCH * CH + bc]);
        mnm[c] = __uint_as_float(g_minmul[stage * BATCH * CH + bc]);
        dp[c] = dln_f(g_pos[(size_t)bc * NH + rem], mnp);
    }

    #pragma unroll
    for (int dy = 0; dy < 2; dy++) {
        int row = 2 * y + dy;
        float2 acc[3];
        #pragma unroll
        for (int o = 0; o < 3; o++) { acc[o].x = bo3[o]; acc[o].y = bo3[o]; }
        #pragma unroll
        for (int c = 0; c < CH; c++) {
            int bc = b * CH + c;
            const float2* neg2 = (const float2*)(g_neg + (size_t)bc * OH * OH);
            const float2* mul2 = (const float2*)(g_mul + (size_t)bc * OH * OH);
            float2 n = neg2[row * (OH / 2) + x];
            float2 m = mul2[row * (OH / 2) + x];
            float xv0 = (dp[c] + dln_f(n.x, mnn[c])) * dln_f(m.x, mnm[c]);
            float xv1 = (dp[c] + dln_f(n.y, mnn[c])) * dln_f(m.y, mnm[c]);
            #pragma unroll
            for (int o = 0; o < 3; o++) {
                acc[o].x += wo[o * CH + c] * xv0;
                acc[o].y += wo[o * CH + c] * xv1;
            }
        }
        #pragma unroll
        for (int o = 0; o < 3; o++) {
            float2* dst2 = (float2*)(out + ((size_t)b * 3 + o) * OH * OH);
            dst2[row * (OH / 2) + x] = acc[o];
        }
    }
}

// ---------------- launcher ----------------
extern "C" void kernel_launch(void* const* d_in, const int* in_sizes, int n_in,
                              void* d_out, int out_size) {
    const int*   ids = (const int*)  d_in[0];
    const float* cc  = (const float*)d_in[1];
    const float* lat = (const float*)d_in[2];
    const float* Wr = (const float*)d_in[3];
    const float* Ur = (const float*)d_in[4];
    const float* Vr = (const float*)d_in[5];
    const float* Br = (const float*)d_in[6];
    const float* Wt = (const float*)d_in[7];
    const float* Ut = (const float*)d_in[8];
    const float* Vt = (const float*)d_in[9];
    const float* Bt = (const float*)d_in[10];
    const float* Wm = (const float*)d_in[11];
    const float* Um = (const float*)d_in[12];
    const float* Vm = (const float*)d_in[13];
    const float* Bm = (const float*)d_in[14];
    const float* Wo = (const float*)d_in[15];
    const float* Uo = (const float*)d_in[16];
    const float* Vo = (const float*)d_in[17];
    const float* Bo = (const float*)d_in[18];

    k_gather<<<64, 256>>>(ids, cc, lat);
    k_weights<<<dim3(13, 64), 128>>>(Wr, Ur, Vr, Br, Wt, Ut, Vt, Bt,
                                     Wm, Um, Vm, Bm, Wo, Uo, Vo, Bo);
    k_mininit<<<(NSTAGE * BATCH * CH + 255) / 256, 256>>>();

    // stage 0: H=16, OH=32
    k_stage<0><<<dim3(1, 4, 192), 256>>>(1);
    k_combine<16><<<(BATCH * CH * 16 * 16 + 255) / 256, 256>>>(0, 0);
    // stage 1: H=32, OH=64
    k_stage<1><<<dim3(2, 8, 192), 256>>>(0);
    k_combine<32><<<(BATCH * CH * 32 * 32 + 255) / 256, 256>>>(1, 1);
    // stage 2: H=64, OH=128
    k_stage<2><<<dim3(4, 16, 192), 256>>>(1);
    k_combine<64><<<(BATCH * CH * 64 * 64 + 255) / 256, 256>>>(2, 0);
    // stage 3: H=128, OH=256 (combine fused with final 1x1)
    k_stage<3><<<dim3(8, 32, 192), 256>>>(0);
    k_comfinal<<<(BATCH * 128 * 128 + 255) / 256, 256>>>((float*)d_out);
}

// round 6
// speedup vs baseline: 1.1758x; 1.0018x over previous
#include <cuda_runtime.h>
#include <cuda_bf16.h>

#define BATCH 64
#define CH 8
#define NSTAGE 4

typedef unsigned long long u64;

__device__ __forceinline__ u64 pk2(float lo, float hi) {
    u64 r; asm("mov.b64 %0,{%1,%2};" : "=l"(r) : "f"(lo), "f"(hi)); return r;
}
__device__ __forceinline__ void fma2(u64& d, u64 a, u64 b) {
    asm("fma.rn.f32x2 %0,%1,%2,%0;" : "+l"(d) : "l"(a), "l"(b));
}
__device__ __forceinline__ float2 upk2(u64 v) {
    float2 r; asm("mov.b64 {%0,%1},%2;" : "=f"(r.x), "=f"(r.y) : "l"(v)); return r;
}

// ---------------- device scratch (static, no allocations) ----------------
__device__ float g_ctx[BATCH*32];
__device__ float g_wr[NSTAGE*BATCH*CH*CH*9];
__device__ float g_wt[NSTAGE*BATCH*CH*CH*16];
__device__ float g_wm[NSTAGE*BATCH*CH*CH*25];
__device__ float g_wo[BATCH*3*CH];
__device__ float g_br[NSTAGE*BATCH*CH];
__device__ float g_bt[NSTAGE*BATCH*CH];
__device__ float g_bm[NSTAGE*BATCH*CH];
__device__ float g_bo[BATCH*3];
__device__ __align__(16) float g_xA[BATCH*CH*128*128];
__device__ __align__(16) float g_xB[BATCH*CH*128*128];
__device__ __align__(16) float g_pos[BATCH*CH*128*128];
__device__ __align__(16) float g_neg[BATCH*CH*256*256];
__device__ __align__(16) float g_mul[BATCH*CH*256*256];
__device__ unsigned g_minpos[NSTAGE*BATCH*CH];
__device__ unsigned g_minneg[NSTAGE*BATCH*CH];
__device__ unsigned g_minmul[NSTAGE*BATCH*CH];

__device__ __forceinline__ float dln_f(float v, float mn) {
    float s = (v > 0.0f) ? 1.0f : -1.0f;
    float a = fabsf(v) - mn;
    return s * __logf(__logf(a + 2.718281828459045f) + 0.01f);
}

// ---------------- gather ----------------
__global__ void k_gather(const int* __restrict__ ids,
                         const float* __restrict__ cc,
                         const float* __restrict__ lat) {
    int t = blockIdx.x * blockDim.x + threadIdx.x;
    int T = gridDim.x * blockDim.x;
    for (int i = t; i < BATCH * 32; i += T) {
        int b = i >> 5;
        g_ctx[i] = cc[ids[b] * 32 + (i & 31)];
    }
    for (int i = t; i < BATCH * CH * 16 * 16; i += T) {
        int b = i >> 11;
        g_xA[i] = lat[ids[b] * (CH * 16 * 16) + (i & 2047)];
    }
}

__global__ void k_mininit() {
    int t = blockIdx.x * blockDim.x + threadIdx.x;
    if (t < NSTAGE * BATCH * CH) {
        g_minpos[t] = 0x7F800000u;
        g_minneg[t] = 0x7F800000u;
        g_minmul[t] = 0x7F800000u;
    }
}

// ---------------- dynamic weight computation ----------------
__global__ void k_weights(
    const float* __restrict__ Wr, const float* __restrict__ Ur, const float* __restrict__ Vr, const float* __restrict__ Br,
    const float* __restrict__ Wt, const float* __restrict__ Ut, const float* __restrict__ Vt, const float* __restrict__ Bt,
    const float* __restrict__ Wm, const float* __restrict__ Um, const float* __restrict__ Vm, const float* __restrict__ Bm,
    const float* __restrict__ Wo, const float* __restrict__ Uo, const float* __restrict__ Vo, const float* __restrict__ Bo)
{
    int inst = blockIdx.x, b = blockIdx.y, tid = threadIdx.x;
    __shared__ float sctx[32];
    __shared__ float su[128];
    __shared__ float sv[3200];
    if (tid < 32) sctx[tid] = g_ctx[b * 32 + tid];
    __syncthreads();

    int O, KK;
    const float *U, *V, *W, *Bb;
    float *gw, *gb;
    if (inst < 12) {
        int type = inst >> 2, stage = inst & 3;
        O = CH;
        if (type == 0)      { KK = 9;  U = Ur; V = Vr; W = Wr; Bb = Br; gw = g_wr; gb = g_br; }
        else if (type == 1) { KK = 16; U = Ut; V = Vt; W = Wt; Bb = Bt; gw = g_wt; gb = g_bt; }
        else                { KK = 25; U = Um; V = Vm; W = Wm; Bb = Bm; gw = g_wm; gb = g_bm; }
        int uLen = 16 * O, vLen = 16 * CH * KK;
        U  += (size_t)stage * 32 * uLen;
        V  += (size_t)stage * 32 * vLen;
        W  += (size_t)stage * O * CH * KK;
        Bb += (size_t)stage * 32 * O;
        gw += (size_t)(stage * BATCH + b) * O * CH * KK;
        gb += (size_t)(stage * BATCH + b) * O;
    } else {
        O = 3; KK = 1;
        U = Uo; V = Vo; W = Wo; Bb = Bo;
        gw = g_wo + b * 3 * CH;
        gb = g_bo + b * 3;
    }
    int uLen = 16 * O, vLen = 16 * CH * KK, IKK = CH * KK, wN = O * IKK;

    for (int j = tid; j < uLen; j += blockDim.x) {
        float s = 0.f;
        #pragma unroll
        for (int l = 0; l < 32; l++) s += sctx[l] * U[l * uLen + j];
        su[j] = s;
    }
    for (int j = tid; j < vLen; j += blockDim.x) {
        float s = 0.f;
        #pragma unroll
        for (int l = 0; l < 32; l++) s += sctx[l] * V[l * vLen + j];
        sv[j] = s;
    }
    __syncthreads();

    for (int widx = tid; widx < wN; widx += blockDim.x) {
        int o = widx / IKK, k = widx - o * IKK;
        float m = 0.f;
        #pragma unroll
        for (int r = 0; r < 16; r++) m += su[r * O + o] * sv[r * IKK + k];
        gw[widx] = W[widx] * (1.0f + m + 1e-3f);
    }
    if (tid < O) {
        float s = 0.f;
        #pragma unroll
        for (int l = 0; l < 32; l++) s += sctx[l] * Bb[l * O + tid];
        gb[tid] = s;
    }
}

// ---------------- conv3 packed f32x2, SPLIT-lane ----------------
template<int H, int TWP, int SPLIT>
__device__ __forceinline__ void conv3p_body(float* smraw, const float* xb, int b,
                                            int bx, int by, int tid, int stage) {
    constexpr int TW = 2 * TWP;
    constexpr int THT = 8 / SPLIT;
    constexpr int IW = TW + 2;
    constexpr int IH = 10;
    float* sIn = smraw;                              // CH*IH*IW
    float2* sW2 = (float2*)(sIn + CH * IH * IW);     // CH*CH*9
    float* sB = (float*)(sW2 + CH * CH * 9);
    int x0t = bx * TW, y0 = by * 8;
    const float* wsrc = g_wr + (size_t)(stage * BATCH + b) * CH * CH * 9;
    for (int j = tid; j < CH * CH * 9; j += 256) { float w = wsrc[j]; sW2[j] = make_float2(w, w); }
    if (tid < CH) sB[tid] = g_br[(stage * BATCH + b) * CH + tid];
    for (int j = tid; j < CH * IH * IW; j += 256) {
        int i = j / (IH * IW);
        int rem = j - i * IH * IW;
        int r = rem / IW, c = rem - r * IW;
        int gy = y0 - 1 + r, gx = x0t - 1 + c;
        float v = 0.f;
        if ((unsigned)gy < (unsigned)H && (unsigned)gx < (unsigned)H)
            v = xb[i * H * H + gy * H + gx];
        sIn[j] = v;
    }
    __syncthreads();
    int lane = tid & 31, o = tid >> 5;
    int xp = lane & (TWP - 1);
    int L0 = (lane / TWP) * THT;

    u64 acc[THT];
    float bias = sB[o];
    u64 pb = pk2(bias, bias);
    #pragma unroll
    for (int y = 0; y < THT; y++) acc[y] = pb;

    #pragma unroll
    for (int i = 0; i < CH; i++) {
        u64 ww[9];
        const u64* pw = (const u64*)(sW2 + (o * CH + i) * 9);
        #pragma unroll
        for (int k = 0; k < 9; k++) ww[k] = pw[k];
        #pragma unroll
        for (int rl = 0; rl < THT + 2; rl++) {
            const float2* row = (const float2*)(sIn + (i * IH + L0 + rl) * IW) + xp;
            float2 e0 = row[0], e1 = row[1];
            u64 p[3];
            p[0] = pk2(e0.x, e0.y); p[1] = pk2(e0.y, e1.x); p[2] = pk2(e1.x, e1.y);
            #pragma unroll
            for (int kx = 0; kx < 3; kx++) {
                #pragma unroll
                for (int ky = 0; ky < 3; ky++) {
                    int ly = rl - ky;
                    if (ly >= 0 && ly < THT)
                        fma2(acc[ly], p[kx], ww[ky * 3 + kx]);
                }
            }
        }
    }
    int bo = b * CH + o;
    float* outp = g_pos + (size_t)bo * H * H;
    float mn = 3.4e38f;
    #pragma unroll
    for (int y = 0; y < THT; y++) {
        float2 v = upk2(acc[y]);
        ((float2*)(outp + (y0 + L0 + y) * H))[(x0t >> 1) + xp] = v;
        mn = fminf(mn, fminf(fabsf(v.x), fabsf(v.y)));
    }
    #pragma unroll
    for (int off = 16; off > 0; off >>= 1)
        mn = fminf(mn, __shfl_down_sync(0xFFFFFFFFu, mn, off));
    if (lane == 0) atomicMin(&g_minpos[stage * BATCH * CH + bo], __float_as_uint(mn));
}

// ---------------- convT 4x4 s2 p1 on -x, parity-decomposed (scalar) ----------------
template<int H>
__device__ __forceinline__ void convt_body(float* sm, const float* x, int b,
                                           int x0, int y0, int tid, int stage) {
    constexpr int OH = 2 * H;
    constexpr int TW = 32, TH = 8;
    constexpr int IWT = TW / 2 + 2;
    constexpr int IHT = TH / 2 + 2;
    float* sIn = sm;
    float* sW  = sm + CH * IHT * IWT;
    float* sB  = sW + CH * CH * 16;
    const float* wsrc = g_wt + (size_t)(stage * BATCH + b) * CH * CH * 16;
    if (tid < CH) sB[tid] = g_bt[(stage * BATCH + b) * CH + tid];
    for (int j = tid; j < CH * CH * 16; j += 256) sW[j] = wsrc[j];
    int ix0 = x0 / 2 - 1, iy0 = y0 / 2 - 1;
    for (int j = tid; j < CH * IHT * IWT; j += 256) {
        int i = j / (IHT * IWT);
        int rem = j - i * IHT * IWT;
        int r = rem / IWT, c = rem - r * IWT;
        int gy = iy0 + r, gx = ix0 + c;
        float v = 0.f;
        if ((unsigned)gy < (unsigned)H && (unsigned)gx < (unsigned)H)
            v = x[i * H * H + gy * H + gx];
        sIn[j] = v;
    }
    __syncthreads();

    int tx = tid & 31, o = tid >> 5;
    int px = tx & 1;
    int cA = (tx >> 1) + px;
    float acc[TH];
    float bias = sB[o];
    #pragma unroll
    for (int y = 0; y < TH; y++) acc[y] = bias;

    #pragma unroll
    for (int i = 0; i < CH; i++) {
        float wA[4], wB[4];
        #pragma unroll
        for (int ky = 0; ky < 4; ky++) {
            wA[ky] = sW[(o * CH + i) * 16 + ky * 4 + (3 - px)];
            wB[ky] = sW[(o * CH + i) * 16 + ky * 4 + (1 - px)];
        }
        float vA[IHT], vB[IHT];
        #pragma unroll
        for (int r = 0; r < IHT; r++) {
            vA[r] = sIn[(i * IHT + r) * IWT + cA];
            vB[r] = sIn[(i * IHT + r) * IWT + cA + 1];
        }
        #pragma unroll
        for (int ty = 0; ty < TH; ty++) {
            const int py = ty & 1;
            const int r = (ty >> 1) + py;
            acc[ty] -= vA[r]     * wA[3 - py]
                     + vB[r]     * wB[3 - py]
                     + vA[r + 1] * wA[1 - py]
                     + vB[r + 1] * wB[1 - py];
        }
    }

    int bo = b * CH + o;
    float* outp = g_neg + (size_t)bo * OH * OH;
    float mn = 3.4e38f;
    #pragma unroll
    for (int y = 0; y < TH; y++) {
        outp[(y0 + y) * OH + x0 + tx] = acc[y];
        mn = fminf(mn, fabsf(acc[y]));
    }
    #pragma unroll
    for (int off = 16; off > 0; off >>= 1)
        mn = fminf(mn, __shfl_down_sync(0xFFFFFFFFu, mn, off));
    if (tx == 0) atomicMin(&g_minneg[stage * BATCH * CH + bo], __float_as_uint(mn));
}

// ---------------- conv5 packed f32x2, SPLIT=2 (TWP=16, TW=32), fused log+bilinear ----------------
template<int H>
__device__ __forceinline__ void conv5p_body(float* smraw, const float* xb, int b,
                                            int bx, int by, int tid, int stage) {
    constexpr int OH = 2 * H;
    constexpr int TWP = 16, THT = 4;
    constexpr int TW = 2 * TWP;
    constexpr int IW = TW + 4, IH = 12;
    constexpr int LW = TW / 2 + 4, LH = 8;
    float* sLx = smraw;                              // CH*LH*LW
    float* sXu = sLx + CH * LH * LW;                 // CH*IH*IW
    float2* sW2 = (float2*)(sXu + CH * IH * IW);     // CH*CH*25
    float* sB = (float*)(sW2 + CH * CH * 25);
    int x0 = bx * TW, y0 = by * 8;
    const float* wsrc = g_wm + (size_t)(stage * BATCH + b) * CH * CH * 25;
    for (int j = tid; j < CH * CH * 25; j += 256) { float w = wsrc[j]; sW2[j] = make_float2(w, w); }
    if (tid < CH) sB[tid] = g_bm[(stage * BATCH + b) * CH + tid];

    int gyLo = ((y0 - 2) >> 1) - 1;
    int gxLo = ((x0 - 2) >> 1) - 1;
    for (int j = tid; j < CH * LH * LW; j += 256) {
        int i = j / (LH * LW);
        int rem = j - i * LH * LW;
        int r = rem / LW, c = rem - r * LW;
        int gy = gyLo + r, gx = gxLo + c;
        float v = 0.f;
        if ((unsigned)gy < (unsigned)H && (unsigned)gx < (unsigned)H)
            v = __logf(fabsf(xb[i * H * H + gy * H + gx]) + 1.0f);
        sLx[j] = v;
    }
    __syncthreads();
    for (int j = tid; j < CH * IH * IW; j += 256) {
        int i = j / (IH * IW);
        int rem = j - i * IH * IW;
        int r = rem / IW, c = rem - r * IW;
        int Y = y0 - 2 + r, X = x0 - 2 + c;
        float v = 0.f;
        if ((unsigned)Y < (unsigned)OH && (unsigned)X < (unsigned)OH) {
            int iy = Y >> 1, ix = X >> 1;
            int yo = (Y & 1) ? min(iy + 1, H - 1) : max(iy - 1, 0);
            int xo = (X & 1) ? min(ix + 1, H - 1) : max(ix - 1, 0);
            const float* L = sLx + i * LH * LW;
            int ry = iy - gyLo, ryo = yo - gyLo;
            int cx = ix - gxLo, cxo = xo - gxLo;
            v = 0.5625f * L[ry * LW + cx] + 0.1875f * L[ry * LW + cxo]
              + 0.1875f * L[ryo * LW + cx] + 0.0625f * L[ryo * LW + cxo];
        }
        sXu[j] = v;
    }
    __syncthreads();

    int lane = tid & 31, o = tid >> 5;
    int xp = lane & (TWP - 1);
    int L0 = (lane / TWP) * THT;

    u64 acc[THT];
    float bias = sB[o];
    u64 pb = pk2(bias, bias);
    #pragma unroll
    for (int y = 0; y < THT; y++) acc[y] = pb;

    #pragma unroll
    for (int i = 0; i < CH; i++) {
        u64 ww[25];
        const u64* pw = (const u64*)(sW2 + (o * CH + i) * 25);
        #pragma unroll
        for (int k = 0; k < 25; k++) ww[k] = pw[k];
        #pragma unroll
        for (int rl = 0; rl < THT + 4; rl++) {
            const float2* row = (const float2*)(sXu + (i * IH + L0 + rl) * IW) + xp;
            float2 e0 = row[0], e1 = row[1], e2 = row[2];
            u64 p[5];
            p[0] = pk2(e0.x, e0.y); p[1] = pk2(e0.y, e1.x); p[2] = pk2(e1.x, e1.y);
            p[3] = pk2(e1.y, e2.x); p[4] = pk2(e2.x, e2.y);
            #pragma unroll
            for (int kx = 0; kx < 5; kx++) {
                #pragma unroll
                for (int ky = 0; ky < 5; ky++) {
                    int ly = rl - ky;
                    if (ly >= 0 && ly < THT)
                        fma2(acc[ly], p[kx], ww[ky * 5 + kx]);
                }
            }
        }
    }
    int bo = b * CH + o;
    float* outp = g_mul + (size_t)bo * OH * OH;
    float mn = 3.4e38f;
    #pragma unroll
    for (int y = 0; y < THT; y++) {
        float2 v = upk2(acc[y]);
        ((float2*)(outp + (y0 + L0 + y) * OH))[(x0 >> 1) + xp] = v;
        mn = fminf(mn, fminf(fabsf(v.x), fabsf(v.y)));
    }
    #pragma unroll
    for (int off = 16; off > 0; off >>= 1)
        mn = fminf(mn, __shfl_down_sync(0xFFFFFFFFu, mn, off));
    if (lane == 0) atomicMin(&g_minmul[stage * BATCH * CH + bo], __float_as_uint(mn));
}

// ---------------- per-stage superkernel ----------------
template<int STAGE>
__global__ __launch_bounds__(256) void k_stage(int srcA) {
    constexpr int H = 16 << STAGE;
    constexpr int OH = 2 * H;
    constexpr int TWP3 = (STAGE == 0) ? 8 : (STAGE == 1 ? 16 : 32);
    constexpr int SPL3 = 32 / TWP3 / ((STAGE >= 2) ? 1 : 1);   // TWP3*SPLIT=32
    constexpr int SPLIT3 = 32 / TWP3;
    constexpr int TW3 = 2 * TWP3;
    __shared__ __align__(16) float smem[7944];
    int role = blockIdx.z >> 6;
    int b = blockIdx.z & 63;
    (void)SPL3;
    const float* xb = (srcA ? g_xA : g_xB) + (size_t)b * CH * H * H;
    if (role == 0) {
        if ((int)blockIdx.x >= H / TW3 || (int)blockIdx.y >= H / 8) return;
        conv3p_body<H, TWP3, SPLIT3>(smem, xb, b, blockIdx.x, blockIdx.y, threadIdx.x, STAGE);
    } else if (role == 1) {
        convt_body<H>(smem, xb, b, blockIdx.x * 32, blockIdx.y * 8, threadIdx.x, STAGE);
    } else {
        conv5p_body<H>(smem, xb, b, blockIdx.x, blockIdx.y, threadIdx.x, STAGE);
    }
}

// ---------------- combine (stages 0-2) ----------------
template<int H>
__global__ __launch_bounds__(256) void k_combine(int stage, int dstA) {
    constexpr int OH = 2 * H;
    constexpr int NH = H * H;
    int t = blockIdx.x * 256 + threadIdx.x;
    if (t >= BATCH * CH * NH) return;
    int bc = t / NH;
    int rem = t - bc * NH;
    int y = rem / H, x = rem - y * H;
    float mnp = __uint_as_float(g_minpos[stage * BATCH * CH + bc]);
    float mnn = __uint_as_float(g_minneg[stage * BATCH * CH + bc]);
    float mnm = __uint_as_float(g_minmul[stage * BATCH * CH + bc]);
    float dp = dln_f(g_pos[(size_t)bc * NH + rem], mnp);
    const float2* neg2 = (const float2*)(g_neg + (size_t)bc * OH * OH);
    const float2* mul2 = (const float2*)(g_mul + (size_t)bc * OH * OH);
    float2* dst2 = (float2*)((dstA ? g_xA : g_xB) + (size_t)bc * OH * OH);
    #pragma unroll
    for (int dy = 0; dy < 2; dy++) {
        int row = 2 * y + dy;
        float2 n = neg2[row * (OH / 2) + x];
        float2 m = mul2[row * (OH / 2) + x];
        float2 r;
        r.x = (dp + dln_f(n.x, mnn)) * dln_f(m.x, mnm);
        r.y = (dp + dln_f(n.y, mnn)) * dln_f(m.y, mnm);
        dst2[row * (OH / 2) + x] = r;
    }
}

// ---------------- stage-3 combine fused with final 1x1 conv -> 3 ch ----------------
__global__ __launch_bounds__(256) void k_comfinal(float* __restrict__ out) {
    constexpr int H = 128, OH = 256, NH = H * H;
    constexpr int stage = 3;
    int t = blockIdx.x * 256 + threadIdx.x;
    int b = t / NH;
    int rem = t - b * NH;
    int y = rem / H, x = rem - y * H;

    float wo[3 * CH], bo3[3];
    #pragma unroll
    for (int k = 0; k < 3 * CH; k++) wo[k] = g_wo[b * 3 * CH + k];
    #pragma unroll
    for (int k = 0; k < 3; k++) bo3[k] = g_bo[b * 3 + k];

    float dp[CH], mnn[CH], mnm[CH];
    #pragma unroll
    for (int c = 0; c < CH; c++) {
        int bc = b * CH + c;
        float mnp = __uint_as_float(g_minpos[stage * BATCH * CH + bc]);
        mnn[c] = __uint_as_float(g_minneg[stage * BATCH * CH + bc]);
        mnm[c] = __uint_as_float(g_minmul[stage * BATCH * CH + bc]);
        dp[c] = dln_f(g_pos[(size_t)bc * NH + rem], mnp);
    }

    #pragma unroll
    for (int dy = 0; dy < 2; dy++) {
        int row = 2 * y + dy;
        float2 acc[3];
        #pragma unroll
        for (int o = 0; o < 3; o++) { acc[o].x = bo3[o]; acc[o].y = bo3[o]; }
        #pragma unroll
        for (int c = 0; c < CH; c++) {
            int bc = b * CH + c;
            const float2* neg2 = (const float2*)(g_neg + (size_t)bc * OH * OH);
            const float2* mul2 = (const float2*)(g_mul + (size_t)bc * OH * OH);
            float2 n = neg2[row * (OH / 2) + x];
            float2 m = mul2[row * (OH / 2) + x];
            float xv0 = (dp[c] + dln_f(n.x, mnn[c])) * dln_f(m.x, mnm[c]);
            float xv1 = (dp[c] + dln_f(n.y, mnn[c])) * dln_f(m.y, mnm[c]);
            #pragma unroll
            for (int o = 0; o < 3; o++) {
                acc[o].x += wo[o * CH + c] * xv0;
                acc[o].y += wo[o * CH + c] * xv1;
            }
        }
        #pragma unroll
        for (int o = 0; o < 3; o++) {
            float2* dst2 = (float2*)(out + ((size_t)b * 3 + o) * OH * OH);
            dst2[row * (OH / 2) + x] = acc[o];
        }
    }
}

// ---------------- launcher ----------------
extern "C" void kernel_launch(void* const* d_in, const int* in_sizes, int n_in,
                              void* d_out, int out_size) {
    const int*   ids = (const int*)  d_in[0];
    const float* cc  = (const float*)d_in[1];
    const float* lat = (const float*)d_in[2];
    const float* Wr = (const float*)d_in[3];
    const float* Ur = (const float*)d_in[4];
    const float* Vr = (const float*)d_in[5];
    const float* Br = (const float*)d_in[6];
    const float* Wt = (const float*)d_in[7];
    const float* Ut = (const float*)d_in[8];
    const float* Vt = (const float*)d_in[9];
    const float* Bt = (const float*)d_in[10];
    const float* Wm = (const float*)d_in[11];
    const float* Um = (const float*)d_in[12];
    const float* Vm = (const float*)d_in[13];
    const float* Bm = (const float*)d_in[14];
    const float* Wo = (const float*)d_in[15];
    const float* Uo = (const float*)d_in[16];
    const float* Vo = (const float*)d_in[17];
    const float* Bo = (const float*)d_in[18];

    k_gather<<<64, 256>>>(ids, cc, lat);
    k_weights<<<dim3(13, 64), 128>>>(Wr, Ur, Vr, Br, Wt, Ut, Vt, Bt,
                                     Wm, Um, Vm, Bm, Wo, Uo, Vo, Bo);
    k_mininit<<<(NSTAGE * BATCH * CH + 255) / 256, 256>>>();

    // stage 0: H=16, OH=32
    k_stage<0><<<dim3(1, 4, 192), 256>>>(1);
    k_combine<16><<<(BATCH * CH * 16 * 16 + 255) / 256, 256>>>(0, 0);
    // stage 1: H=32, OH=64
    k_stage<1><<<dim3(2, 8, 192), 256>>>(0);
    k_combine<32><<<(BATCH * CH * 32 * 32 + 255) / 256, 256>>>(1, 1);
    // stage 2: H=64, OH=128
    k_stage<2><<<dim3(4, 16, 192), 256>>>(1);
    k_combine<64><<<(BATCH * CH * 64 * 64 + 255) / 256, 256>>>(2, 0);
    // stage 3: H=128, OH=256 (combine fused with final 1x1)
    k_stage<3><<<dim3(8, 32, 192), 256>>>(0);
    k_comfinal<<<(BATCH * 128 * 128 + 255) / 256, 256>>>((float*)d_out);
}

// round 7
// speedup vs baseline: 1.4194x; 1.2072x over previous
#include <cuda_runtime.h>
#include <cuda_bf16.h>
#include <cstdint>

#define BATCH 64
#define CH 8
#define NSTAGE 4

// ---------------- device scratch ----------------
__device__ float g_ctx[BATCH*32];
__device__ float g_wr[NSTAGE*BATCH*CH*CH*9];
__device__ float g_wt[NSTAGE*BATCH*CH*CH*16];
__device__ float g_wm[NSTAGE*BATCH*CH*CH*25];
__device__ __nv_bfloat16 g_wmbh[NSTAGE*BATCH*8*27*8];
__device__ __nv_bfloat16 g_wmbl[NSTAGE*BATCH*8*27*8];
__device__ float g_wo[BATCH*3*CH];
__device__ float g_br[NSTAGE*BATCH*CH];
__device__ float g_bt[NSTAGE*BATCH*CH];
__device__ float g_bm[NSTAGE*BATCH*CH];
__device__ float g_bo[BATCH*3];
__device__ __align__(16) float g_xA[BATCH*CH*128*128];
__device__ __align__(16) float g_xB[BATCH*CH*128*128];
__device__ __align__(16) float g_pos[BATCH*CH*128*128];
__device__ __align__(16) float g_neg[BATCH*CH*256*256];
__device__ __align__(16) float g_mul[BATCH*CH*256*256];
__device__ unsigned g_minpos[NSTAGE*BATCH*CH];
__device__ unsigned g_minneg[NSTAGE*BATCH*CH];
__device__ unsigned g_minmul[NSTAGE*BATCH*CH];

__device__ __forceinline__ float dln_f(float v, float mn) {
    float s = (v > 0.0f) ? 1.0f : -1.0f;
    float a = fabsf(v) - mn;
    return s * __logf(__logf(a + 2.718281828459045f) + 0.01f);
}

__device__ __forceinline__ void mma16816(float* c, uint32_t a0, uint32_t a1, uint32_t a2, uint32_t a3,
                                         uint32_t b0, uint32_t b1) {
    asm("mma.sync.aligned.m16n8k16.row.col.f32.bf16.bf16.f32 "
        "{%0,%1,%2,%3},{%4,%5,%6,%7},{%8,%9},{%0,%1,%2,%3};"
        : "+f"(c[0]), "+f"(c[1]), "+f"(c[2]), "+f"(c[3])
        : "r"(a0), "r"(a1), "r"(a2), "r"(a3), "r"(b0), "r"(b1));
}

// ---------------- gather ----------------
__global__ void k_gather(const int* __restrict__ ids, const float* __restrict__ cc,
                         const float* __restrict__ lat) {
    int t = blockIdx.x * blockDim.x + threadIdx.x;
    int T = gridDim.x * blockDim.x;
    for (int i = t; i < BATCH * 32; i += T) g_ctx[i] = cc[ids[i >> 5] * 32 + (i & 31)];
    for (int i = t; i < BATCH * CH * 256; i += T)
        g_xA[i] = lat[ids[i >> 11] * (CH * 256) + (i & 2047)];
}

__global__ void k_mininit() {
    int t = blockIdx.x * blockDim.x + threadIdx.x;
    if (t < NSTAGE * BATCH * CH) {
        g_minpos[t] = 0x7F800000u; g_minneg[t] = 0x7F800000u; g_minmul[t] = 0x7F800000u;
    }
}

// ---------------- dynamic weights ----------------
__global__ void k_weights(
    const float* __restrict__ Wr, const float* __restrict__ Ur, const float* __restrict__ Vr, const float* __restrict__ Br,
    const float* __restrict__ Wt, const float* __restrict__ Ut, const float* __restrict__ Vt, const float* __restrict__ Bt,
    const float* __restrict__ Wm, const float* __restrict__ Um, const float* __restrict__ Vm, const float* __restrict__ Bm,
    const float* __restrict__ Wo, const float* __restrict__ Uo, const float* __restrict__ Vo, const float* __restrict__ Bo)
{
    int inst = blockIdx.x, b = blockIdx.y, tid = threadIdx.x;
    __shared__ float sctx[32];
    __shared__ float su[128];
    __shared__ float sv[3200];
    if (tid < 32) sctx[tid] = g_ctx[b * 32 + tid];
    __syncthreads();

    int O, KK, type = -1, stage = 0;
    const float *U, *V, *W, *Bb;
    float *gw, *gb;
    if (inst < 12) {
        type = inst >> 2; stage = inst & 3;
        O = CH;
        if (type == 0)      { KK = 9;  U = Ur; V = Vr; W = Wr; Bb = Br; gw = g_wr; gb = g_br; }
        else if (type == 1) { KK = 16; U = Ut; V = Vt; W = Wt; Bb = Bt; gw = g_wt; gb = g_bt; }
        else                { KK = 25; U = Um; V = Vm; W = Wm; Bb = Bm; gw = g_wm; gb = g_bm; }
        int uL = 16 * O, vL = 16 * CH * KK;
        U += (size_t)stage * 32 * uL; V += (size_t)stage * 32 * vL;
        W += (size_t)stage * O * CH * KK; Bb += (size_t)stage * 32 * O;
        gw += (size_t)(stage * BATCH + b) * O * CH * KK;
        gb += (size_t)(stage * BATCH + b) * O;
    } else {
        O = 3; KK = 1;
        U = Uo; V = Vo; W = Wo; Bb = Bo;
        gw = g_wo + b * 3 * CH; gb = g_bo + b * 3;
    }
    int uLen = 16 * O, vLen = 16 * CH * KK, IKK = CH * KK, wN = O * IKK;

    for (int j = tid; j < uLen; j += blockDim.x) {
        float s = 0.f;
        #pragma unroll
        for (int l = 0; l < 32; l++) s += sctx[l] * U[l * uLen + j];
        su[j] = s;
    }
    for (int j = tid; j < vLen; j += blockDim.x) {
        float s = 0.f;
        #pragma unroll
        for (int l = 0; l < 32; l++) s += sctx[l] * V[l * vLen + j];
        sv[j] = s;
    }
    __syncthreads();

    for (int widx = tid; widx < wN; widx += blockDim.x) {
        int o = widx / IKK, k = widx - o * IKK;
        float m = 0.f;
        #pragma unroll
        for (int r = 0; r < 16; r++) m += su[r * O + o] * sv[r * IKK + k];
        float w = W[widx] * (1.0f + m + 1e-3f);
        gw[widx] = w;
        if (type == 2) {  // reorder [o][tap][ch] bf16 hi/lo for mma
            int i = k / 25, t = k - i * 25;
            size_t d = (size_t)((stage * BATCH + b) * 8 + o) * 216 + t * 8 + i;
            __nv_bfloat16 h = __float2bfloat16(w);
            g_wmbh[d] = h;
            g_wmbl[d] = __float2bfloat16(w - __bfloat162float(h));
        }
    }
    if (type == 2 && tid < 128) {  // zero pad taps 25,26
        int o = tid >> 4, t = 25 + ((tid >> 3) & 1), i = tid & 7;
        size_t d = (size_t)((stage * BATCH + b) * 8 + o) * 216 + t * 8 + i;
        g_wmbh[d] = __float2bfloat16(0.f);
        g_wmbl[d] = __float2bfloat16(0.f);
    }
    if (tid < O) {
        float s = 0.f;
        #pragma unroll
        for (int l = 0; l < 32; l++) s += sctx[l] * Bb[l * O + tid];
        gb[tid] = s;
    }
}

// ---------------- scalar conv3 (R3) ----------------
template<int H, int TW, int TH>
__device__ __forceinline__ void conv3_body(float* sm, const float* xb, int b,
                                           int x0, int y0, int tid, int stage) {
    constexpr int IW = TW + 2, IH = TH + 2;
    float* sIn = sm;
    float* sW  = sm + CH * IH * IW;
    float* sB  = sW + CH * CH * 9;
    const float* wsrc = g_wr + (size_t)(stage * BATCH + b) * CH * CH * 9;
    for (int j = tid; j < CH * CH * 9; j += 256) sW[j] = wsrc[j];
    if (tid < CH) sB[tid] = g_br[(stage * BATCH + b) * CH + tid];
    for (int j = tid; j < CH * IH * IW; j += 256) {
        int i = j / (IH * IW);
        int rem = j - i * IH * IW;
        int r = rem / IW, c = rem - r * IW;
        int gy = y0 - 1 + r, gx = x0 - 1 + c;
        float v = 0.f;
        if ((unsigned)gy < (unsigned)H && (unsigned)gx < (unsigned)H)
            v = xb[i * H * H + gy * H + gx];
        sIn[j] = v;
    }
    __syncthreads();
    if (tid < TW * CH) {
        int tx = tid & (TW - 1);
        int o  = tid / TW;
        float acc[TH];
        float bias = sB[o];
        #pragma unroll
        for (int y = 0; y < TH; y++) acc[y] = bias;
        #pragma unroll
        for (int i = 0; i < CH; i++) {
            float w[9];
            #pragma unroll
            for (int k = 0; k < 9; k++) w[k] = sW[(o * CH + i) * 9 + k];
            #pragma unroll
            for (int r = 0; r < IH; r++) {
                float v[3];
                #pragma unroll
                for (int k = 0; k < 3; k++) v[k] = sIn[(i * IH + r) * IW + tx + k];
                #pragma unroll
                for (int ky = 0; ky < 3; ky++) {
                    int y = r - ky;
                    if (y >= 0 && y < TH) {
                        #pragma unroll
                        for (int kx = 0; kx < 3; kx++) acc[y] += v[kx] * w[ky * 3 + kx];
                    }
                }
            }
        }
        int bo = b * CH + o;
        float* outp = g_pos + (size_t)bo * H * H;
        float mn = 3.4e38f;
        #pragma unroll
        for (int y = 0; y < TH; y++) {
            outp[(y0 + y) * H + x0 + tx] = acc[y];
            mn = fminf(mn, fabsf(acc[y]));
        }
        #pragma unroll
        for (int off = TW / 2; off > 0; off >>= 1)
            mn = fminf(mn, __shfl_down_sync(0xFFFFFFFFu, mn, off, TW));
        if (tx == 0) atomicMin(&g_minpos[stage * BATCH * CH + bo], __float_as_uint(mn));
    }
}

// ---------------- scalar convT (R3) ----------------
template<int H>
__device__ __forceinline__ void convt_body(float* sm, const float* x, int b,
                                           int x0, int y0, int tid, int stage) {
    constexpr int OH = 2 * H;
    constexpr int TW = 32, TH = 8;
    constexpr int IWT = 18, IHT = 6;
    float* sIn = sm;
    float* sW  = sm + CH * IHT * IWT;
    float* sB  = sW + CH * CH * 16;
    const float* wsrc = g_wt + (size_t)(stage * BATCH + b) * CH * CH * 16;
    if (tid < CH) sB[tid] = g_bt[(stage * BATCH + b) * CH + tid];
    for (int j = tid; j < CH * CH * 16; j += 256) sW[j] = wsrc[j];
    int ix0 = x0 / 2 - 1, iy0 = y0 / 2 - 1;
    for (int j = tid; j < CH * IHT * IWT; j += 256) {
        int i = j / (IHT * IWT);
        int rem = j - i * IHT * IWT;
        int r = rem / IWT, c = rem - r * IWT;
        int gy = iy0 + r, gx = ix0 + c;
        float v = 0.f;
        if ((unsigned)gy < (unsigned)H && (unsigned)gx < (unsigned)H)
            v = x[i * H * H + gy * H + gx];
        sIn[j] = v;
    }
    __syncthreads();
    int tx = tid & 31, o = tid >> 5;
    int px = tx & 1;
    int cA = (tx >> 1) + px;
    float acc[TH];
    float bias = sB[o];
    #pragma unroll
    for (int y = 0; y < TH; y++) acc[y] = bias;
    #pragma unroll
    for (int i = 0; i < CH; i++) {
        float wA[4], wB[4];
        #pragma unroll
        for (int ky = 0; ky < 4; ky++) {
            wA[ky] = sW[(o * CH + i) * 16 + ky * 4 + (3 - px)];
            wB[ky] = sW[(o * CH + i) * 16 + ky * 4 + (1 - px)];
        }
        float vA[IHT], vB[IHT];
        #pragma unroll
        for (int r = 0; r < IHT; r++) {
            vA[r] = sIn[(i * IHT + r) * IWT + cA];
            vB[r] = sIn[(i * IHT + r) * IWT + cA + 1];
        }
        #pragma unroll
        for (int ty = 0; ty < TH; ty++) {
            const int py = ty & 1;
            const int r = (ty >> 1) + py;
            acc[ty] -= vA[r] * wA[3 - py] + vB[r] * wB[3 - py]
                     + vA[r + 1] * wA[1 - py] + vB[r + 1] * wB[1 - py];
        }
    }
    int bo = b * CH + o;
    float* outp = g_neg + (size_t)bo * OH * OH;
    float mn = 3.4e38f;
    #pragma unroll
    for (int y = 0; y < TH; y++) {
        outp[(y0 + y) * OH + x0 + tx] = acc[y];
        mn = fminf(mn, fabsf(acc[y]));
    }
    #pragma unroll
    for (int off = 16; off > 0; off >>= 1)
        mn = fminf(mn, __shfl_down_sync(0xFFFFFFFFu, mn, off));
    if (tx == 0) atomicMin(&g_minneg[stage * BATCH * CH + bo], __float_as_uint(mn));
}

// ---------------- scalar conv5 w/ fused log+bilinear (R3, stages 0/1) ----------------
template<int H>
__device__ __forceinline__ void conv5_body(float* sm, const float* xb, int b,
                                           int x0, int y0, int tid, int stage) {
    constexpr int OH = 2 * H;
    constexpr int LH = 8, LW = 20;
    constexpr int IH = 12, IW = 36;
    float* sLx = sm;
    float* sXu = sm + CH * LH * LW;
    float* sW  = sXu + CH * IH * IW;
    float* sB  = sW + CH * CH * 25;
    const float* wsrc = g_wm + (size_t)(stage * BATCH + b) * CH * CH * 25;
    for (int j = tid; j < CH * CH * 25; j += 256) sW[j] = wsrc[j];
    if (tid < CH) sB[tid] = g_bm[(stage * BATCH + b) * CH + tid];
    int gyLo = ((y0 - 2) >> 1) - 1;
    int gxLo = ((x0 - 2) >> 1) - 1;
    for (int j = tid; j < CH * LH * LW; j += 256) {
        int i = j / (LH * LW);
        int rem = j - i * LH * LW;
        int r = rem / LW, c = rem - r * LW;
        int gy = gyLo + r, gx = gxLo + c;
        float v = 0.f;
        if ((unsigned)gy < (unsigned)H && (unsigned)gx < (unsigned)H)
            v = __logf(fabsf(xb[i * H * H + gy * H + gx]) + 1.0f);
        sLx[j] = v;
    }
    __syncthreads();
    for (int j = tid; j < CH * IH * IW; j += 256) {
        int i = j / (IH * IW);
        int rem = j - i * IH * IW;
        int r = rem / IW, c = rem - r * IW;
        int Y = y0 - 2 + r, X = x0 - 2 + c;
        float v = 0.f;
        if ((unsigned)Y < (unsigned)OH && (unsigned)X < (unsigned)OH) {
            int iy = Y >> 1, ix = X >> 1;
            int yo = (Y & 1) ? min(iy + 1, H - 1) : max(iy - 1, 0);
            int xo = (X & 1) ? min(ix + 1, H - 1) : max(ix - 1, 0);
            const float* L = sLx + i * LH * LW;
            int ry = iy - gyLo, ryo = yo - gyLo;
            int cx = ix - gxLo, cxo = xo - gxLo;
            v = 0.5625f * L[ry * LW + cx] + 0.1875f * L[ry * LW + cxo]
              + 0.1875f * L[ryo * LW + cx] + 0.0625f * L[ryo * LW + cxo];
        }
        sXu[j] = v;
    }
    __syncthreads();
    int tx = tid & 31, o = tid >> 5;
    float acc[8];
    float bias = sB[o];
    #pragma unroll
    for (int y = 0; y < 8; y++) acc[y] = bias;
    #pragma unroll
    for (int i = 0; i < CH; i++) {
        float w[25];
        #pragma unroll
        for (int k = 0; k < 25; k++) w[k] = sW[(o * CH + i) * 25 + k];
        #pragma unroll
        for (int r = 0; r < IH; r++) {
            float v[5];
            #pragma unroll
            for (int k = 0; k < 5; k++) v[k] = sXu[(i * IH + r) * IW + tx + k];
            #pragma unroll
            for (int ky = 0; ky < 5; ky++) {
                int y = r - ky;
                if (y >= 0 && y < 8) {
                    #pragma unroll
                    for (int kx = 0; kx < 5; kx++) acc[y] += v[kx] * w[ky * 5 + kx];
                }
            }
        }
    }
    int bo = b * CH + o;
    float* outp = g_mul + (size_t)bo * OH * OH;
    float mn = 3.4e38f;
    #pragma unroll
    for (int y = 0; y < 8; y++) {
        outp[(y0 + y) * OH + x0 + tx] = acc[y];
        mn = fminf(mn, fabsf(acc[y]));
    }
    #pragma unroll
    for (int off = 16; off > 0; off >>= 1)
        mn = fminf(mn, __shfl_down_sync(0xFFFFFFFFu, mn, off));
    if (tx == 0) atomicMin(&g_minmul[stage * BATCH * CH + bo], __float_as_uint(mn));
}

// ---------------- superkernel: roles conv3/convT (+scalar conv5 if WITH5) ----------------
template<int STAGE, bool WITH5>
__global__ __launch_bounds__(256) void k_stage(int srcA) {
    constexpr int H = 16 << STAGE;
    __shared__ float smem[6400];
    int role = blockIdx.z >> 6;
    int b = blockIdx.z & 63;
    int tid = threadIdx.x;
    const float* xb = (srcA ? g_xA : g_xB) + (size_t)b * CH * H * H;
    if (role == 0) {
        constexpr int TW = (STAGE == 0) ? 16 : 32;
        if ((int)blockIdx.x >= H / TW || (int)blockIdx.y >= H / 8) return;
        conv3_body<H, TW, 8>(smem, xb, b, blockIdx.x * TW, blockIdx.y * 8, tid, STAGE);
    } else if (role == 1) {
        convt_body<H>(smem, xb, b, blockIdx.x * 32, blockIdx.y * 8, tid, STAGE);
    } else if (WITH5) {
        conv5_body<H>(smem, xb, b, blockIdx.x * 32, blockIdx.y * 8, tid, STAGE);
    }
}

// ---------------- mma conv5 (stages 2/3): bf16 split, m16n8k16 ----------------
template<int H>
__global__ __launch_bounds__(256) void k_conv5mma(int srcA, int stage) {
    constexpr int OH = 2 * H;
    constexpr int LH = 8, LW = 20;
    __shared__ float sLx[CH * LH * LW];
    __shared__ uint32_t sXuH[12 * 36 * 4];
    __shared__ uint32_t sXuL[12 * 36 * 4];
    __shared__ uint32_t sWH[8 * 27 * 4];
    __shared__ uint32_t sWL[8 * 27 * 4];
    __shared__ float sB[8];
    __shared__ unsigned sMin[8];

    int b = blockIdx.z;
    int x0 = blockIdx.x * 32, y0 = blockIdx.y * 8;
    int tid = threadIdx.x;
    const float* xb = (srcA ? g_xA : g_xB) + (size_t)b * CH * H * H;

    const __nv_bfloat16* wh = g_wmbh + (size_t)((stage * BATCH + b) * 8) * 216;
    const __nv_bfloat16* wl = g_wmbl + (size_t)((stage * BATCH + b) * 8) * 216;
    __nv_bfloat16* swh = (__nv_bfloat16*)sWH;
    __nv_bfloat16* swl = (__nv_bfloat16*)sWL;
    for (int j = tid; j < 8 * 216; j += 256) { swh[j] = wh[j]; swl[j] = wl[j]; }
    if (tid < 8) { sB[tid] = g_bm[(stage * BATCH + b) * CH + tid]; sMin[tid] = 0x7F800000u; }

    int gyLo = ((y0 - 2) >> 1) - 1;
    int gxLo = ((x0 - 2) >> 1) - 1;
    for (int j = tid; j < CH * LH * LW; j += 256) {
        int i = j / (LH * LW);
        int rem = j - i * LH * LW;
        int r = rem / LW, c = rem - r * LW;
        int gy = gyLo + r, gx = gxLo + c;
        float v = 0.f;
        if ((unsigned)gy < (unsigned)H && (unsigned)gx < (unsigned)H)
            v = __logf(fabsf(xb[i * H * H + gy * H + gx]) + 1.0f);
        sLx[j] = v;
    }
    __syncthreads();
    // xu pixel-major bf16 hi/lo: [r<12][c<36][ch<8]
    __nv_bfloat16* xuh = (__nv_bfloat16*)sXuH;
    __nv_bfloat16* xul = (__nv_bfloat16*)sXuL;
    for (int j = tid; j < 12 * 36 * 8; j += 256) {
        int ch = j & 7;
        int rc = j >> 3;
        int r = rc / 36, c = rc - 36 * r;
        int Y = y0 - 2 + r, X = x0 - 2 + c;
        float v = 0.f;
        if ((unsigned)Y < (unsigned)OH && (unsigned)X < (unsigned)OH) {
            int iy = Y >> 1, ix = X >> 1;
            int yo = (Y & 1) ? min(iy + 1, H - 1) : max(iy - 1, 0);
            int xo = (X & 1) ? min(ix + 1, H - 1) : max(ix - 1, 0);
            const float* L = sLx + ch * LH * LW;
            int ry = iy - gyLo, ryo = yo - gyLo;
            int cx = ix - gxLo, cxo = xo - gxLo;
            v = 0.5625f * L[ry * LW + cx] + 0.1875f * L[ry * LW + cxo]
              + 0.1875f * L[ryo * LW + cx] + 0.0625f * L[ryo * LW + cxo];
        }
        __nv_bfloat16 h = __float2bfloat16(v);
        xuh[j] = h;
        xul[j] = __float2bfloat16(v - __bfloat162float(h));
    }
    __syncthreads();

    int w = tid >> 5, lane = tid & 31, g = lane >> 2, tg = lane & 3;
    float b0f = sB[2 * tg], b1f = sB[2 * tg + 1];
    float c0[4] = {b0f, b1f, b0f, b1f};
    float c1[4] = {b0f, b1f, b0f, b1f};
    int yl = w;

    #pragma unroll
    for (int k = 0; k < 13; k++) {
        const int t0 = 2 * k, t1 = 2 * k + 1;
        const int ky0 = t0 / 5, kx0 = t0 % 5;
        const int ky1 = (t1 < 25) ? t1 / 5 : 0, kx1 = (t1 < 25) ? t1 % 5 : 0;
        uint32_t bh0 = sWH[(g * 27 + t0) * 4 + tg], bh1 = sWH[(g * 27 + t1) * 4 + tg];
        uint32_t bl0 = sWL[(g * 27 + t0) * 4 + tg], bl1 = sWL[(g * 27 + t1) * 4 + tg];
        #pragma unroll
        for (int s = 0; s < 2; s++) {
            int xbse = s * 16 + g;
            int p0 = ((yl + ky0) * 36 + xbse + kx0) * 4 + tg;
            int p1 = ((yl + ky1) * 36 + xbse + kx1) * 4 + tg;
            uint32_t a0h = sXuH[p0], a1h = sXuH[p0 + 32], a2h = sXuH[p1], a3h = sXuH[p1 + 32];
            uint32_t a0l = sXuL[p0], a1l = sXuL[p0 + 32], a2l = sXuL[p1], a3l = sXuL[p1 + 32];
            float* cc = s ? c1 : c0;
            mma16816(cc, a0h, a1h, a2h, a3h, bh0, bh1);
            mma16816(cc, a0l, a1l, a2l, a3l, bh0, bh1);
            mma16816(cc, a0h, a1h, a2h, a3h, bl0, bl1);
        }
    }

    int Y = y0 + yl;
    float* mulb = g_mul + (size_t)b * CH * OH * OH;
    float me = 3.4e38f, mo = 3.4e38f;
    #pragma unroll
    for (int s = 0; s < 2; s++) {
        float* cc = s ? c1 : c0;
        int X = x0 + s * 16 + g;
        mulb[(size_t)(2 * tg) * OH * OH + Y * OH + X] = cc[0];
        mulb[(size_t)(2 * tg + 1) * OH * OH + Y * OH + X] = cc[1];
        mulb[(size_t)(2 * tg) * OH * OH + Y * OH + X + 8] = cc[2];
        mulb[(size_t)(2 * tg + 1) * OH * OH + Y * OH + X + 8] = cc[3];
        me = fminf(me, fminf(fabsf(cc[0]), fabsf(cc[2])));
        mo = fminf(mo, fminf(fabsf(cc[1]), fabsf(cc[3])));
    }
    #pragma unroll
    for (int off = 16; off >= 4; off >>= 1) {
        me = fminf(me, __shfl_xor_sync(0xFFFFFFFFu, me, off));
        mo = fminf(mo, __shfl_xor_sync(0xFFFFFFFFu, mo, off));
    }
    if (lane < 4) {
        atomicMin(&sMin[2 * tg], __float_as_uint(me));
        atomicMin(&sMin[2 * tg + 1], __float_as_uint(mo));
    }
    __syncthreads();
    if (tid < 8) atomicMin(&g_minmul[stage * BATCH * CH + b * CH + tid], sMin[tid]);
}

// ---------------- combine (stages 0-2) ----------------
template<int H>
__global__ __launch_bounds__(256) void k_combine(int stage, int dstA) {
    constexpr int OH = 2 * H;
    constexpr int NH = H * H;
    int t = blockIdx.x * 256 + threadIdx.x;
    if (t >= BATCH * CH * NH) return;
    int bc = t / NH;
    int rem = t - bc * NH;
    int y = rem / H, x = rem - y * H;
    float mnp = __uint_as_float(g_minpos[stage * BATCH * CH + bc]);
    float mnn = __uint_as_float(g_minneg[stage * BATCH * CH + bc]);
    float mnm = __uint_as_float(g_minmul[stage * BATCH * CH + bc]);
    float dp = dln_f(g_pos[(size_t)bc * NH + rem], mnp);
    const float2* neg2 = (const float2*)(g_neg + (size_t)bc * OH * OH);
    const float2* mul2 = (const float2*)(g_mul + (size_t)bc * OH * OH);
    float2* dst2 = (float2*)((dstA ? g_xA : g_xB) + (size_t)bc * OH * OH);
    #pragma unroll
    for (int dy = 0; dy < 2; dy++) {
        int row = 2 * y + dy;
        float2 n = neg2[row * (OH / 2) + x];
        float2 m = mul2[row * (OH / 2) + x];
        float2 r;
        r.x = (dp + dln_f(n.x, mnn)) * dln_f(m.x, mnm);
        r.y = (dp + dln_f(n.y, mnn)) * dln_f(m.y, mnm);
        dst2[row * (OH / 2) + x] = r;
    }
}

// ---------------- stage-3 combine + final 1x1 ----------------
__global__ __launch_bounds__(256) void k_comfinal(float* __restrict__ out) {
    constexpr int H = 128, OH = 256, NH = H * H;
    constexpr int stage = 3;
    int t = blockIdx.x * 256 + threadIdx.x;
    int b = t / NH;
    int rem = t - b * NH;
    int y = rem / H, x = rem - y * H;
    float wo[3 * CH], bo3[3];
    #pragma unroll
    for (int k = 0; k < 3 * CH; k++) wo[k] = g_wo[b * 3 * CH + k];
    #pragma unroll
    for (int k = 0; k < 3; k++) bo3[k] = g_bo[b * 3 + k];
    float dp[CH], mnn[CH], mnm[CH];
    #pragma unroll
    for (int c = 0; c < CH; c++) {
        int bc = b * CH + c;
        float mnp = __uint_as_float(g_minpos[stage * BATCH * CH + bc]);
        mnn[c] = __uint_as_float(g_minneg[stage * BATCH * CH + bc]);
        mnm[c] = __uint_as_float(g_minmul[stage * BATCH * CH + bc]);
        dp[c] = dln_f(g_pos[(size_t)bc * NH + rem], mnp);
    }
    #pragma unroll
    for (int dy = 0; dy < 2; dy++) {
        int row = 2 * y + dy;
        float2 acc[3];
        #pragma unroll
        for (int o = 0; o < 3; o++) { acc[o].x = bo3[o]; acc[o].y = bo3[o]; }
        #pragma unroll
        for (int c = 0; c < CH; c++) {
            int bc = b * CH + c;
            const float2* neg2 = (const float2*)(g_neg + (size_t)bc * OH * OH);
            const float2* mul2 = (const float2*)(g_mul + (size_t)bc * OH * OH);
            float2 n = neg2[row * (OH / 2) + x];
            float2 m = mul2[row * (OH / 2) + x];
            float xv0 = (dp[c] + dln_f(n.x, mnn[c])) * dln_f(m.x, mnm[c]);
            float xv1 = (dp[c] + dln_f(n.y, mnn[c])) * dln_f(m.y, mnm[c]);
            #pragma unroll
            for (int o = 0; o < 3; o++) {
                acc[o].x += wo[o * CH + c] * xv0;
                acc[o].y += wo[o * CH + c] * xv1;
            }
        }
        #pragma unroll
        for (int o = 0; o < 3; o++) {
            float2* dst2 = (float2*)(out + ((size_t)b * 3 + o) * OH * OH);
            dst2[row * (OH / 2) + x] = acc[o];
        }
    }
}

// ---------------- launcher ----------------
extern "C" void kernel_launch(void* const* d_in, const int* in_sizes, int n_in,
                              void* d_out, int out_size) {
    const int*   ids = (const int*)  d_in[0];
    const float* cc  = (const float*)d_in[1];
    const float* lat = (const float*)d_in[2];
    const float* Wr = (const float*)d_in[3];
    const float* Ur = (const float*)d_in[4];
    const float* Vr = (const float*)d_in[5];
    const float* Br = (const float*)d_in[6];
    const float* Wt = (const float*)d_in[7];
    const float* Ut = (const float*)d_in[8];
    const float* Vt = (const float*)d_in[9];
    const float* Bt = (const float*)d_in[10];
    const float* Wm = (const float*)d_in[11];
    const float* Um = (const float*)d_in[12];
    const float* Vm = (const float*)d_in[13];
    const float* Bm = (const float*)d_in[14];
    const float* Wo = (const float*)d_in[15];
    const float* Uo = (const float*)d_in[16];
    const float* Vo = (const float*)d_in[17];
    const float* Bo = (const float*)d_in[18];

    k_gather<<<64, 256>>>(ids, cc, lat);
    k_weights<<<dim3(13, 64), 128>>>(Wr, Ur, Vr, Br, Wt, Ut, Vt, Bt,
                                     Wm, Um, Vm, Bm, Wo, Uo, Vo, Bo);
    k_mininit<<<(NSTAGE * BATCH * CH + 255) / 256, 256>>>();

    // stage 0 (H=16): scalar all roles
    k_stage<0, true><<<dim3(1, 4, 192), 256>>>(1);
    k_combine<16><<<(BATCH * CH * 256 + 255) / 256, 256>>>(0, 0);
    // stage 1 (H=32)
    k_stage<1, true><<<dim3(2, 8, 192), 256>>>(0);
    k_combine<32><<<(BATCH * CH * 1024 + 255) / 256, 256>>>(1, 1);
    // stage 2 (H=64): conv3/convT scalar, conv5 on tensor cores
    k_stage<2, false><<<dim3(4, 16, 128), 256>>>(1);
    k_conv5mma<64><<<dim3(4, 16, 64), 256>>>(1, 2);
    k_combine<64><<<(BATCH * CH * 4096 + 255) / 256, 256>>>(2, 0);
    // stage 3 (H=128)
    k_stage<3, false><<<dim3(8, 32, 128), 256>>>(0);
    k_conv5mma<128><<<dim3(8, 32, 64), 256>>>(0, 3);
    k_comfinal<<<(BATCH * 128 * 128 + 255) / 256, 256>>>((float*)d_out);
}

// round 8
// speedup vs baseline: 1.4762x; 1.0400x over previous
#include <cuda_runtime.h>
#include <cuda_bf16.h>
#include <cstdint>

#define BATCH 64
#define CH 8
#define NSTAGE 4

typedef uint32_t u32;

// ---------------- device scratch ----------------
__device__ float g_ctx[BATCH*32];
__device__ float g_wr[NSTAGE*BATCH*CH*CH*9];
__device__ float g_wt[NSTAGE*BATCH*CH*CH*16];
__device__ float g_wm[NSTAGE*BATCH*CH*CH*25];
__device__ __nv_bfloat16 g_wmbh[NSTAGE*BATCH*8*27*8];
__device__ __nv_bfloat16 g_wmbl[NSTAGE*BATCH*8*27*8];
__device__ __nv_bfloat16 g_wrbh[NSTAGE*BATCH*8*10*8];
__device__ __nv_bfloat16 g_wrbl[NSTAGE*BATCH*8*10*8];
__device__ __nv_bfloat16 g_wtbh[NSTAGE*BATCH*1024];
__device__ __nv_bfloat16 g_wtbl[NSTAGE*BATCH*1024];
__device__ float g_wo[BATCH*3*CH];
__device__ float g_br[NSTAGE*BATCH*CH];
__device__ float g_bt[NSTAGE*BATCH*CH];
__device__ float g_bm[NSTAGE*BATCH*CH];
__device__ float g_bo[BATCH*3];
__device__ __align__(16) float g_xA[BATCH*CH*128*128];
__device__ __align__(16) float g_xB[BATCH*CH*128*128];
__device__ __align__(16) float g_pos[BATCH*CH*128*128];
__device__ __align__(16) float g_neg[BATCH*CH*256*256];
__device__ __align__(16) float g_mul[BATCH*CH*256*256];
__device__ unsigned g_minpos[NSTAGE*BATCH*CH];
__device__ unsigned g_minneg[NSTAGE*BATCH*CH];
__device__ unsigned g_minmul[NSTAGE*BATCH*CH];

__device__ __forceinline__ float dln_f(float v, float mn) {
    float s = (v > 0.0f) ? 1.0f : -1.0f;
    float a = fabsf(v) - mn;
    return s * __logf(__logf(a + 2.718281828459045f) + 0.01f);
}

__device__ __forceinline__ void mma16816(float* c, u32 a0, u32 a1, u32 a2, u32 a3,
                                         u32 b0, u32 b1) {
    asm("mma.sync.aligned.m16n8k16.row.col.f32.bf16.bf16.f32 "
        "{%0,%1,%2,%3},{%4,%5,%6,%7},{%8,%9},{%0,%1,%2,%3};"
        : "+f"(c[0]), "+f"(c[1]), "+f"(c[2]), "+f"(c[3])
        : "r"(a0), "r"(a1), "r"(a2), "r"(a3), "r"(b0), "r"(b1));
}

// ---------------- gather ----------------
__global__ void k_gather(const int* __restrict__ ids, const float* __restrict__ cc,
                         const float* __restrict__ lat) {
    int t = blockIdx.x * blockDim.x + threadIdx.x;
    int T = gridDim.x * blockDim.x;
    for (int i = t; i < BATCH * 32; i += T) g_ctx[i] = cc[ids[i >> 5] * 32 + (i & 31)];
    for (int i = t; i < BATCH * CH * 256; i += T)
        g_xA[i] = lat[ids[i >> 11] * (CH * 256) + (i & 2047)];
}

__global__ void k_mininit() {
    int t = blockIdx.x * blockDim.x + threadIdx.x;
    if (t < NSTAGE * BATCH * CH) {
        g_minpos[t] = 0x7F800000u; g_minneg[t] = 0x7F800000u; g_minmul[t] = 0x7F800000u;
    }
}

// ---------------- dynamic weights ----------------
__global__ void k_weights(
    const float* __restrict__ Wr, const float* __restrict__ Ur, const float* __restrict__ Vr, const float* __restrict__ Br,
    const float* __restrict__ Wt, const float* __restrict__ Ut, const float* __restrict__ Vt, const float* __restrict__ Bt,
    const float* __restrict__ Wm, const float* __restrict__ Um, const float* __restrict__ Vm, const float* __restrict__ Bm,
    const float* __restrict__ Wo, const float* __restrict__ Uo, const float* __restrict__ Vo, const float* __restrict__ Bo)
{
    int inst = blockIdx.x, b = blockIdx.y, tid = threadIdx.x;
    __shared__ float sctx[32];
    __shared__ float su[128];
    __shared__ float sv[3200];
    if (tid < 32) sctx[tid] = g_ctx[b * 32 + tid];
    __syncthreads();

    int O, KK, type = -1, stage = 0;
    const float *U, *V, *W, *Bb;
    float *gw, *gb;
    if (inst < 12) {
        type = inst >> 2; stage = inst & 3;
        O = CH;
        if (type == 0)      { KK = 9;  U = Ur; V = Vr; W = Wr; Bb = Br; gw = g_wr; gb = g_br; }
        else if (type == 1) { KK = 16; U = Ut; V = Vt; W = Wt; Bb = Bt; gw = g_wt; gb = g_bt; }
        else                { KK = 25; U = Um; V = Vm; W = Wm; Bb = Bm; gw = g_wm; gb = g_bm; }
        int uL = 16 * O, vL = 16 * CH * KK;
        U += (size_t)stage * 32 * uL; V += (size_t)stage * 32 * vL;
        W += (size_t)stage * O * CH * KK; Bb += (size_t)stage * 32 * O;
        gw += (size_t)(stage * BATCH + b) * O * CH * KK;
        gb += (size_t)(stage * BATCH + b) * O;
    } else {
        O = 3; KK = 1;
        U = Uo; V = Vo; W = Wo; Bb = Bo;
        gw = g_wo + b * 3 * CH; gb = g_bo + b * 3;
    }
    int uLen = 16 * O, vLen = 16 * CH * KK, IKK = CH * KK, wN = O * IKK;
    int sb = stage * BATCH + b;

    for (int j = tid; j < uLen; j += blockDim.x) {
        float s = 0.f;
        #pragma unroll
        for (int l = 0; l < 32; l++) s += sctx[l] * U[l * uLen + j];
        su[j] = s;
    }
    for (int j = tid; j < vLen; j += blockDim.x) {
        float s = 0.f;
        #pragma unroll
        for (int l = 0; l < 32; l++) s += sctx[l] * V[l * vLen + j];
        sv[j] = s;
    }
    __syncthreads();

    for (int widx = tid; widx < wN; widx += blockDim.x) {
        int o = widx / IKK, k = widx - o * IKK;
        float m = 0.f;
        #pragma unroll
        for (int r = 0; r < 16; r++) m += su[r * O + o] * sv[r * IKK + k];
        float w = W[widx] * (1.0f + m + 1e-3f);
        gw[widx] = w;
        if (type == 2) {
            int i = k / 25, t = k - i * 25;
            size_t d = (size_t)(sb * 8 + o) * 216 + t * 8 + i;
            __nv_bfloat16 h = __float2bfloat16(w);
            g_wmbh[d] = h;
            g_wmbl[d] = __float2bfloat16(w - __bfloat162float(h));
        } else if (type == 0) {
            int i = k / 9, t = k - i * 9;
            size_t d = (size_t)sb * 640 + (o * 10 + t) * 8 + i;
            __nv_bfloat16 h = __float2bfloat16(w);
            g_wrbh[d] = h;
            g_wrbl[d] = __float2bfloat16(w - __bfloat162float(h));
        } else if (type == 1) {
            int i = k / 16, t = k - i * 16;
            int ky = t >> 2, kx = t & 3;
            int py = (3 - ky) & 1, dy = (3 - ky) >> 1;
            int px = (3 - kx) & 1, dx = (3 - kx) >> 1;
            float wn = -w;
            size_t d = (size_t)sb * 1024 +
                       ((((size_t)(py * 2 + px) * 8 + o) * 2 + dy) * 2 + dx) * 8 + i;
            __nv_bfloat16 h = __float2bfloat16(wn);
            g_wtbh[d] = h;
            g_wtbl[d] = __float2bfloat16(wn - __bfloat162float(h));
        }
    }
    if (type == 2 && tid < 128) {  // zero-pad taps 25,26
        int o = tid >> 4, t = 25 + ((tid >> 3) & 1), i = tid & 7;
        size_t d = (size_t)(sb * 8 + o) * 216 + t * 8 + i;
        g_wmbh[d] = __float2bfloat16(0.f);
        g_wmbl[d] = __float2bfloat16(0.f);
    }
    if (type == 0 && tid < 64) {  // zero-pad tap 9
        int o = tid >> 3, i = tid & 7;
        size_t d = (size_t)sb * 640 + (o * 10 + 9) * 8 + i;
        g_wrbh[d] = __float2bfloat16(0.f);
        g_wrbl[d] = __float2bfloat16(0.f);
    }
    if (tid < O) {
        float s = 0.f;
        #pragma unroll
        for (int l = 0; l < 32; l++) s += sctx[l] * Bb[l * O + tid];
        gb[tid] = s;
    }
}

// ---------------- scalar bodies (stages 0/1) ----------------
template<int H, int TW, int TH>
__device__ __forceinline__ void conv3_body(float* sm, const float* xb, int b,
                                           int x0, int y0, int tid, int stage) {
    constexpr int IW = TW + 2, IH = TH + 2;
    float* sIn = sm;
    float* sW  = sm + CH * IH * IW;
    float* sB  = sW + CH * CH * 9;
    const float* wsrc = g_wr + (size_t)(stage * BATCH + b) * CH * CH * 9;
    for (int j = tid; j < CH * CH * 9; j += 256) sW[j] = wsrc[j];
    if (tid < CH) sB[tid] = g_br[(stage * BATCH + b) * CH + tid];
    for (int j = tid; j < CH * IH * IW; j += 256) {
        int i = j / (IH * IW);
        int rem = j - i * IH * IW;
        int r = rem / IW, c = rem - r * IW;
        int gy = y0 - 1 + r, gx = x0 - 1 + c;
        float v = 0.f;
        if ((unsigned)gy < (unsigned)H && (unsigned)gx < (unsigned)H)
            v = xb[i * H * H + gy * H + gx];
        sIn[j] = v;
    }
    __syncthreads();
    if (tid < TW * CH) {
        int tx = tid & (TW - 1);
        int o  = tid / TW;
        float acc[TH];
        float bias = sB[o];
        #pragma unroll
        for (int y = 0; y < TH; y++) acc[y] = bias;
        #pragma unroll
        for (int i = 0; i < CH; i++) {
            float w[9];
            #pragma unroll
            for (int k = 0; k < 9; k++) w[k] = sW[(o * CH + i) * 9 + k];
            #pragma unroll
            for (int r = 0; r < IH; r++) {
                float v[3];
                #pragma unroll
                for (int k = 0; k < 3; k++) v[k] = sIn[(i * IH + r) * IW + tx + k];
                #pragma unroll
                for (int ky = 0; ky < 3; ky++) {
                    int y = r - ky;
                    if (y >= 0 && y < TH) {
                        #pragma unroll
                        for (int kx = 0; kx < 3; kx++) acc[y] += v[kx] * w[ky * 3 + kx];
                    }
                }
            }
        }
        int bo = b * CH + o;
        float* outp = g_pos + (size_t)bo * H * H;
        float mn = 3.4e38f;
        #pragma unroll
        for (int y = 0; y < TH; y++) {
            outp[(y0 + y) * H + x0 + tx] = acc[y];
            mn = fminf(mn, fabsf(acc[y]));
        }
        #pragma unroll
        for (int off = TW / 2; off > 0; off >>= 1)
            mn = fminf(mn, __shfl_down_sync(0xFFFFFFFFu, mn, off, TW));
        if (tx == 0) atomicMin(&g_minpos[stage * BATCH * CH + bo], __float_as_uint(mn));
    }
}

template<int H>
__device__ __forceinline__ void convt_body(float* sm, const float* x, int b,
                                           int x0, int y0, int tid, int stage) {
    constexpr int OH = 2 * H;
    constexpr int TW = 32, TH = 8;
    constexpr int IWT = 18, IHT = 6;
    float* sIn = sm;
    float* sW  = sm + CH * IHT * IWT;
    float* sB  = sW + CH * CH * 16;
    const float* wsrc = g_wt + (size_t)(stage * BATCH + b) * CH * CH * 16;
    if (tid < CH) sB[tid] = g_bt[(stage * BATCH + b) * CH + tid];
    for (int j = tid; j < CH * CH * 16; j += 256) sW[j] = wsrc[j];
    int ix0 = x0 / 2 - 1, iy0 = y0 / 2 - 1;
    for (int j = tid; j < CH * IHT * IWT; j += 256) {
        int i = j / (IHT * IWT);
        int rem = j - i * IHT * IWT;
        int r = rem / IWT, c = rem - r * IWT;
        int gy = iy0 + r, gx = ix0 + c;
        float v = 0.f;
        if ((unsigned)gy < (unsigned)H && (unsigned)gx < (unsigned)H)
            v = x[i * H * H + gy * H + gx];
        sIn[j] = v;
    }
    __syncthreads();
    int tx = tid & 31, o = tid >> 5;
    int px = tx & 1;
    int cA = (tx >> 1) + px;
    float acc[TH];
    float bias = sB[o];
    #pragma unroll
    for (int y = 0; y < TH; y++) acc[y] = bias;
    #pragma unroll
    for (int i = 0; i < CH; i++) {
        float wA[4], wB[4];
        #pragma unroll
        for (int ky = 0; ky < 4; ky++) {
            wA[ky] = sW[(o * CH + i) * 16 + ky * 4 + (3 - px)];
            wB[ky] = sW[(o * CH + i) * 16 + ky * 4 + (1 - px)];
        }
        float vA[IHT], vB[IHT];
        #pragma unroll
        for (int r = 0; r < IHT; r++) {
            vA[r] = sIn[(i * IHT + r) * IWT + cA];
            vB[r] = sIn[(i * IHT + r) * IWT + cA + 1];
        }
        #pragma unroll
        for (int ty = 0; ty < TH; ty++) {
            const int py = ty & 1;
            const int r = (ty >> 1) + py;
            acc[ty] -= vA[r] * wA[3 - py] + vB[r] * wB[3 - py]
                     + vA[r + 1] * wA[1 - py] + vB[r + 1] * wB[1 - py];
        }
    }
    int bo = b * CH + o;
    float* outp = g_neg + (size_t)bo * OH * OH;
    float mn = 3.4e38f;
    #pragma unroll
    for (int y = 0; y < TH; y++) {
        outp[(y0 + y) * OH + x0 + tx] = acc[y];
        mn = fminf(mn, fabsf(acc[y]));
    }
    #pragma unroll
    for (int off = 16; off > 0; off >>= 1)
        mn = fminf(mn, __shfl_down_sync(0xFFFFFFFFu, mn, off));
    if (tx == 0) atomicMin(&g_minneg[stage * BATCH * CH + bo], __float_as_uint(mn));
}

template<int H>
__device__ __forceinline__ void conv5_body(float* sm, const float* xb, int b,
                                           int x0, int y0, int tid, int stage) {
    constexpr int OH = 2 * H;
    constexpr int LH = 8, LW = 20;
    constexpr int IH = 12, IW = 36;
    float* sLx = sm;
    float* sXu = sm + CH * LH * LW;
    float* sW  = sXu + CH * IH * IW;
    float* sB  = sW + CH * CH * 25;
    const float* wsrc = g_wm + (size_t)(stage * BATCH + b) * CH * CH * 25;
    for (int j = tid; j < CH * CH * 25; j += 256) sW[j] = wsrc[j];
    if (tid < CH) sB[tid] = g_bm[(stage * BATCH + b) * CH + tid];
    int gyLo = ((y0 - 2) >> 1) - 1;
    int gxLo = ((x0 - 2) >> 1) - 1;
    for (int j = tid; j < CH * LH * LW; j += 256) {
        int i = j / (LH * LW);
        int rem = j - i * LH * LW;
        int r = rem / LW, c = rem - r * LW;
        int gy = gyLo + r, gx = gxLo + c;
        float v = 0.f;
        if ((unsigned)gy < (unsigned)H && (unsigned)gx < (unsigned)H)
            v = __logf(fabsf(xb[i * H * H + gy * H + gx]) + 1.0f);
        sLx[j] = v;
    }
    __syncthreads();
    for (int j = tid; j < CH * IH * IW; j += 256) {
        int i = j / (IH * IW);
        int rem = j - i * IH * IW;
        int r = rem / IW, c = rem - r * IW;
        int Y = y0 - 2 + r, X = x0 - 2 + c;
        float v = 0.f;
        if ((unsigned)Y < (unsigned)OH && (unsigned)X < (unsigned)OH) {
            int iy = Y >> 1, ix = X >> 1;
            int yo = (Y & 1) ? min(iy + 1, H - 1) : max(iy - 1, 0);
            int xo = (X & 1) ? min(ix + 1, H - 1) : max(ix - 1, 0);
            const float* L = sLx + i * LH * LW;
            int ry = iy - gyLo, ryo = yo - gyLo;
            int cx = ix - gxLo, cxo = xo - gxLo;
            v = 0.5625f * L[ry * LW + cx] + 0.1875f * L[ry * LW + cxo]
              + 0.1875f * L[ryo * LW + cx] + 0.0625f * L[ryo * LW + cxo];
        }
        sXu[j] = v;
    }
    __syncthreads();
    int tx = tid & 31, o = tid >> 5;
    float acc[8];
    float bias = sB[o];
    #pragma unroll
    for (int y = 0; y < 8; y++) acc[y] = bias;
    #pragma unroll
    for (int i = 0; i < CH; i++) {
        float w[25];
        #pragma unroll
        for (int k = 0; k < 25; k++) w[k] = sW[(o * CH + i) * 25 + k];
        #pragma unroll
        for (int r = 0; r < IH; r++) {
            float v[5];
            #pragma unroll
            for (int k = 0; k < 5; k++) v[k] = sXu[(i * IH + r) * IW + tx + k];
            #pragma unroll
            for (int ky = 0; ky < 5; ky++) {
                int y = r - ky;
                if (y >= 0 && y < 8) {
                    #pragma unroll
                    for (int kx = 0; kx < 5; kx++) acc[y] += v[kx] * w[ky * 5 + kx];
                }
            }
        }
    }
    int bo = b * CH + o;
    float* outp = g_mul + (size_t)bo * OH * OH;
    float mn = 3.4e38f;
    #pragma unroll
    for (int y = 0; y < 8; y++) {
        outp[(y0 + y) * OH + x0 + tx] = acc[y];
        mn = fminf(mn, fabsf(acc[y]));
    }
    #pragma unroll
    for (int off = 16; off > 0; off >>= 1)
        mn = fminf(mn, __shfl_down_sync(0xFFFFFFFFu, mn, off));
    if (tx == 0) atomicMin(&g_minmul[stage * BATCH * CH + bo], __float_as_uint(mn));
}

// ---------------- small-stage superkernel ----------------
template<int STAGE>
__global__ __launch_bounds__(256) void k_stage(int srcA) {
    constexpr int H = 16 << STAGE;
    __shared__ float smem[6400];
    int role = blockIdx.z >> 6;
    int b = blockIdx.z & 63;
    int tid = threadIdx.x;
    const float* xb = (srcA ? g_xA : g_xB) + (size_t)b * CH * H * H;
    if (role == 0) {
        constexpr int TW = (STAGE == 0) ? 16 : 32;
        if ((int)blockIdx.x >= H / TW || (int)blockIdx.y >= H / 8) return;
        conv3_body<H, TW, 8>(smem, xb, b, blockIdx.x * TW, blockIdx.y * 8, tid, STAGE);
    } else if (role == 1) {
        convt_body<H>(smem, xb, b, blockIdx.x * 32, blockIdx.y * 8, tid, STAGE);
    } else {
        conv5_body<H>(smem, xb, b, blockIdx.x * 32, blockIdx.y * 8, tid, STAGE);
    }
}

// ---------------- big-stage mma superkernel (stages 2/3) ----------------
template<int H>
__global__ __launch_bounds__(256) void k_mma(int srcA, int stage) {
    constexpr int OH = 2 * H;
    __shared__ __align__(16) u32 sm[6500];
    int role = blockIdx.z >> 6;
    int b = blockIdx.z & 63;
    int tid = threadIdx.x;
    int bx = blockIdx.x, by = blockIdx.y;
    const float* xb = (srcA ? g_xA : g_xB) + (size_t)b * CH * H * H;
    int w_ = tid >> 5, lane = tid & 31, g = lane >> 2, tg = lane & 3;

    if (role == 0) {
        // ---- conv3 mma: output 32x8 tile at H res ----
        if (bx >= H / 32 || by >= H / 8) return;
        u32* XH = sm;            // 10*34*4 = 1360
        u32* XL = sm + 1360;
        u32* WH = sm + 2720;     // 320
        u32* WL = sm + 3040;
        float* sB = (float*)(sm + 3360);
        unsigned* sMin = (unsigned*)(sm + 3372);
        int x0 = bx * 32, y0 = by * 8;
        const __nv_bfloat16* wh = g_wrbh + (size_t)(stage * BATCH + b) * 640;
        const __nv_bfloat16* wl = g_wrbl + (size_t)(stage * BATCH + b) * 640;
        __nv_bfloat16* swh = (__nv_bfloat16*)WH;
        __nv_bfloat16* swl = (__nv_bfloat16*)WL;
        for (int j = tid; j < 640; j += 256) { swh[j] = wh[j]; swl[j] = wl[j]; }
        if (tid < 8) { sB[tid] = g_br[(stage * BATCH + b) * CH + tid]; sMin[tid] = 0x7F800000u; }
        __nv_bfloat16* xh = (__nv_bfloat16*)XH;
        __nv_bfloat16* xl = (__nv_bfloat16*)XL;
        for (int j = tid; j < 10 * 34 * 8; j += 256) {
            int ch = j & 7, rc = j >> 3;
            int r = rc / 34, c = rc - 34 * r;
            int gy = y0 - 1 + r, gx = x0 - 1 + c;
            float v = 0.f;
            if ((unsigned)gy < (unsigned)H && (unsigned)gx < (unsigned)H)
                v = xb[ch * H * H + gy * H + gx];
            __nv_bfloat16 h = __float2bfloat16(v);
            xh[j] = h;
            xl[j] = __float2bfloat16(v - __bfloat162float(h));
        }
        __syncthreads();

        float b0f = sB[2 * tg], b1f = sB[2 * tg + 1];
        float c0[4] = {b0f, b1f, b0f, b1f};
        float c1[4] = {b0f, b1f, b0f, b1f};
        #pragma unroll
        for (int k = 0; k < 5; k++) {
            const int t0 = 2 * k, t1 = 2 * k + 1;
            const int t1c = (t1 < 9) ? t1 : 0;
            const int ky0 = t0 / 3, kx0 = t0 % 3;
            const int ky1 = t1c / 3, kx1 = t1c % 3;
            u32 bh0 = WH[(g * 10 + t0) * 4 + tg], bh1 = WH[(g * 10 + t1) * 4 + tg];
            u32 bl0 = WL[(g * 10 + t0) * 4 + tg], bl1 = WL[(g * 10 + t1) * 4 + tg];
            #pragma unroll
            for (int s = 0; s < 2; s++) {
                int xbse = s * 16 + g;
                int p0 = ((w_ + ky0) * 34 + xbse + kx0) * 4 + tg;
                int p1 = ((w_ + ky1) * 34 + xbse + kx1) * 4 + tg;
                u32 a0h = XH[p0], a1h = XH[p0 + 32], a2h = XH[p1], a3h = XH[p1 + 32];
                u32 a0l = XL[p0], a1l = XL[p0 + 32], a2l = XL[p1], a3l = XL[p1 + 32];
                float* cc = s ? c1 : c0;
                mma16816(cc, a0h, a1h, a2h, a3h, bh0, bh1);
                mma16816(cc, a0l, a1l, a2l, a3l, bh0, bh1);
                mma16816(cc, a0h, a1h, a2h, a3h, bl0, bl1);
            }
        }
        int Y = y0 + w_;
        float* outp = g_pos + (size_t)b * CH * H * H;
        float me = 3.4e38f, mo = 3.4e38f;
        #pragma unroll
        for (int s = 0; s < 2; s++) {
            float* cc = s ? c1 : c0;
            int X = x0 + s * 16 + g;
            outp[(size_t)(2 * tg) * H * H + Y * H + X] = cc[0];
            outp[(size_t)(2 * tg + 1) * H * H + Y * H + X] = cc[1];
            outp[(size_t)(2 * tg) * H * H + Y * H + X + 8] = cc[2];
            outp[(size_t)(2 * tg + 1) * H * H + Y * H + X + 8] = cc[3];
            me = fminf(me, fminf(fabsf(cc[0]), fabsf(cc[2])));
            mo = fminf(mo, fminf(fabsf(cc[1]), fabsf(cc[3])));
        }
        #pragma unroll
        for (int off = 16; off >= 4; off >>= 1) {
            me = fminf(me, __shfl_xor_sync(0xFFFFFFFFu, me, off));
            mo = fminf(mo, __shfl_xor_sync(0xFFFFFFFFu, mo, off));
        }
        if (lane < 4) {
            atomicMin(&sMin[2 * tg], __float_as_uint(me));
            atomicMin(&sMin[2 * tg + 1], __float_as_uint(mo));
        }
        __syncthreads();
        if (tid < 8) atomicMin(&g_minpos[stage * BATCH * CH + b * CH + tid], sMin[tid]);

    } else if (role == 1) {
        // ---- convT mma: output 32x8 tile at OH res; parity-split M ----
        u32* XH = sm;            // 6*18*4 = 432
        u32* XL = sm + 432;
        u32* WH = sm + 864;      // 512
        u32* WL = sm + 1376;
        float* sB = (float*)(sm + 1888);
        unsigned* sMin = (unsigned*)(sm + 1900);
        int x0 = bx * 32, y0 = by * 8;
        const __nv_bfloat16* wh = g_wtbh + (size_t)(stage * BATCH + b) * 1024;
        const __nv_bfloat16* wl = g_wtbl + (size_t)(stage * BATCH + b) * 1024;
        __nv_bfloat16* swh = (__nv_bfloat16*)WH;
        __nv_bfloat16* swl = (__nv_bfloat16*)WL;
        for (int j = tid; j < 1024; j += 256) { swh[j] = wh[j]; swl[j] = wl[j]; }
        if (tid < 8) { sB[tid] = g_bt[(stage * BATCH + b) * CH + tid]; sMin[tid] = 0x7F800000u; }
        int iy0 = y0 / 2 - 1, ix0 = x0 / 2 - 1;
        __nv_bfloat16* xh = (__nv_bfloat16*)XH;
        __nv_bfloat16* xl = (__nv_bfloat16*)XL;
        for (int j = tid; j < 6 * 18 * 8; j += 256) {
            int ch = j & 7, rc = j >> 3;
            int r = rc / 18, c = rc - 18 * r;
            int gy = iy0 + r, gx = ix0 + c;
            float v = 0.f;
            if ((unsigned)gy < (unsigned)H && (unsigned)gx < (unsigned)H)
                v = xb[ch * H * H + gy * H + gx];
            __nv_bfloat16 h = __float2bfloat16(v);
            xh[j] = h;
            xl[j] = __float2bfloat16(v - __bfloat162float(h));
        }
        __syncthreads();

        int py = w_ & 1;
        int r0 = (w_ >> 1) + py;
        float b0f = sB[2 * tg], b1f = sB[2 * tg + 1];
        int Y = y0 + w_;
        float* outp = g_neg + (size_t)b * CH * OH * OH;
        float me = 3.4e38f, mo = 3.4e38f;
        #pragma unroll
        for (int px = 0; px < 2; px++) {
            float cc[4] = {b0f, b1f, b0f, b1f};
            #pragma unroll
            for (int dy = 0; dy < 2; dy++) {
                int wb = ((((py * 2 + px) * 8 + g) * 2 + dy) * 2) * 4 + tg;
                u32 bh0 = WH[wb], bh1 = WH[wb + 4];
                u32 bl0 = WL[wb], bl1 = WL[wb + 4];
                int base0 = ((r0 + dy) * 18 + g + px) * 4 + tg;
                u32 a0h = XH[base0], a1h = XH[base0 + 32], a2h = XH[base0 + 4], a3h = XH[base0 + 36];
                u32 a0l = XL[base0], a1l = XL[base0 + 32], a2l = XL[base0 + 4], a3l = XL[base0 + 36];
                mma16816(cc, a0h, a1h, a2h, a3h, bh0, bh1);
                mma16816(cc, a0l, a1l, a2l, a3l, bh0, bh1);
                mma16816(cc, a0h, a1h, a2h, a3h, bl0, bl1);
            }
            int X0 = x0 + 2 * g + px;
            int X1 = x0 + 2 * (g + 8) + px;
            outp[(size_t)(2 * tg) * OH * OH + Y * OH + X0] = cc[0];
            outp[(size_t)(2 * tg + 1) * OH * OH + Y * OH + X0] = cc[1];
            outp[(size_t)(2 * tg) * OH * OH + Y * OH + X1] = cc[2];
            outp[(size_t)(2 * tg + 1) * OH * OH + Y * OH + X1] = cc[3];
            me = fminf(me, fminf(fabsf(cc[0]), fabsf(cc[2])));
            mo = fminf(mo, fminf(fabsf(cc[1]), fabsf(cc[3])));
        }
        #pragma unroll
        for (int off = 16; off >= 4; off >>= 1) {
            me = fminf(me, __shfl_xor_sync(0xFFFFFFFFu, me, off));
            mo = fminf(mo, __shfl_xor_sync(0xFFFFFFFFu, mo, off));
        }
        if (lane < 4) {
            atomicMin(&sMin[2 * tg], __float_as_uint(me));
            atomicMin(&sMin[2 * tg + 1], __float_as_uint(mo));
        }
        __syncthreads();
        if (tid < 8) atomicMin(&g_minneg[stage * BATCH * CH + b * CH + tid], sMin[tid]);

    } else {
        // ---- conv5 mma (validated R7) ----
        constexpr int LH = 8, LW = 20;
        float* sLx = (float*)sm;                    // 1280 f
        u32* XuH = sm + 1280;                       // 1728
        u32* XuL = sm + 3008;                       // 1728
        u32* WH = sm + 4736;                        // 864
        u32* WL = sm + 5600;                        // 864
        float* sB = (float*)(sm + 6464);
        unsigned* sMin = (unsigned*)(sm + 6476);
        int x0 = bx * 32, y0 = by * 8;
        const __nv_bfloat16* wh = g_wmbh + (size_t)((stage * BATCH + b) * 8) * 216;
        const __nv_bfloat16* wl = g_wmbl + (size_t)((stage * BATCH + b) * 8) * 216;
        __nv_bfloat16* swh = (__nv_bfloat16*)WH;
        __nv_bfloat16* swl = (__nv_bfloat16*)WL;
        for (int j = tid; j < 8 * 216; j += 256) { swh[j] = wh[j]; swl[j] = wl[j]; }
        if (tid < 8) { sB[tid] = g_bm[(stage * BATCH + b) * CH + tid]; sMin[tid] = 0x7F800000u; }
        int gyLo = ((y0 - 2) >> 1) - 1;
        int gxLo = ((x0 - 2) >> 1) - 1;
        for (int j = tid; j < CH * LH * LW; j += 256) {
            int i = j / (LH * LW);
            int rem = j - i * LH * LW;
            int r = rem / LW, c = rem - r * LW;
            int gy = gyLo + r, gx = gxLo + c;
            float v = 0.f;
            if ((unsigned)gy < (unsigned)H && (unsigned)gx < (unsigned)H)
                v = __logf(fabsf(xb[i * H * H + gy * H + gx]) + 1.0f);
            sLx[j] = v;
        }
        __syncthreads();
        __nv_bfloat16* xuh = (__nv_bfloat16*)XuH;
        __nv_bfloat16* xul = (__nv_bfloat16*)XuL;
        for (int j = tid; j < 12 * 36 * 8; j += 256) {
            int ch = j & 7, rc = j >> 3;
            int r = rc / 36, c = rc - 36 * r;
            int Y = y0 - 2 + r, X = x0 - 2 + c;
            float v = 0.f;
            if ((unsigned)Y < (unsigned)OH && (unsigned)X < (unsigned)OH) {
                int iy = Y >> 1, ix = X >> 1;
                int yo = (Y & 1) ? min(iy + 1, H - 1) : max(iy - 1, 0);
                int xo = (X & 1) ? min(ix + 1, H - 1) : max(ix - 1, 0);
                const float* L = sLx + ch * LH * LW;
                int ry = iy - gyLo, ryo = yo - gyLo;
                int cx = ix - gxLo, cxo = xo - gxLo;
                v = 0.5625f * L[ry * LW + cx] + 0.1875f * L[ry * LW + cxo]
                  + 0.1875f * L[ryo * LW + cx] + 0.0625f * L[ryo * LW + cxo];
            }
            __nv_bfloat16 h = __float2bfloat16(v);
            xuh[j] = h;
            xul[j] = __float2bfloat16(v - __bfloat162float(h));
        }
        __syncthreads();

        float b0f = sB[2 * tg], b1f = sB[2 * tg + 1];
        float c0[4] = {b0f, b1f, b0f, b1f};
        float c1[4] = {b0f, b1f, b0f, b1f};
        #pragma unroll
        for (int k = 0; k < 13; k++) {
            const int t0 = 2 * k, t1 = 2 * k + 1;
            const int ky0 = t0 / 5, kx0 = t0 % 5;
            const int ky1 = (t1 < 25) ? t1 / 5 : 0, kx1 = (t1 < 25) ? t1 % 5 : 0;
            u32 bh0 = WH[(g * 27 + t0) * 4 + tg], bh1 = WH[(g * 27 + t1) * 4 + tg];
            u32 bl0 = WL[(g * 27 + t0) * 4 + tg], bl1 = WL[(g * 27 + t1) * 4 + tg];
            #pragma unroll
            for (int s = 0; s < 2; s++) {
                int xbse = s * 16 + g;
                int p0 = ((w_ + ky0) * 36 + xbse + kx0) * 4 + tg;
                int p1 = ((w_ + ky1) * 36 + xbse + kx1) * 4 + tg;
                u32 a0h = XuH[p0], a1h = XuH[p0 + 32], a2h = XuH[p1], a3h = XuH[p1 + 32];
                u32 a0l = XuL[p0], a1l = XuL[p0 + 32], a2l = XuL[p1], a3l = XuL[p1 + 32];
                float* cc = s ? c1 : c0;
                mma16816(cc, a0h, a1h, a2h, a3h, bh0, bh1);
                mma16816(cc, a0l, a1l, a2l, a3l, bh0, bh1);
                mma16816(cc, a0h, a1h, a2h, a3h, bl0, bl1);
            }
        }
        int Y = y0 + w_;
        float* mulb = g_mul + (size_t)b * CH * OH * OH;
        float me = 3.4e38f, mo = 3.4e38f;
        #pragma unroll
        for (int s = 0; s < 2; s++) {
            float* cc = s ? c1 : c0;
            int X = x0 + s * 16 + g;
            mulb[(size_t)(2 * tg) * OH * OH + Y * OH + X] = cc[0];
            mulb[(size_t)(2 * tg + 1) * OH * OH + Y * OH + X] = cc[1];
            mulb[(size_t)(2 * tg) * OH * OH + Y * OH + X + 8] = cc[2];
            mulb[(size_t)(2 * tg + 1) * OH * OH + Y * OH + X + 8] = cc[3];
            me = fminf(me, fminf(fabsf(cc[0]), fabsf(cc[2])));
            mo = fminf(mo, fminf(fabsf(cc[1]), fabsf(cc[3])));
        }
        #pragma unroll
        for (int off = 16; off >= 4; off >>= 1) {
            me = fminf(me, __shfl_xor_sync(0xFFFFFFFFu, me, off));
            mo = fminf(mo, __shfl_xor_sync(0xFFFFFFFFu, mo, off));
        }
        if (lane < 4) {
            atomicMin(&sMin[2 * tg], __float_as_uint(me));
            atomicMin(&sMin[2 * tg + 1], __float_as_uint(mo));
        }
        __syncthreads();
        if (tid < 8) atomicMin(&g_minmul[stage * BATCH * CH + b * CH + tid], sMin[tid]);
    }
}

// ---------------- combine (stages 0-2) ----------------
template<int H>
__global__ __launch_bounds__(256) void k_combine(int stage, int dstA) {
    constexpr int OH = 2 * H;
    constexpr int NH = H * H;
    int t = blockIdx.x * 256 + threadIdx.x;
    if (t >= BATCH * CH * NH) return;
    int bc = t / NH;
    int rem = t - bc * NH;
    int y = rem / H, x = rem - y * H;
    float mnp = __uint_as_float(g_minpos[stage * BATCH * CH + bc]);
    float mnn = __uint_as_float(g_minneg[stage * BATCH * CH + bc]);
    float mnm = __uint_as_float(g_minmul[stage * BATCH * CH + bc]);
    float dp = dln_f(g_pos[(size_t)bc * NH + rem], mnp);
    const float2* neg2 = (const float2*)(g_neg + (size_t)bc * OH * OH);
    const float2* mul2 = (const float2*)(g_mul + (size_t)bc * OH * OH);
    float2* dst2 = (float2*)((dstA ? g_xA : g_xB) + (size_t)bc * OH * OH);
    #pragma unroll
    for (int dy = 0; dy < 2; dy++) {
        int row = 2 * y + dy;
        float2 n = neg2[row * (OH / 2) + x];
        float2 m = mul2[row * (OH / 2) + x];
        float2 r;
        r.x = (dp + dln_f(n.x, mnn)) * dln_f(m.x, mnm);
        r.y = (dp + dln_f(n.y, mnn)) * dln_f(m.y, mnm);
        dst2[row * (OH / 2) + x] = r;
    }
}

// ---------------- stage-3 combine + final 1x1 ----------------
__global__ __launch_bounds__(256) void k_comfinal(float* __restrict__ out) {
    constexpr int H = 128, OH = 256, NH = H * H;
    constexpr int stage = 3;
    int t = blockIdx.x * 256 + threadIdx.x;
    int b = t / NH;
    int rem = t - b * NH;
    int y = rem / H, x = rem - y * H;
    float wo[3 * CH], bo3[3];
    #pragma unroll
    for (int k = 0; k < 3 * CH; k++) wo[k] = g_wo[b * 3 * CH + k];
    #pragma unroll
    for (int k = 0; k < 3; k++) bo3[k] = g_bo[b * 3 + k];
    float dp[CH], mnn[CH], mnm[CH];
    #pragma unroll
    for (int c = 0; c < CH; c++) {
        int bc = b * CH + c;
        float mnp = __uint_as_float(g_minpos[stage * BATCH * CH + bc]);
        mnn[c] = __uint_as_float(g_minneg[stage * BATCH * CH + bc]);
        mnm[c] = __uint_as_float(g_minmul[stage * BATCH * CH + bc]);
        dp[c] = dln_f(g_pos[(size_t)bc * NH + rem], mnp);
    }
    #pragma unroll
    for (int dy = 0; dy < 2; dy++) {
        int row = 2 * y + dy;
        float2 acc[3];
        #pragma unroll
        for (int o = 0; o < 3; o++) { acc[o].x = bo3[o]; acc[o].y = bo3[o]; }
        #pragma unroll
        for (int c = 0; c < CH; c++) {
            int bc = b * CH + c;
            const float2* neg2 = (const float2*)(g_neg + (size_t)bc * OH * OH);
            const float2* mul2 = (const float2*)(g_mul + (size_t)bc * OH * OH);
            float2 n = neg2[row * (OH / 2) + x];
            float2 m = mul2[row * (OH / 2) + x];
            float xv0 = (dp[c] + dln_f(n.x, mnn[c])) * dln_f(m.x, mnm[c]);
            float xv1 = (dp[c] + dln_f(n.y, mnn[c])) * dln_f(m.y, mnm[c]);
            #pragma unroll
            for (int o = 0; o < 3; o++) {
                acc[o].x += wo[o * CH + c] * xv0;
                acc[o].y += wo[o * CH + c] * xv1;
            }
        }
        #pragma unroll
        for (int o = 0; o < 3; o++) {
            float2* dst2 = (float2*)(out + ((size_t)b * 3 + o) * OH * OH);
            dst2[row * (OH / 2) + x] = acc[o];
        }
    }
}

// ---------------- launcher ----------------
extern "C" void kernel_launch(void* const* d_in, const int* in_sizes, int n_in,
                              void* d_out, int out_size) {
    const int*   ids = (const int*)  d_in[0];
    const float* cc  = (const float*)d_in[1];
    const float* lat = (const float*)d_in[2];
    const float* Wr = (const float*)d_in[3];
    const float* Ur = (const float*)d_in[4];
    const float* Vr = (const float*)d_in[5];
    const float* Br = (const float*)d_in[6];
    const float* Wt = (const float*)d_in[7];
    const float* Ut = (const float*)d_in[8];
    const float* Vt = (const float*)d_in[9];
    const float* Bt = (const float*)d_in[10];
    const float* Wm = (const float*)d_in[11];
    const float* Um = (const float*)d_in[12];
    const float* Vm = (const float*)d_in[13];
    const float* Bm = (const float*)d_in[14];
    const float* Wo = (const float*)d_in[15];
    const float* Uo = (const float*)d_in[16];
    const float* Vo = (const float*)d_in[17];
    const float* Bo = (const float*)d_in[18];

    k_gather<<<64, 256>>>(ids, cc, lat);
    k_weights<<<dim3(13, 64), 128>>>(Wr, Ur, Vr, Br, Wt, Ut, Vt, Bt,
                                     Wm, Um, Vm, Bm, Wo, Uo, Vo, Bo);
    k_mininit<<<(NSTAGE * BATCH * CH + 255) / 256, 256>>>();

    // stage 0 (H=16): scalar
    k_stage<0><<<dim3(1, 4, 192), 256>>>(1);
    k_combine<16><<<(BATCH * CH * 256 + 255) / 256, 256>>>(0, 0);
    // stage 1 (H=32): scalar
    k_stage<1><<<dim3(2, 8, 192), 256>>>(0);
    k_combine<32><<<(BATCH * CH * 1024 + 255) / 256, 256>>>(1, 1);
    // stage 2 (H=64): all three convs on tensor cores
    k_mma<64><<<dim3(4, 16, 192), 256>>>(1, 2);
    k_combine<64><<<(BATCH * CH * 4096 + 255) / 256, 256>>>(2, 0);
    // stage 3 (H=128)
    k_mma<128><<<dim3(8, 32, 192), 256>>>(0, 3);
    k_comfinal<<<(BATCH * 128 * 128 + 255) / 256, 256>>>((float*)d_out);
}

// round 9
// speedup vs baseline: 1.9808x; 1.3418x over previous
#include <cuda_runtime.h>
#include <cuda_bf16.h>
#include <cstdint>

#define BATCH 64
#define CH 8
#define NSTAGE 4

typedef uint32_t u32;
typedef __nv_bfloat16 bf16;

// ---------------- device scratch ----------------
__device__ float g_ctx[BATCH*32];
__device__ float g_wr[NSTAGE*BATCH*CH*CH*9];
__device__ float g_wt[NSTAGE*BATCH*CH*CH*16];
__device__ float g_wm[NSTAGE*BATCH*CH*CH*25];
__device__ bf16 g_wmbh[NSTAGE*BATCH*8*27*8];
__device__ bf16 g_wmbl[NSTAGE*BATCH*8*27*8];
__device__ bf16 g_wrbh[NSTAGE*BATCH*8*10*8];
__device__ bf16 g_wrbl[NSTAGE*BATCH*8*10*8];
__device__ bf16 g_wtbh[NSTAGE*BATCH*1024];
__device__ bf16 g_wtbl[NSTAGE*BATCH*1024];
__device__ float g_wo[BATCH*3*CH];
__device__ float g_br[NSTAGE*BATCH*CH];
__device__ float g_bt[NSTAGE*BATCH*CH];
__device__ float g_bm[NSTAGE*BATCH*CH];
__device__ float g_bo[BATCH*3];
__device__ __align__(16) float g_xA[BATCH*CH*32*32];
__device__ __align__(16) float g_xB[BATCH*CH*32*32];
__device__ __align__(16) float g_pos[BATCH*CH*128*128];   // chan-major (st0/1), pix-major (st2/3)
__device__ __align__(16) float g_neg[BATCH*CH*256*256];
__device__ __align__(16) float g_mul[BATCH*CH*256*256];
__device__ __align__(16) bf16 g_xph[BATCH*128*128*CH];    // pixel-major x hi
__device__ __align__(16) bf16 g_xpl[BATCH*128*128*CH];
__device__ __align__(16) float g_lxp[BATCH*128*128*CH];   // pixel-major log(|x|+1)
__device__ __align__(16) bf16 g_xuh[BATCH*256*256*CH];    // pixel-major upsampled lx hi
__device__ __align__(16) bf16 g_xul[BATCH*256*256*CH];
__device__ unsigned g_minpos[NSTAGE*BATCH*CH];
__device__ unsigned g_minneg[NSTAGE*BATCH*CH];
__device__ unsigned g_minmul[NSTAGE*BATCH*CH];

__device__ __forceinline__ float dln_f(float v, float mn) {
    float s = (v > 0.0f) ? 1.0f : -1.0f;
    float a = fabsf(v) - mn;
    return s * __logf(__logf(a + 2.718281828459045f) + 0.01f);
}

__device__ __forceinline__ void mma16816(float* c, u32 a0, u32 a1, u32 a2, u32 a3,
                                         u32 b0, u32 b1) {
    asm("mma.sync.aligned.m16n8k16.row.col.f32.bf16.bf16.f32 "
        "{%0,%1,%2,%3},{%4,%5,%6,%7},{%8,%9},{%0,%1,%2,%3};"
        : "+f"(c[0]), "+f"(c[1]), "+f"(c[2]), "+f"(c[3])
        : "r"(a0), "r"(a1), "r"(a2), "r"(a3), "r"(b0), "r"(b1));
}

// ---------------- gather ----------------
__global__ void k_gather(const int* __restrict__ ids, const float* __restrict__ cc,
                         const float* __restrict__ lat) {
    int t = blockIdx.x * blockDim.x + threadIdx.x;
    int T = gridDim.x * blockDim.x;
    for (int i = t; i < BATCH * 32; i += T) g_ctx[i] = cc[ids[i >> 5] * 32 + (i & 31)];
    for (int i = t; i < BATCH * CH * 256; i += T)
        g_xA[i] = lat[ids[i >> 11] * (CH * 256) + (i & 2047)];
}

__global__ void k_mininit() {
    int t = blockIdx.x * blockDim.x + threadIdx.x;
    if (t < NSTAGE * BATCH * CH) {
        g_minpos[t] = 0x7F800000u; g_minneg[t] = 0x7F800000u; g_minmul[t] = 0x7F800000u;
    }
}

// ---------------- dynamic weights ----------------
__global__ void k_weights(
    const float* __restrict__ Wr, const float* __restrict__ Ur, const float* __restrict__ Vr, const float* __restrict__ Br,
    const float* __restrict__ Wt, const float* __restrict__ Ut, const float* __restrict__ Vt, const float* __restrict__ Bt,
    const float* __restrict__ Wm, const float* __restrict__ Um, const float* __restrict__ Vm, const float* __restrict__ Bm,
    const float* __restrict__ Wo, const float* __restrict__ Uo, const float* __restrict__ Vo, const float* __restrict__ Bo)
{
    int inst = blockIdx.x, b = blockIdx.y, tid = threadIdx.x;
    __shared__ float sctx[32];
    __shared__ float su[128];
    __shared__ float sv[3200];
    if (tid < 32) sctx[tid] = g_ctx[b * 32 + tid];
    __syncthreads();

    int O, KK, type = -1, stage = 0;
    const float *U, *V, *W, *Bb;
    float *gw, *gb;
    if (inst < 12) {
        type = inst >> 2; stage = inst & 3;
        O = CH;
        if (type == 0)      { KK = 9;  U = Ur; V = Vr; W = Wr; Bb = Br; gw = g_wr; gb = g_br; }
        else if (type == 1) { KK = 16; U = Ut; V = Vt; W = Wt; Bb = Bt; gw = g_wt; gb = g_bt; }
        else                { KK = 25; U = Um; V = Vm; W = Wm; Bb = Bm; gw = g_wm; gb = g_bm; }
        int uL = 16 * O, vL = 16 * CH * KK;
        U += (size_t)stage * 32 * uL; V += (size_t)stage * 32 * vL;
        W += (size_t)stage * O * CH * KK; Bb += (size_t)stage * 32 * O;
        gw += (size_t)(stage * BATCH + b) * O * CH * KK;
        gb += (size_t)(stage * BATCH + b) * O;
    } else {
        O = 3; KK = 1;
        U = Uo; V = Vo; W = Wo; Bb = Bo;
        gw = g_wo + b * 3 * CH; gb = g_bo + b * 3;
    }
    int uLen = 16 * O, vLen = 16 * CH * KK, IKK = CH * KK, wN = O * IKK;
    int sb = stage * BATCH + b;

    for (int j = tid; j < uLen; j += blockDim.x) {
        float s = 0.f;
        #pragma unroll
        for (int l = 0; l < 32; l++) s += sctx[l] * U[l * uLen + j];
        su[j] = s;
    }
    for (int j = tid; j < vLen; j += blockDim.x) {
        float s = 0.f;
        #pragma unroll
        for (int l = 0; l < 32; l++) s += sctx[l] * V[l * vLen + j];
        sv[j] = s;
    }
    __syncthreads();

    for (int widx = tid; widx < wN; widx += blockDim.x) {
        int o = widx / IKK, k = widx - o * IKK;
        float m = 0.f;
        #pragma unroll
        for (int r = 0; r < 16; r++) m += su[r * O + o] * sv[r * IKK + k];
        float w = W[widx] * (1.0f + m + 1e-3f);
        gw[widx] = w;
        if (type == 2) {
            int i = k / 25, t = k - i * 25;
            size_t d = (size_t)(sb * 8 + o) * 216 + t * 8 + i;
            bf16 h = __float2bfloat16(w);
            g_wmbh[d] = h;
            g_wmbl[d] = __float2bfloat16(w - __bfloat162float(h));
        } else if (type == 0) {
            int i = k / 9, t = k - i * 9;
            size_t d = (size_t)sb * 640 + (o * 10 + t) * 8 + i;
            bf16 h = __float2bfloat16(w);
            g_wrbh[d] = h;
            g_wrbl[d] = __float2bfloat16(w - __bfloat162float(h));
        } else if (type == 1) {
            int i = k / 16, t = k - i * 16;
            int ky = t >> 2, kx = t & 3;
            int py = (3 - ky) & 1, dy = (3 - ky) >> 1;
            int px = (3 - kx) & 1, dx = (3 - kx) >> 1;
            float wn = -w;
            size_t d = (size_t)sb * 1024 +
                       ((((size_t)(py * 2 + px) * 8 + o) * 2 + dy) * 2 + dx) * 8 + i;
            bf16 h = __float2bfloat16(wn);
            g_wtbh[d] = h;
            g_wtbl[d] = __float2bfloat16(wn - __bfloat162float(h));
        }
    }
    if (type == 2 && tid < 128) {
        int o = tid >> 4, t = 25 + ((tid >> 3) & 1), i = tid & 7;
        size_t d = (size_t)(sb * 8 + o) * 216 + t * 8 + i;
        g_wmbh[d] = __float2bfloat16(0.f);
        g_wmbl[d] = __float2bfloat16(0.f);
    }
    if (type == 0 && tid < 64) {
        int o = tid >> 3, i = tid & 7;
        size_t d = (size_t)sb * 640 + (o * 10 + 9) * 8 + i;
        g_wrbh[d] = __float2bfloat16(0.f);
        g_wrbl[d] = __float2bfloat16(0.f);
    }
    if (tid < O) {
        float s = 0.f;
        #pragma unroll
        for (int l = 0; l < 32; l++) s += sctx[l] * Bb[l * O + tid];
        gb[tid] = s;
    }
}

// ---------------- scalar bodies (stages 0/1; channel-major) ----------------
template<int H, int TW, int TH>
__device__ __forceinline__ void conv3_body(float* sm, const float* xb, int b,
                                           int x0, int y0, int tid, int stage) {
    constexpr int IW = TW + 2, IH = TH + 2;
    float* sIn = sm;
    float* sW  = sm + CH * IH * IW;
    float* sB  = sW + CH * CH * 9;
    const float* wsrc = g_wr + (size_t)(stage * BATCH + b) * CH * CH * 9;
    for (int j = tid; j < CH * CH * 9; j += 256) sW[j] = wsrc[j];
    if (tid < CH) sB[tid] = g_br[(stage * BATCH + b) * CH + tid];
    for (int j = tid; j < CH * IH * IW; j += 256) {
        int i = j / (IH * IW);
        int rem = j - i * IH * IW;
        int r = rem / IW, c = rem - r * IW;
        int gy = y0 - 1 + r, gx = x0 - 1 + c;
        float v = 0.f;
        if ((unsigned)gy < (unsigned)H && (unsigned)gx < (unsigned)H)
            v = xb[i * H * H + gy * H + gx];
        sIn[j] = v;
    }
    __syncthreads();
    if (tid < TW * CH) {
        int tx = tid & (TW - 1);
        int o  = tid / TW;
        float acc[TH];
        float bias = sB[o];
        #pragma unroll
        for (int y = 0; y < TH; y++) acc[y] = bias;
        #pragma unroll
        for (int i = 0; i < CH; i++) {
            float w[9];
            #pragma unroll
            for (int k = 0; k < 9; k++) w[k] = sW[(o * CH + i) * 9 + k];
            #pragma unroll
            for (int r = 0; r < IH; r++) {
                float v[3];
                #pragma unroll
                for (int k = 0; k < 3; k++) v[k] = sIn[(i * IH + r) * IW + tx + k];
                #pragma unroll
                for (int ky = 0; ky < 3; ky++) {
                    int y = r - ky;
                    if (y >= 0 && y < TH) {
                        #pragma unroll
                        for (int kx = 0; kx < 3; kx++) acc[y] += v[kx] * w[ky * 3 + kx];
                    }
                }
            }
        }
        int bo = b * CH + o;
        float* outp = g_pos + (size_t)bo * H * H;
        float mn = 3.4e38f;
        #pragma unroll
        for (int y = 0; y < TH; y++) {
            outp[(y0 + y) * H + x0 + tx] = acc[y];
            mn = fminf(mn, fabsf(acc[y]));
        }
        #pragma unroll
        for (int off = TW / 2; off > 0; off >>= 1)
            mn = fminf(mn, __shfl_down_sync(0xFFFFFFFFu, mn, off, TW));
        if (tx == 0) atomicMin(&g_minpos[stage * BATCH * CH + bo], __float_as_uint(mn));
    }
}

template<int H>
__device__ __forceinline__ void convt_body(float* sm, const float* x, int b,
                                           int x0, int y0, int tid, int stage) {
    constexpr int OH = 2 * H;
    constexpr int TW = 32, TH = 8;
    constexpr int IWT = 18, IHT = 6;
    float* sIn = sm;
    float* sW  = sm + CH * IHT * IWT;
    float* sB  = sW + CH * CH * 16;
    const float* wsrc = g_wt + (size_t)(stage * BATCH + b) * CH * CH * 16;
    if (tid < CH) sB[tid] = g_bt[(stage * BATCH + b) * CH + tid];
    for (int j = tid; j < CH * CH * 16; j += 256) sW[j] = wsrc[j];
    int ix0 = x0 / 2 - 1, iy0 = y0 / 2 - 1;
    for (int j = tid; j < CH * IHT * IWT; j += 256) {
        int i = j / (IHT * IWT);
        int rem = j - i * IHT * IWT;
        int r = rem / IWT, c = rem - r * IWT;
        int gy = iy0 + r, gx = ix0 + c;
        float v = 0.f;
        if ((unsigned)gy < (unsigned)H && (unsigned)gx < (unsigned)H)
            v = x[i * H * H + gy * H + gx];
        sIn[j] = v;
    }
    __syncthreads();
    int tx = tid & 31, o = tid >> 5;
    int px = tx & 1;
    int cA = (tx >> 1) + px;
    float acc[TH];
    float bias = sB[o];
    #pragma unroll
    for (int y = 0; y < TH; y++) acc[y] = bias;
    #pragma unroll
    for (int i = 0; i < CH; i++) {
        float wA[4], wB[4];
        #pragma unroll
        for (int ky = 0; ky < 4; ky++) {
            wA[ky] = sW[(o * CH + i) * 16 + ky * 4 + (3 - px)];
            wB[ky] = sW[(o * CH + i) * 16 + ky * 4 + (1 - px)];
        }
        float vA[IHT], vB[IHT];
        #pragma unroll
        for (int r = 0; r < IHT; r++) {
            vA[r] = sIn[(i * IHT + r) * IWT + cA];
            vB[r] = sIn[(i * IHT + r) * IWT + cA + 1];
        }
        #pragma unroll
        for (int ty = 0; ty < TH; ty++) {
            const int py = ty & 1;
            const int r = (ty >> 1) + py;
            acc[ty] -= vA[r] * wA[3 - py] + vB[r] * wB[3 - py]
                     + vA[r + 1] * wA[1 - py] + vB[r + 1] * wB[1 - py];
        }
    }
    int bo = b * CH + o;
    float* outp = g_neg + (size_t)bo * OH * OH;
    float mn = 3.4e38f;
    #pragma unroll
    for (int y = 0; y < TH; y++) {
        outp[(y0 + y) * OH + x0 + tx] = acc[y];
        mn = fminf(mn, fabsf(acc[y]));
    }
    #pragma unroll
    for (int off = 16; off > 0; off >>= 1)
        mn = fminf(mn, __shfl_down_sync(0xFFFFFFFFu, mn, off));
    if (tx == 0) atomicMin(&g_minneg[stage * BATCH * CH + bo], __float_as_uint(mn));
}

template<int H>
__device__ __forceinline__ void conv5_body(float* sm, const float* xb, int b,
                                           int x0, int y0, int tid, int stage) {
    constexpr int OH = 2 * H;
    constexpr int LH = 8, LW = 20;
    constexpr int IH = 12, IW = 36;
    float* sLx = sm;
    float* sXu = sm + CH * LH * LW;
    float* sW  = sXu + CH * IH * IW;
    float* sB  = sW + CH * CH * 25;
    const float* wsrc = g_wm + (size_t)(stage * BATCH + b) * CH * CH * 25;
    for (int j = tid; j < CH * CH * 25; j += 256) sW[j] = wsrc[j];
    if (tid < CH) sB[tid] = g_bm[(stage * BATCH + b) * CH + tid];
    int gyLo = ((y0 - 2) >> 1) - 1;
    int gxLo = ((x0 - 2) >> 1) - 1;
    for (int j = tid; j < CH * LH * LW; j += 256) {
        int i = j / (LH * LW);
        int rem = j - i * LH * LW;
        int r = rem / LW, c = rem - r * LW;
        int gy = gyLo + r, gx = gxLo + c;
        float v = 0.f;
        if ((unsigned)gy < (unsigned)H && (unsigned)gx < (unsigned)H)
            v = __logf(fabsf(xb[i * H * H + gy * H + gx]) + 1.0f);
        sLx[j] = v;
    }
    __syncthreads();
    for (int j = tid; j < CH * IH * IW; j += 256) {
        int i = j / (IH * IW);
        int rem = j - i * IH * IW;
        int r = rem / IW, c = rem - r * IW;
        int Y = y0 - 2 + r, X = x0 - 2 + c;
        float v = 0.f;
        if ((unsigned)Y < (unsigned)OH && (unsigned)X < (unsigned)OH) {
            int iy = Y >> 1, ix = X >> 1;
            int yo = (Y & 1) ? min(iy + 1, H - 1) : max(iy - 1, 0);
            int xo = (X & 1) ? min(ix + 1, H - 1) : max(ix - 1, 0);
            const float* L = sLx + i * LH * LW;
            int ry = iy - gyLo, ryo = yo - gyLo;
            int cx = ix - gxLo, cxo = xo - gxLo;
            v = 0.5625f * L[ry * LW + cx] + 0.1875f * L[ry * LW + cxo]
              + 0.1875f * L[ryo * LW + cx] + 0.0625f * L[ryo * LW + cxo];
        }
        sXu[j] = v;
    }
    __syncthreads();
    int tx = tid & 31, o = tid >> 5;
    float acc[8];
    float bias = sB[o];
    #pragma unroll
    for (int y = 0; y < 8; y++) acc[y] = bias;
    #pragma unroll
    for (int i = 0; i < CH; i++) {
        float w[25];
        #pragma unroll
        for (int k = 0; k < 25; k++) w[k] = sW[(o * CH + i) * 25 + k];
        #pragma unroll
        for (int r = 0; r < IH; r++) {
            float v[5];
            #pragma unroll
            for (int k = 0; k < 5; k++) v[k] = sXu[(i * IH + r) * IW + tx + k];
            #pragma unroll
            for (int ky = 0; ky < 5; ky++) {
                int y = r - ky;
                if (y >= 0 && y < 8) {
                    #pragma unroll
                    for (int kx = 0; kx < 5; kx++) acc[y] += v[kx] * w[ky * 5 + kx];
                }
            }
        }
    }
    int bo = b * CH + o;
    float* outp = g_mul + (size_t)bo * OH * OH;
    float mn = 3.4e38f;
    #pragma unroll
    for (int y = 0; y < 8; y++) {
        outp[(y0 + y) * OH + x0 + tx] = acc[y];
        mn = fminf(mn, fabsf(acc[y]));
    }
    #pragma unroll
    for (int off = 16; off > 0; off >>= 1)
        mn = fminf(mn, __shfl_down_sync(0xFFFFFFFFu, mn, off));
    if (tx == 0) atomicMin(&g_minmul[stage * BATCH * CH + bo], __float_as_uint(mn));
}

// ---------------- small-stage superkernel ----------------
template<int STAGE>
__global__ __launch_bounds__(256) void k_stage(int srcA) {
    constexpr int H = 16 << STAGE;
    __shared__ float smem[6400];
    int role = blockIdx.z >> 6;
    int b = blockIdx.z & 63;
    int tid = threadIdx.x;
    const float* xb = (srcA ? g_xA : g_xB) + (size_t)b * CH * H * H;
    if (role == 0) {
        constexpr int TW = (STAGE == 0) ? 16 : 32;
        if ((int)blockIdx.x >= H / TW || (int)blockIdx.y >= H / 8) return;
        conv3_body<H, TW, 8>(smem, xb, b, blockIdx.x * TW, blockIdx.y * 8, tid, STAGE);
    } else if (role == 1) {
        convt_body<H>(smem, xb, b, blockIdx.x * 32, blockIdx.y * 8, tid, STAGE);
    } else {
        conv5_body<H>(smem, xb, b, blockIdx.x * 32, blockIdx.y * 8, tid, STAGE);
    }
}

// ---------------- combineA (stage 0): chan-in, chan-out ----------------
template<int H>
__global__ __launch_bounds__(256) void k_combineA(int stage, int dstA) {
    constexpr int OH = 2 * H;
    constexpr int NH = H * H;
    int t = blockIdx.x * 256 + threadIdx.x;
    if (t >= BATCH * CH * NH) return;
    int bc = t / NH;
    int rem = t - bc * NH;
    int y = rem / H, x = rem - y * H;
    float mnp = __uint_as_float(g_minpos[stage * BATCH * CH + bc]);
    float mnn = __uint_as_float(g_minneg[stage * BATCH * CH + bc]);
    float mnm = __uint_as_float(g_minmul[stage * BATCH * CH + bc]);
    float dp = dln_f(g_pos[(size_t)bc * NH + rem], mnp);
    const float2* neg2 = (const float2*)(g_neg + (size_t)bc * OH * OH);
    const float2* mul2 = (const float2*)(g_mul + (size_t)bc * OH * OH);
    float2* dst2 = (float2*)((dstA ? g_xA : g_xB) + (size_t)bc * OH * OH);
    #pragma unroll
    for (int dy = 0; dy < 2; dy++) {
        int row = 2 * y + dy;
        float2 n = neg2[row * (OH / 2) + x];
        float2 m = mul2[row * (OH / 2) + x];
        float2 r;
        r.x = (dp + dln_f(n.x, mnn)) * dln_f(m.x, mnm);
        r.y = (dp + dln_f(n.y, mnn)) * dln_f(m.y, mnm);
        dst2[row * (OH / 2) + x] = r;
    }
}

// ---------------- combine to pixel-major: writes xph/xpl/lxp ----------------
// CHANIN=1: pos/neg/mul channel-major (scalar stage); else pixel-major (mma stage)
template<int H, int CHANIN>
__global__ __launch_bounds__(256) void k_combineP(int stage) {
    constexpr int OH = 2 * H;
    int b = blockIdx.y;
    int p = blockIdx.x * 256 + threadIdx.x;
    if (p >= OH * OH) return;
    int Y = p / OH, X = p - Y * OH;
    int pp = (Y >> 1) * H + (X >> 1);
    __shared__ float sMn[3 * CH];
    if (threadIdx.x < 3 * CH) {
        int c = threadIdx.x & 7, which = threadIdx.x >> 3;
        const unsigned* src = which == 0 ? g_minpos : (which == 1 ? g_minneg : g_minmul);
        sMn[threadIdx.x] = __uint_as_float(src[stage * BATCH * CH + b * CH + c]);
    }
    __syncthreads();

    float pos[CH], ng[CH], ml[CH];
    if (CHANIN) {
        #pragma unroll
        for (int c = 0; c < CH; c++) {
            int bc = b * CH + c;
            pos[c] = g_pos[(size_t)bc * H * H + pp];
            ng[c] = g_neg[(size_t)bc * OH * OH + p];
            ml[c] = g_mul[(size_t)bc * OH * OH + p];
        }
    } else {
        const float4* p4 = (const float4*)(g_pos + ((size_t)b * H * H + pp) * 8);
        const float4* n4 = (const float4*)(g_neg + ((size_t)b * OH * OH + p) * 8);
        const float4* m4 = (const float4*)(g_mul + ((size_t)b * OH * OH + p) * 8);
        float4 a0 = p4[0], a1 = p4[1];
        pos[0]=a0.x; pos[1]=a0.y; pos[2]=a0.z; pos[3]=a0.w;
        pos[4]=a1.x; pos[5]=a1.y; pos[6]=a1.z; pos[7]=a1.w;
        a0 = n4[0]; a1 = n4[1];
        ng[0]=a0.x; ng[1]=a0.y; ng[2]=a0.z; ng[3]=a0.w;
        ng[4]=a1.x; ng[5]=a1.y; ng[6]=a1.z; ng[7]=a1.w;
        a0 = m4[0]; a1 = m4[1];
        ml[0]=a0.x; ml[1]=a0.y; ml[2]=a0.z; ml[3]=a0.w;
        ml[4]=a1.x; ml[5]=a1.y; ml[6]=a1.z; ml[7]=a1.w;
    }

    uint4 hv, lv;
    bf16* hp = (bf16*)&hv;
    bf16* lp = (bf16*)&lv;
    float lx[CH];
    #pragma unroll
    for (int c = 0; c < CH; c++) {
        float dp = dln_f(pos[c], sMn[c]);
        float xv = (dp + dln_f(ng[c], sMn[8 + c])) * dln_f(ml[c], sMn[16 + c]);
        bf16 h = __float2bfloat16(xv);
        hp[c] = h;
        lp[c] = __float2bfloat16(xv - __bfloat162float(h));
        lx[c] = __logf(fabsf(xv) + 1.0f);
    }
    size_t base = (size_t)b * OH * OH + p;
    ((uint4*)g_xph)[base] = hv;
    ((uint4*)g_xpl)[base] = lv;
    float4* lxd = (float4*)(g_lxp + base * 8);
    lxd[0] = make_float4(lx[0], lx[1], lx[2], lx[3]);
    lxd[1] = make_float4(lx[4], lx[5], lx[6], lx[7]);
}

// ---------------- xumake: bilinear upsample lxp(H) -> xuh/xul(2H), bf16 split ----------------
template<int H>
__global__ __launch_bounds__(256) void k_xumake() {
    constexpr int OH = 2 * H;
    int b = blockIdx.y;
    int p = blockIdx.x * 256 + threadIdx.x;
    if (p >= OH * OH) return;
    int Y = p / OH, X = p - Y * OH;
    int iy = Y >> 1, ix = X >> 1;
    int yo = (Y & 1) ? min(iy + 1, H - 1) : max(iy - 1, 0);
    int xo = (X & 1) ? min(ix + 1, H - 1) : max(ix - 1, 0);
    const float* L = g_lxp + (size_t)b * H * H * 8;
    const float4* A = (const float4*)(L + (size_t)(iy * H + ix) * 8);
    const float4* Bq = (const float4*)(L + (size_t)(iy * H + xo) * 8);
    const float4* Cq = (const float4*)(L + (size_t)(yo * H + ix) * 8);
    const float4* D = (const float4*)(L + (size_t)(yo * H + xo) * 8);
    uint4 hv, lv;
    bf16* hp = (bf16*)&hv;
    bf16* lp = (bf16*)&lv;
    #pragma unroll
    for (int half = 0; half < 2; half++) {
        float4 a = A[half], bb = Bq[half], cc = Cq[half], d = D[half];
        float v[4];
        v[0] = 0.5625f * a.x + 0.1875f * bb.x + 0.1875f * cc.x + 0.0625f * d.x;
        v[1] = 0.5625f * a.y + 0.1875f * bb.y + 0.1875f * cc.y + 0.0625f * d.y;
        v[2] = 0.5625f * a.z + 0.1875f * bb.z + 0.1875f * cc.z + 0.0625f * d.z;
        v[3] = 0.5625f * a.w + 0.1875f * bb.w + 0.1875f * cc.w + 0.0625f * d.w;
        #pragma unroll
        for (int k = 0; k < 4; k++) {
            bf16 h = __float2bfloat16(v[k]);
            hp[half * 4 + k] = h;
            lp[half * 4 + k] = __float2bfloat16(v[k] - __bfloat162float(h));
        }
    }
    size_t base = (size_t)b * OH * OH + p;
    ((uint4*)g_xuh)[base] = hv;
    ((uint4*)g_xul)[base] = lv;
}

// ---------------- big-stage mma superkernel (stages 2/3), pixel-major I/O ----------------
template<int H>
__global__ __launch_bounds__(256) void k_mma(int stage) {
    constexpr int OH = 2 * H;
    __shared__ __align__(16) u32 sm[5220];
    int role = blockIdx.z >> 6;
    int b = blockIdx.z & 63;
    int tid = threadIdx.x;
    int bx = blockIdx.x, by = blockIdx.y;
    int w_ = tid >> 5, lane = tid & 31, g = lane >> 2, tg = lane & 3;

    if (role == 0) {
        // ---- conv3 mma at H res ----
        if (bx >= H / 32 || by >= H / 8) return;
        u32* XH = sm;            // 1360
        u32* XL = sm + 1360;
        u32* WH = sm + 2720;     // 320
        u32* WL = sm + 3040;
        float* sB = (float*)(sm + 3360);
        unsigned* sMin = (unsigned*)(sm + 3372);
        int x0 = bx * 32, y0 = by * 8;
        const bf16* wh = g_wrbh + (size_t)(stage * BATCH + b) * 640;
        const bf16* wl = g_wrbl + (size_t)(stage * BATCH + b) * 640;
        bf16* swh = (bf16*)WH;
        bf16* swl = (bf16*)WL;
        for (int j = tid; j < 640; j += 256) { swh[j] = wh[j]; swl[j] = wl[j]; }
        if (tid < 8) { sB[tid] = g_br[(stage * BATCH + b) * CH + tid]; sMin[tid] = 0x7F800000u; }
        const uint4* xh4 = (const uint4*)g_xph + (size_t)b * H * H;
        const uint4* xl4 = (const uint4*)g_xpl + (size_t)b * H * H;
        for (int j = tid; j < 10 * 34; j += 256) {
            int r = j / 34, c = j - 34 * r;
            int gy = y0 - 1 + r, gx = x0 - 1 + c;
            uint4 v = make_uint4(0, 0, 0, 0), w2 = make_uint4(0, 0, 0, 0);
            if ((unsigned)gy < (unsigned)H && (unsigned)gx < (unsigned)H) {
                v = xh4[gy * H + gx]; w2 = xl4[gy * H + gx];
            }
            ((uint4*)XH)[j] = v; ((uint4*)XL)[j] = w2;
        }
        __syncthreads();

        float b0f = sB[2 * tg], b1f = sB[2 * tg + 1];
        float c0[4] = {b0f, b1f, b0f, b1f};
        float c1[4] = {b0f, b1f, b0f, b1f};
        #pragma unroll
        for (int k = 0; k < 5; k++) {
            const int t0 = 2 * k, t1 = 2 * k + 1;
            const int t1c = (t1 < 9) ? t1 : 0;
            const int ky0 = t0 / 3, kx0 = t0 % 3;
            const int ky1 = t1c / 3, kx1 = t1c % 3;
            u32 bh0 = WH[(g * 10 + t0) * 4 + tg], bh1 = WH[(g * 10 + t1) * 4 + tg];
            u32 bl0 = WL[(g * 10 + t0) * 4 + tg], bl1 = WL[(g * 10 + t1) * 4 + tg];
            #pragma unroll
            for (int s = 0; s < 2; s++) {
                int xbse = s * 16 + g;
                int p0 = ((w_ + ky0) * 34 + xbse + kx0) * 4 + tg;
                int p1 = ((w_ + ky1) * 34 + xbse + kx1) * 4 + tg;
                u32 a0h = XH[p0], a1h = XH[p0 + 32], a2h = XH[p1], a3h = XH[p1 + 32];
                u32 a0l = XL[p0], a1l = XL[p0 + 32], a2l = XL[p1], a3l = XL[p1 + 32];
                float* cc = s ? c1 : c0;
                mma16816(cc, a0h, a1h, a2h, a3h, bh0, bh1);
                mma16816(cc, a0l, a1l, a2l, a3l, bh0, bh1);
                mma16816(cc, a0h, a1h, a2h, a3h, bl0, bl1);
            }
        }
        int Y = y0 + w_;
        float* outp = g_pos + (size_t)b * H * H * 8;   // pixel-major
        float me = 3.4e38f, mo = 3.4e38f;
        #pragma unroll
        for (int s = 0; s < 2; s++) {
            float* cc = s ? c1 : c0;
            int X = x0 + s * 16 + g;
            *(float2*)&outp[(size_t)(Y * H + X) * 8 + 2 * tg] = make_float2(cc[0], cc[1]);
            *(float2*)&outp[(size_t)(Y * H + X + 8) * 8 + 2 * tg] = make_float2(cc[2], cc[3]);
            me = fminf(me, fminf(fabsf(cc[0]), fabsf(cc[2])));
            mo = fminf(mo, fminf(fabsf(cc[1]), fabsf(cc[3])));
        }
        #pragma unroll
        for (int off = 16; off >= 4; off >>= 1) {
            me = fminf(me, __shfl_xor_sync(0xFFFFFFFFu, me, off));
            mo = fminf(mo, __shfl_xor_sync(0xFFFFFFFFu, mo, off));
        }
        if (lane < 4) {
            atomicMin(&sMin[2 * tg], __float_as_uint(me));
            atomicMin(&sMin[2 * tg + 1], __float_as_uint(mo));
        }
        __syncthreads();
        if (tid < 8) atomicMin(&g_minpos[stage * BATCH * CH + b * CH + tid], sMin[tid]);

    } else if (role == 1) {
        // ---- convT mma at OH res ----
        u32* XH = sm;            // 432
        u32* XL = sm + 432;
        u32* WH = sm + 864;      // 512
        u32* WL = sm + 1376;
        float* sB = (float*)(sm + 1888);
        unsigned* sMin = (unsigned*)(sm + 1900);
        int x0 = bx * 32, y0 = by * 8;
        const bf16* wh = g_wtbh + (size_t)(stage * BATCH + b) * 1024;
        const bf16* wl = g_wtbl + (size_t)(stage * BATCH + b) * 1024;
        bf16* swh = (bf16*)WH;
        bf16* swl = (bf16*)WL;
        for (int j = tid; j < 1024; j += 256) { swh[j] = wh[j]; swl[j] = wl[j]; }
        if (tid < 8) { sB[tid] = g_bt[(stage * BATCH + b) * CH + tid]; sMin[tid] = 0x7F800000u; }
        int iy0 = y0 / 2 - 1, ix0 = x0 / 2 - 1;
        const uint4* xh4 = (const uint4*)g_xph + (size_t)b * H * H;
        const uint4* xl4 = (const uint4*)g_xpl + (size_t)b * H * H;
        for (int j = tid; j < 6 * 18; j += 256) {
            int r = j / 18, c = j - 18 * r;
            int gy = iy0 + r, gx = ix0 + c;
            uint4 v = make_uint4(0, 0, 0, 0), w2 = make_uint4(0, 0, 0, 0);
            if ((unsigned)gy < (unsigned)H && (unsigned)gx < (unsigned)H) {
                v = xh4[gy * H + gx]; w2 = xl4[gy * H + gx];
            }
            ((uint4*)XH)[j] = v; ((uint4*)XL)[j] = w2;
        }
        __syncthreads();

        int py = w_ & 1;
        int r0 = (w_ >> 1) + py;
        float b0f = sB[2 * tg], b1f = sB[2 * tg + 1];
        int Y = y0 + w_;
        float* outp = g_neg + (size_t)b * OH * OH * 8;  // pixel-major
        float me = 3.4e38f, mo = 3.4e38f;
        #pragma unroll
        for (int px = 0; px < 2; px++) {
            float cc[4] = {b0f, b1f, b0f, b1f};
            #pragma unroll
            for (int dy = 0; dy < 2; dy++) {
                int wb = ((((py * 2 + px) * 8 + g) * 2 + dy) * 2) * 4 + tg;
                u32 bh0 = WH[wb], bh1 = WH[wb + 4];
                u32 bl0 = WL[wb], bl1 = WL[wb + 4];
                int base0 = ((r0 + dy) * 18 + g + px) * 4 + tg;
                u32 a0h = XH[base0], a1h = XH[base0 + 32], a2h = XH[base0 + 4], a3h = XH[base0 + 36];
                u32 a0l = XL[base0], a1l = XL[base0 + 32], a2l = XL[base0 + 4], a3l = XL[base0 + 36];
                mma16816(cc, a0h, a1h, a2h, a3h, bh0, bh1);
                mma16816(cc, a0l, a1l, a2l, a3l, bh0, bh1);
                mma16816(cc, a0h, a1h, a2h, a3h, bl0, bl1);
            }
            int X0 = x0 + 2 * g + px;
            int X1 = x0 + 2 * (g + 8) + px;
            *(float2*)&outp[(size_t)(Y * OH + X0) * 8 + 2 * tg] = make_float2(cc[0], cc[1]);
            *(float2*)&outp[(size_t)(Y * OH + X1) * 8 + 2 * tg] = make_float2(cc[2], cc[3]);
            me = fminf(me, fminf(fabsf(cc[0]), fabsf(cc[2])));
            mo = fminf(mo, fminf(fabsf(cc[1]), fabsf(cc[3])));
        }
        #pragma unroll
        for (int off = 16; off >= 4; off >>= 1) {
            me = fminf(me, __shfl_xor_sync(0xFFFFFFFFu, me, off));
            mo = fminf(mo, __shfl_xor_sync(0xFFFFFFFFu, mo, off));
        }
        if (lane < 4) {
            atomicMin(&sMin[2 * tg], __float_as_uint(me));
            atomicMin(&sMin[2 * tg + 1], __float_as_uint(mo));
        }
        __syncthreads();
        if (tid < 8) atomicMin(&g_minneg[stage * BATCH * CH + b * CH + tid], sMin[tid]);

    } else {
        // ---- conv5 mma at OH res, input from precomputed xu ----
        u32* XuH = sm;           // 1728
        u32* XuL = sm + 1728;
        u32* WH = sm + 3456;     // 864
        u32* WL = sm + 4320;
        float* sB = (float*)(sm + 5184);
        unsigned* sMin = (unsigned*)(sm + 5196);
        int x0 = bx * 32, y0 = by * 8;
        const bf16* wh = g_wmbh + (size_t)((stage * BATCH + b) * 8) * 216;
        const bf16* wl = g_wmbl + (size_t)((stage * BATCH + b) * 8) * 216;
        bf16* swh = (bf16*)WH;
        bf16* swl = (bf16*)WL;
        for (int j = tid; j < 8 * 216; j += 256) { swh[j] = wh[j]; swl[j] = wl[j]; }
        if (tid < 8) { sB[tid] = g_bm[(stage * BATCH + b) * CH + tid]; sMin[tid] = 0x7F800000u; }
        const uint4* xh4 = (const uint4*)g_xuh + (size_t)b * OH * OH;
        const uint4* xl4 = (const uint4*)g_xul + (size_t)b * OH * OH;
        for (int j = tid; j < 12 * 36; j += 256) {
            int r = j / 36, c = j - 36 * r;
            int Y = y0 - 2 + r, X = x0 - 2 + c;
            uint4 v = make_uint4(0, 0, 0, 0), w2 = make_uint4(0, 0, 0, 0);
            if ((unsigned)Y < (unsigned)OH && (unsigned)X < (unsigned)OH) {
                v = xh4[Y * OH + X]; w2 = xl4[Y * OH + X];
            }
            ((uint4*)XuH)[j] = v; ((uint4*)XuL)[j] = w2;
        }
        __syncthreads();

        float b0f = sB[2 * tg], b1f = sB[2 * tg + 1];
        float c0[4] = {b0f, b1f, b0f, b1f};
        float c1[4] = {b0f, b1f, b0f, b1f};
        #pragma unroll
        for (int k = 0; k < 13; k++) {
            const int t0 = 2 * k, t1 = 2 * k + 1;
            const int ky0 = t0 / 5, kx0 = t0 % 5;
            const int ky1 = (t1 < 25) ? t1 / 5 : 0, kx1 = (t1 < 25) ? t1 % 5 : 0;
            u32 bh0 = WH[(g * 27 + t0) * 4 + tg], bh1 = WH[(g * 27 + t1) * 4 + tg];
            u32 bl0 = WL[(g * 27 + t0) * 4 + tg], bl1 = WL[(g * 27 + t1) * 4 + tg];
            #pragma unroll
            for (int s = 0; s < 2; s++) {
                int xbse = s * 16 + g;
                int p0 = ((w_ + ky0) * 36 + xbse + kx0) * 4 + tg;
                int p1 = ((w_ + ky1) * 36 + xbse + kx1) * 4 + tg;
                u32 a0h = XuH[p0], a1h = XuH[p0 + 32], a2h = XuH[p1], a3h = XuH[p1 + 32];
                u32 a0l = XuL[p0], a1l = XuL[p0 + 32], a2l = XuL[p1], a3l = XuL[p1 + 32];
                float* cc = s ? c1 : c0;
                mma16816(cc, a0h, a1h, a2h, a3h, bh0, bh1);
                mma16816(cc, a0l, a1l, a2l, a3l, bh0, bh1);
                mma16816(cc, a0h, a1h, a2h, a3h, bl0, bl1);
            }
        }
        int Y = y0 + w_;
        float* mulb = g_mul + (size_t)b * OH * OH * 8;  // pixel-major
        float me = 3.4e38f, mo = 3.4e38f;
        #pragma unroll
        for (int s = 0; s < 2; s++) {
            float* cc = s ? c1 : c0;
            int X = x0 + s * 16 + g;
            *(float2*)&mulb[(size_t)(Y * OH + X) * 8 + 2 * tg] = make_float2(cc[0], cc[1]);
            *(float2*)&mulb[(size_t)(Y * OH + X + 8) * 8 + 2 * tg] = make_float2(cc[2], cc[3]);
            me = fminf(me, fminf(fabsf(cc[0]), fabsf(cc[2])));
            mo = fminf(mo, fminf(fabsf(cc[1]), fabsf(cc[3])));
        }
        #pragma unroll
        for (int off = 16; off >= 4; off >>= 1) {
            me = fminf(me, __shfl_xor_sync(0xFFFFFFFFu, me, off));
            mo = fminf(mo, __shfl_xor_sync(0xFFFFFFFFu, mo, off));
        }
        if (lane < 4) {
            atomicMin(&sMin[2 * tg], __float_as_uint(me));
            atomicMin(&sMin[2 * tg + 1], __float_as_uint(mo));
        }
        __syncthreads();
        if (tid < 8) atomicMin(&g_minmul[stage * BATCH * CH + b * CH + tid], sMin[tid]);
    }
}

// ---------------- final combine + 1x1 conv (pixel-major in) ----------------
__global__ __launch_bounds__(256) void k_comfinal(float* __restrict__ out) {
    constexpr int H = 128, OH = 256;
    constexpr int stage = 3;
    int b = blockIdx.y;
    int p = blockIdx.x * 256 + threadIdx.x;  // < 65536
    int Y = p >> 8, X = p & 255;
    int pp = (Y >> 1) * H + (X >> 1);
    __shared__ float sMn[3 * CH];
    __shared__ float sWo[3 * CH];
    __shared__ float sBo[3];
    if (threadIdx.x < 3 * CH) {
        int c = threadIdx.x & 7, which = threadIdx.x >> 3;
        const unsigned* src = which == 0 ? g_minpos : (which == 1 ? g_minneg : g_minmul);
        sMn[threadIdx.x] = __uint_as_float(src[stage * BATCH * CH + b * CH + c]);
        sWo[threadIdx.x] = g_wo[b * 24 + threadIdx.x];
    }
    if (threadIdx.x >= 32 && threadIdx.x < 35) sBo[threadIdx.x - 32] = g_bo[b * 3 + threadIdx.x - 32];
    __syncthreads();

    const float4* p4 = (const float4*)(g_pos + ((size_t)b * H * H + pp) * 8);
    const float4* n4 = (const float4*)(g_neg + ((size_t)b * OH * OH + p) * 8);
    const float4* m4 = (const float4*)(g_mul + ((size_t)b * OH * OH + p) * 8);
    float pos[8], ng[8], ml[8];
    float4 a0 = p4[0], a1 = p4[1];
    pos[0]=a0.x; pos[1]=a0.y; pos[2]=a0.z; pos[3]=a0.w; pos[4]=a1.x; pos[5]=a1.y; pos[6]=a1.z; pos[7]=a1.w;
    a0 = n4[0]; a1 = n4[1];
    ng[0]=a0.x; ng[1]=a0.y; ng[2]=a0.z; ng[3]=a0.w; ng[4]=a1.x; ng[5]=a1.y; ng[6]=a1.z; ng[7]=a1.w;
    a0 = m4[0]; a1 = m4[1];
    ml[0]=a0.x; ml[1]=a0.y; ml[2]=a0.z; ml[3]=a0.w; ml[4]=a1.x; ml[5]=a1.y; ml[6]=a1.z; ml[7]=a1.w;

    float acc[3] = {sBo[0], sBo[1], sBo[2]};
    #pragma unroll
    for (int c = 0; c < CH; c++) {
        float dp = dln_f(pos[c], sMn[c]);
        float xv = (dp + dln_f(ng[c], sMn[8 + c])) * dln_f(ml[c], sMn[16 + c]);
        #pragma unroll
        for (int o = 0; o < 3; o++) acc[o] += sWo[o * CH + c] * xv;
    }
    #pragma unroll
    for (int o = 0; o < 3; o++)
        out[((size_t)b * 3 + o) * OH * OH + p] = acc[o];
}

// ---------------- launcher ----------------
extern "C" void kernel_launch(void* const* d_in, const int* in_sizes, int n_in,
                              void* d_out, int out_size) {
    const int*   ids = (const int*)  d_in[0];
    const float* cc  = (const float*)d_in[1];
    const float* lat = (const float*)d_in[2];
    const float* Wr = (const float*)d_in[3];
    const float* Ur = (const float*)d_in[4];
    const float* Vr = (const float*)d_in[5];
    const float* Br = (const float*)d_in[6];
    const float* Wt = (const float*)d_in[7];
    const float* Ut = (const float*)d_in[8];
    const float* Vt = (const float*)d_in[9];
    const float* Bt = (const float*)d_in[10];
    const float* Wm = (const float*)d_in[11];
    const float* Um = (const float*)d_in[12];
    const float* Vm = (const float*)d_in[13];
    const float* Bm = (const float*)d_in[14];
    const float* Wo = (const float*)d_in[15];
    const float* Uo = (const float*)d_in[16];
    const float* Vo = (const float*)d_in[17];
    const float* Bo = (const float*)d_in[18];

    k_gather<<<64, 256>>>(ids, cc, lat);
    k_weights<<<dim3(13, 64), 128>>>(Wr, Ur, Vr, Br, Wt, Ut, Vt, Bt,
                                     Wm, Um, Vm, Bm, Wo, Uo, Vo, Bo);
    k_mininit<<<(NSTAGE * BATCH * CH + 255) / 256, 256>>>();

    // stage 0 (H=16): scalar, chan-major
    k_stage<0><<<dim3(1, 4, 192), 256>>>(1);
    k_combineA<16><<<(BATCH * CH * 256 + 255) / 256, 256>>>(0, 0);
    // stage 1 (H=32): scalar
    k_stage<1><<<dim3(2, 8, 192), 256>>>(0);
    k_combineP<32, 1><<<dim3(16, 64), 256>>>(1);       // -> xph/xpl/lxp @64
    k_xumake<64><<<dim3(64, 64), 256>>>();             // -> xu @128
    // stage 2 (H=64): tensor
    k_mma<64><<<dim3(4, 16, 192), 256>>>(2);
    k_combineP<64, 0><<<dim3(64, 64), 256>>>(2);       // -> xph/xpl/lxp @128
    k_xumake<128><<<dim3(256, 64), 256>>>();           // -> xu @256
    // stage 3 (H=128): tensor
    k_mma<128><<<dim3(8, 32, 192), 256>>>(3);
    k_comfinal<<<dim3(256, 64), 256>>>((float*)d_out);
}

// round 10
// speedup vs baseline: 2.0590x; 1.0395x over previous
#include <cuda_runtime.h>
#include <cuda_bf16.h>
#include <cstdint>

#define BATCH 64
#define CH 8
#define NSTAGE 4

typedef uint32_t u32;
typedef __nv_bfloat16 bf16;

// ---------------- device scratch ----------------
__device__ float g_ctx[BATCH*32];
__device__ float g_wr[NSTAGE*BATCH*CH*CH*9];
__device__ float g_wt[NSTAGE*BATCH*CH*CH*16];
__device__ float g_wm[NSTAGE*BATCH*CH*CH*25];
__device__ bf16 g_wmbh[NSTAGE*BATCH*8*27*8];
__device__ bf16 g_wmbl[NSTAGE*BATCH*8*27*8];
__device__ bf16 g_wrbh[NSTAGE*BATCH*8*10*8];
__device__ bf16 g_wrbl[NSTAGE*BATCH*8*10*8];
__device__ bf16 g_wtbh[NSTAGE*BATCH*1024];
__device__ bf16 g_wtbl[NSTAGE*BATCH*1024];
__device__ float g_wo[BATCH*3*CH];
__device__ float g_br[NSTAGE*BATCH*CH];
__device__ float g_bt[NSTAGE*BATCH*CH];
__device__ float g_bm[NSTAGE*BATCH*CH];
__device__ float g_bo[BATCH*3];
__device__ __align__(16) float g_pos[BATCH*128*128*CH];   // pixel-major
__device__ __align__(16) float g_neg[BATCH*256*256*CH];
__device__ __align__(16) float g_mul[BATCH*256*256*CH];
__device__ __align__(16) bf16 g_xph[BATCH*128*128*CH];    // pixel-major x hi
__device__ __align__(16) bf16 g_xpl[BATCH*128*128*CH];
__device__ __align__(16) float g_lxp[BATCH*128*128*CH];   // pixel-major log(|x|+1)
__device__ __align__(16) bf16 g_xuh[BATCH*256*256*CH];    // pixel-major upsampled lx hi
__device__ __align__(16) bf16 g_xul[BATCH*256*256*CH];
__device__ unsigned g_minpos[NSTAGE*BATCH*CH];
__device__ unsigned g_minneg[NSTAGE*BATCH*CH];
__device__ unsigned g_minmul[NSTAGE*BATCH*CH];

__device__ __forceinline__ float dln_f(float v, float mn) {
    float s = (v > 0.0f) ? 1.0f : -1.0f;
    float a = fabsf(v) - mn;
    return s * __logf(__logf(a + 2.718281828459045f) + 0.01f);
}

__device__ __forceinline__ void mma16816(float* c, u32 a0, u32 a1, u32 a2, u32 a3,
                                         u32 b0, u32 b1) {
    asm("mma.sync.aligned.m16n8k16.row.col.f32.bf16.bf16.f32 "
        "{%0,%1,%2,%3},{%4,%5,%6,%7},{%8,%9},{%0,%1,%2,%3};"
        : "+f"(c[0]), "+f"(c[1]), "+f"(c[2]), "+f"(c[3])
        : "r"(a0), "r"(a1), "r"(a2), "r"(a3), "r"(b0), "r"(b1));
}

// ---------------- gather: ctx + latents -> pixel-major xph/xpl/lxp @16 ----------------
__global__ __launch_bounds__(256) void k_gather(const int* __restrict__ ids,
                                                const float* __restrict__ cc,
                                                const float* __restrict__ lat) {
    int t = blockIdx.x * 256 + threadIdx.x;   // 64 blocks -> 16384 threads
    if (t < BATCH * 32) g_ctx[t] = cc[ids[t >> 5] * 32 + (t & 31)];
    int b = t >> 8, p = t & 255;
    const float* lb = lat + (size_t)ids[b] * (CH * 256);
    uint4 hv, lv;
    bf16* hp = (bf16*)&hv;
    bf16* lp = (bf16*)&lv;
    float lx[CH];
    #pragma unroll
    for (int c = 0; c < CH; c++) {
        float v = lb[c * 256 + p];
        bf16 h = __float2bfloat16(v);
        hp[c] = h;
        lp[c] = __float2bfloat16(v - __bfloat162float(h));
        lx[c] = __logf(fabsf(v) + 1.0f);
    }
    size_t base = (size_t)b * 256 + p;
    ((uint4*)g_xph)[base] = hv;
    ((uint4*)g_xpl)[base] = lv;
    float4* lxd = (float4*)(g_lxp + base * 8);
    lxd[0] = make_float4(lx[0], lx[1], lx[2], lx[3]);
    lxd[1] = make_float4(lx[4], lx[5], lx[6], lx[7]);
}

__global__ void k_mininit() {
    int t = blockIdx.x * blockDim.x + threadIdx.x;
    if (t < NSTAGE * BATCH * CH) {
        g_minpos[t] = 0x7F800000u; g_minneg[t] = 0x7F800000u; g_minmul[t] = 0x7F800000u;
    }
}

// ---------------- dynamic weights (unchanged from R9) ----------------
__global__ void k_weights(
    const float* __restrict__ Wr, const float* __restrict__ Ur, const float* __restrict__ Vr, const float* __restrict__ Br,
    const float* __restrict__ Wt, const float* __restrict__ Ut, const float* __restrict__ Vt, const float* __restrict__ Bt,
    const float* __restrict__ Wm, const float* __restrict__ Um, const float* __restrict__ Vm, const float* __restrict__ Bm,
    const float* __restrict__ Wo, const float* __restrict__ Uo, const float* __restrict__ Vo, const float* __restrict__ Bo)
{
    int inst = blockIdx.x, b = blockIdx.y, tid = threadIdx.x;
    __shared__ float sctx[32];
    __shared__ float su[128];
    __shared__ float sv[3200];
    if (tid < 32) sctx[tid] = g_ctx[b * 32 + tid];
    __syncthreads();

    int O, KK, type = -1, stage = 0;
    const float *U, *V, *W, *Bb;
    float *gw, *gb;
    if (inst < 12) {
        type = inst >> 2; stage = inst & 3;
        O = CH;
        if (type == 0)      { KK = 9;  U = Ur; V = Vr; W = Wr; Bb = Br; gw = g_wr; gb = g_br; }
        else if (type == 1) { KK = 16; U = Ut; V = Vt; W = Wt; Bb = Bt; gw = g_wt; gb = g_bt; }
        else                { KK = 25; U = Um; V = Vm; W = Wm; Bb = Bm; gw = g_wm; gb = g_bm; }
        int uL = 16 * O, vL = 16 * CH * KK;
        U += (size_t)stage * 32 * uL; V += (size_t)stage * 32 * vL;
        W += (size_t)stage * O * CH * KK; Bb += (size_t)stage * 32 * O;
        gw += (size_t)(stage * BATCH + b) * O * CH * KK;
        gb += (size_t)(stage * BATCH + b) * O;
    } else {
        O = 3; KK = 1;
        U = Uo; V = Vo; W = Wo; Bb = Bo;
        gw = g_wo + b * 3 * CH; gb = g_bo + b * 3;
    }
    int uLen = 16 * O, vLen = 16 * CH * KK, IKK = CH * KK, wN = O * IKK;
    int sb = stage * BATCH + b;

    for (int j = tid; j < uLen; j += blockDim.x) {
        float s = 0.f;
        #pragma unroll
        for (int l = 0; l < 32; l++) s += sctx[l] * U[l * uLen + j];
        su[j] = s;
    }
    for (int j = tid; j < vLen; j += blockDim.x) {
        float s = 0.f;
        #pragma unroll
        for (int l = 0; l < 32; l++) s += sctx[l] * V[l * vLen + j];
        sv[j] = s;
    }
    __syncthreads();

    for (int widx = tid; widx < wN; widx += blockDim.x) {
        int o = widx / IKK, k = widx - o * IKK;
        float m = 0.f;
        #pragma unroll
        for (int r = 0; r < 16; r++) m += su[r * O + o] * sv[r * IKK + k];
        float w = W[widx] * (1.0f + m + 1e-3f);
        gw[widx] = w;
        if (type == 2) {
            int i = k / 25, t = k - i * 25;
            size_t d = (size_t)(sb * 8 + o) * 216 + t * 8 + i;
            bf16 h = __float2bfloat16(w);
            g_wmbh[d] = h;
            g_wmbl[d] = __float2bfloat16(w - __bfloat162float(h));
        } else if (type == 0) {
            int i = k / 9, t = k - i * 9;
            size_t d = (size_t)sb * 640 + (o * 10 + t) * 8 + i;
            bf16 h = __float2bfloat16(w);
            g_wrbh[d] = h;
            g_wrbl[d] = __float2bfloat16(w - __bfloat162float(h));
        } else if (type == 1) {
            int i = k / 16, t = k - i * 16;
            int ky = t >> 2, kx = t & 3;
            int py = (3 - ky) & 1, dy = (3 - ky) >> 1;
            int px = (3 - kx) & 1, dx = (3 - kx) >> 1;
            float wn = -w;
            size_t d = (size_t)sb * 1024 +
                       ((((size_t)(py * 2 + px) * 8 + o) * 2 + dy) * 2 + dx) * 8 + i;
            bf16 h = __float2bfloat16(wn);
            g_wtbh[d] = h;
            g_wtbl[d] = __float2bfloat16(wn - __bfloat162float(h));
        }
    }
    if (type == 2 && tid < 128) {
        int o = tid >> 4, t = 25 + ((tid >> 3) & 1), i = tid & 7;
        size_t d = (size_t)(sb * 8 + o) * 216 + t * 8 + i;
        g_wmbh[d] = __float2bfloat16(0.f);
        g_wmbl[d] = __float2bfloat16(0.f);
    }
    if (type == 0 && tid < 64) {
        int o = tid >> 3, i = tid & 7;
        size_t d = (size_t)sb * 640 + (o * 10 + 9) * 8 + i;
        g_wrbh[d] = __float2bfloat16(0.f);
        g_wrbl[d] = __float2bfloat16(0.f);
    }
    if (tid < O) {
        float s = 0.f;
        #pragma unroll
        for (int l = 0; l < 32; l++) s += sctx[l] * Bb[l * O + tid];
        gb[tid] = s;
    }
}

// ---------------- mma superkernel (all stages), pixel-major I/O ----------------
template<int H>
__global__ __launch_bounds__(256) void k_mma(int stage) {
    constexpr int OH = 2 * H;
    __shared__ __align__(16) u32 sm[5220];
    int role = blockIdx.z >> 6;
    int b = blockIdx.z & 63;
    int tid = threadIdx.x;
    int bx = blockIdx.x, by = blockIdx.y;
    int w_ = tid >> 5, lane = tid & 31, g = lane >> 2, tg = lane & 3;

    if (role == 0) {
        // ---- conv3 mma at H res; x-tile = min(32,H) ----
        constexpr int BX3 = (H >= 32) ? H / 32 : 1;
        constexpr int SQ3 = (H >= 32) ? 2 : 1;
        if (bx >= BX3 || by >= H / 8) return;
        u32* XH = sm;            // 1360
        u32* XL = sm + 1360;
        u32* WH = sm + 2720;     // 320
        u32* WL = sm + 3040;
        float* sB = (float*)(sm + 3360);
        unsigned* sMin = (unsigned*)(sm + 3372);
        int x0 = bx * 32, y0 = by * 8;
        const bf16* wh = g_wrbh + (size_t)(stage * BATCH + b) * 640;
        const bf16* wl = g_wrbl + (size_t)(stage * BATCH + b) * 640;
        bf16* swh = (bf16*)WH;
        bf16* swl = (bf16*)WL;
        for (int j = tid; j < 640; j += 256) { swh[j] = wh[j]; swl[j] = wl[j]; }
        if (tid < 8) { sB[tid] = g_br[(stage * BATCH + b) * CH + tid]; sMin[tid] = 0x7F800000u; }
        const uint4* xh4 = (const uint4*)g_xph + (size_t)b * H * H;
        const uint4* xl4 = (const uint4*)g_xpl + (size_t)b * H * H;
        for (int j = tid; j < 10 * 34; j += 256) {
            int r = j / 34, c = j - 34 * r;
            int gy = y0 - 1 + r, gx = x0 - 1 + c;
            uint4 v = make_uint4(0, 0, 0, 0), w2 = make_uint4(0, 0, 0, 0);
            if ((unsigned)gy < (unsigned)H && (unsigned)gx < (unsigned)H) {
                v = xh4[gy * H + gx]; w2 = xl4[gy * H + gx];
            }
            ((uint4*)XH)[j] = v; ((uint4*)XL)[j] = w2;
        }
        __syncthreads();

        float b0f = sB[2 * tg], b1f = sB[2 * tg + 1];
        float c0[4] = {b0f, b1f, b0f, b1f};
        float c1[4] = {b0f, b1f, b0f, b1f};
        #pragma unroll
        for (int k = 0; k < 5; k++) {
            const int t0 = 2 * k, t1 = 2 * k + 1;
            const int t1c = (t1 < 9) ? t1 : 0;
            const int ky0 = t0 / 3, kx0 = t0 % 3;
            const int ky1 = t1c / 3, kx1 = t1c % 3;
            u32 bh0 = WH[(g * 10 + t0) * 4 + tg], bh1 = WH[(g * 10 + t1) * 4 + tg];
            u32 bl0 = WL[(g * 10 + t0) * 4 + tg], bl1 = WL[(g * 10 + t1) * 4 + tg];
            #pragma unroll
            for (int s = 0; s < SQ3; s++) {
                int xbse = s * 16 + g;
                int p0 = ((w_ + ky0) * 34 + xbse + kx0) * 4 + tg;
                int p1 = ((w_ + ky1) * 34 + xbse + kx1) * 4 + tg;
                u32 a0h = XH[p0], a1h = XH[p0 + 32], a2h = XH[p1], a3h = XH[p1 + 32];
                u32 a0l = XL[p0], a1l = XL[p0 + 32], a2l = XL[p1], a3l = XL[p1 + 32];
                float* cc = s ? c1 : c0;
                mma16816(cc, a0h, a1h, a2h, a3h, bh0, bh1);
                mma16816(cc, a0l, a1l, a2l, a3l, bh0, bh1);
                mma16816(cc, a0h, a1h, a2h, a3h, bl0, bl1);
            }
        }
        int Y = y0 + w_;
        float* outp = g_pos + (size_t)b * H * H * 8;   // pixel-major
        float me = 3.4e38f, mo = 3.4e38f;
        #pragma unroll
        for (int s = 0; s < SQ3; s++) {
            float* cc = s ? c1 : c0;
            int X = x0 + s * 16 + g;
            *(float2*)&outp[(size_t)(Y * H + X) * 8 + 2 * tg] = make_float2(cc[0], cc[1]);
            *(float2*)&outp[(size_t)(Y * H + X + 8) * 8 + 2 * tg] = make_float2(cc[2], cc[3]);
            me = fminf(me, fminf(fabsf(cc[0]), fabsf(cc[2])));
            mo = fminf(mo, fminf(fabsf(cc[1]), fabsf(cc[3])));
        }
        #pragma unroll
        for (int off = 16; off >= 4; off >>= 1) {
            me = fminf(me, __shfl_xor_sync(0xFFFFFFFFu, me, off));
            mo = fminf(mo, __shfl_xor_sync(0xFFFFFFFFu, mo, off));
        }
        if (lane < 4) {
            atomicMin(&sMin[2 * tg], __float_as_uint(me));
            atomicMin(&sMin[2 * tg + 1], __float_as_uint(mo));
        }
        __syncthreads();
        if (tid < 8) atomicMin(&g_minpos[stage * BATCH * CH + b * CH + tid], sMin[tid]);

    } else if (role == 1) {
        // ---- convT mma at OH res ----
        u32* XH = sm;            // 432
        u32* XL = sm + 432;
        u32* WH = sm + 864;      // 512
        u32* WL = sm + 1376;
        float* sB = (float*)(sm + 1888);
        unsigned* sMin = (unsigned*)(sm + 1900);
        int x0 = bx * 32, y0 = by * 8;
        const bf16* wh = g_wtbh + (size_t)(stage * BATCH + b) * 1024;
        const bf16* wl = g_wtbl + (size_t)(stage * BATCH + b) * 1024;
        bf16* swh = (bf16*)WH;
        bf16* swl = (bf16*)WL;
        for (int j = tid; j < 1024; j += 256) { swh[j] = wh[j]; swl[j] = wl[j]; }
        if (tid < 8) { sB[tid] = g_bt[(stage * BATCH + b) * CH + tid]; sMin[tid] = 0x7F800000u; }
        int iy0 = y0 / 2 - 1, ix0 = x0 / 2 - 1;
        const uint4* xh4 = (const uint4*)g_xph + (size_t)b * H * H;
        const uint4* xl4 = (const uint4*)g_xpl + (size_t)b * H * H;
        for (int j = tid; j < 6 * 18; j += 256) {
            int r = j / 18, c = j - 18 * r;
            int gy = iy0 + r, gx = ix0 + c;
            uint4 v = make_uint4(0, 0, 0, 0), w2 = make_uint4(0, 0, 0, 0);
            if ((unsigned)gy < (unsigned)H && (unsigned)gx < (unsigned)H) {
                v = xh4[gy * H + gx]; w2 = xl4[gy * H + gx];
            }
            ((uint4*)XH)[j] = v; ((uint4*)XL)[j] = w2;
        }
        __syncthreads();

        int py = w_ & 1;
        int r0 = (w_ >> 1) + py;
        float b0f = sB[2 * tg], b1f = sB[2 * tg + 1];
        int Y = y0 + w_;
        float* outp = g_neg + (size_t)b * OH * OH * 8;  // pixel-major
        float me = 3.4e38f, mo = 3.4e38f;
        #pragma unroll
        for (int px = 0; px < 2; px++) {
            float cc[4] = {b0f, b1f, b0f, b1f};
            #pragma unroll
            for (int dy = 0; dy < 2; dy++) {
                int wb = ((((py * 2 + px) * 8 + g) * 2 + dy) * 2) * 4 + tg;
                u32 bh0 = WH[wb], bh1 = WH[wb + 4];
                u32 bl0 = WL[wb], bl1 = WL[wb + 4];
                int base0 = ((r0 + dy) * 18 + g + px) * 4 + tg;
                u32 a0h = XH[base0], a1h = XH[base0 + 32], a2h = XH[base0 + 4], a3h = XH[base0 + 36];
                u32 a0l = XL[base0], a1l = XL[base0 + 32], a2l = XL[base0 + 4], a3l = XL[base0 + 36];
                mma16816(cc, a0h, a1h, a2h, a3h, bh0, bh1);
                mma16816(cc, a0l, a1l, a2l, a3l, bh0, bh1);
                mma16816(cc, a0h, a1h, a2h, a3h, bl0, bl1);
            }
            int X0 = x0 + 2 * g + px;
            int X1 = x0 + 2 * (g + 8) + px;
            *(float2*)&outp[(size_t)(Y * OH + X0) * 8 + 2 * tg] = make_float2(cc[0], cc[1]);
            *(float2*)&outp[(size_t)(Y * OH + X1) * 8 + 2 * tg] = make_float2(cc[2], cc[3]);
            me = fminf(me, fminf(fabsf(cc[0]), fabsf(cc[2])));
            mo = fminf(mo, fminf(fabsf(cc[1]), fabsf(cc[3])));
        }
        #pragma unroll
        for (int off = 16; off >= 4; off >>= 1) {
            me = fminf(me, __shfl_xor_sync(0xFFFFFFFFu, me, off));
            mo = fminf(mo, __shfl_xor_sync(0xFFFFFFFFu, mo, off));
        }
        if (lane < 4) {
            atomicMin(&sMin[2 * tg], __float_as_uint(me));
            atomicMin(&sMin[2 * tg + 1], __float_as_uint(mo));
        }
        __syncthreads();
        if (tid < 8) atomicMin(&g_minneg[stage * BATCH * CH + b * CH + tid], sMin[tid]);

    } else {
        // ---- conv5 mma at OH res, input from precomputed xu ----
        u32* XuH = sm;           // 1728
        u32* XuL = sm + 1728;
        u32* WH = sm + 3456;     // 864
        u32* WL = sm + 4320;
        float* sB = (float*)(sm + 5184);
        unsigned* sMin = (unsigned*)(sm + 5196);
        int x0 = bx * 32, y0 = by * 8;
        const bf16* wh = g_wmbh + (size_t)((stage * BATCH + b) * 8) * 216;
        const bf16* wl = g_wmbl + (size_t)((stage * BATCH + b) * 8) * 216;
        bf16* swh = (bf16*)WH;
        bf16* swl = (bf16*)WL;
        for (int j = tid; j < 8 * 216; j += 256) { swh[j] = wh[j]; swl[j] = wl[j]; }
        if (tid < 8) { sB[tid] = g_bm[(stage * BATCH + b) * CH + tid]; sMin[tid] = 0x7F800000u; }
        const uint4* xh4 = (const uint4*)g_xuh + (size_t)b * OH * OH;
        const uint4* xl4 = (const uint4*)g_xul + (size_t)b * OH * OH;
        for (int j = tid; j < 12 * 36; j += 256) {
            int r = j / 36, c = j - 36 * r;
            int Y = y0 - 2 + r, X = x0 - 2 + c;
            uint4 v = make_uint4(0, 0, 0, 0), w2 = make_uint4(0, 0, 0, 0);
            if ((unsigned)Y < (unsigned)OH && (unsigned)X < (unsigned)OH) {
                v = xh4[Y * OH + X]; w2 = xl4[Y * OH + X];
            }
            ((uint4*)XuH)[j] = v; ((uint4*)XuL)[j] = w2;
        }
        __syncthreads();

        float b0f = sB[2 * tg], b1f = sB[2 * tg + 1];
        float c0[4] = {b0f, b1f, b0f, b1f};
        float c1[4] = {b0f, b1f, b0f, b1f};
        #pragma unroll
        for (int k = 0; k < 13; k++) {
            const int t0 = 2 * k, t1 = 2 * k + 1;
            const int ky0 = t0 / 5, kx0 = t0 % 5;
            const int ky1 = (t1 < 25) ? t1 / 5 : 0, kx1 = (t1 < 25) ? t1 % 5 : 0;
            u32 bh0 = WH[(g * 27 + t0) * 4 + tg], bh1 = WH[(g * 27 + t1) * 4 + tg];
            u32 bl0 = WL[(g * 27 + t0) * 4 + tg], bl1 = WL[(g * 27 + t1) * 4 + tg];
            #pragma unroll
            for (int s = 0; s < 2; s++) {
                int xbse = s * 16 + g;
                int p0 = ((w_ + ky0) * 36 + xbse + kx0) * 4 + tg;
                int p1 = ((w_ + ky1) * 36 + xbse + kx1) * 4 + tg;
                u32 a0h = XuH[p0], a1h = XuH[p0 + 32], a2h = XuH[p1], a3h = XuH[p1 + 32];
                u32 a0l = XuL[p0], a1l = XuL[p0 + 32], a2l = XuL[p1], a3l = XuL[p1 + 32];
                float* cc = s ? c1 : c0;
                mma16816(cc, a0h, a1h, a2h, a3h, bh0, bh1);
                mma16816(cc, a0l, a1l, a2l, a3l, bh0, bh1);
                mma16816(cc, a0h, a1h, a2h, a3h, bl0, bl1);
            }
        }
        int Y = y0 + w_;
        float* mulb = g_mul + (size_t)b * OH * OH * 8;  // pixel-major
        float me = 3.4e38f, mo = 3.4e38f;
        #pragma unroll
        for (int s = 0; s < 2; s++) {
            float* cc = s ? c1 : c0;
            int X = x0 + s * 16 + g;
            *(float2*)&mulb[(size_t)(Y * OH + X) * 8 + 2 * tg] = make_float2(cc[0], cc[1]);
            *(float2*)&mulb[(size_t)(Y * OH + X + 8) * 8 + 2 * tg] = make_float2(cc[2], cc[3]);
            me = fminf(me, fminf(fabsf(cc[0]), fabsf(cc[2])));
            mo = fminf(mo, fminf(fabsf(cc[1]), fabsf(cc[3])));
        }
        #pragma unroll
        for (int off = 16; off >= 4; off >>= 1) {
            me = fminf(me, __shfl_xor_sync(0xFFFFFFFFu, me, off));
            mo = fminf(mo, __shfl_xor_sync(0xFFFFFFFFu, mo, off));
        }
        if (lane < 4) {
            atomicMin(&sMin[2 * tg], __float_as_uint(me));
            atomicMin(&sMin[2 * tg + 1], __float_as_uint(mo));
        }
        __syncthreads();
        if (tid < 8) atomicMin(&g_minmul[stage * BATCH * CH + b * CH + tid], sMin[tid]);
    }
}

// ---------------- combine to pixel-major xph/xpl/lxp (all pixel-major inputs) ----------------
template<int H>
__global__ __launch_bounds__(256) void k_combineP(int stage) {
    constexpr int OH = 2 * H;
    int b = blockIdx.y;
    int p = blockIdx.x * 256 + threadIdx.x;
    if (p >= OH * OH) return;
    int Y = p / OH, X = p - Y * OH;
    int pp = (Y >> 1) * H + (X >> 1);
    __shared__ float sMn[3 * CH];
    if (threadIdx.x < 3 * CH) {
        int c = threadIdx.x & 7, which = threadIdx.x >> 3;
        const unsigned* src = which == 0 ? g_minpos : (which == 1 ? g_minneg : g_minmul);
        sMn[threadIdx.x] = __uint_as_float(src[stage * BATCH * CH + b * CH + c]);
    }
    __syncthreads();

    float pos[CH], ng[CH], ml[CH];
    {
        const float4* p4 = (const float4*)(g_pos + ((size_t)b * H * H + pp) * 8);
        const float4* n4 = (const float4*)(g_neg + ((size_t)b * OH * OH + p) * 8);
        const float4* m4 = (const float4*)(g_mul + ((size_t)b * OH * OH + p) * 8);
        float4 a0 = p4[0], a1 = p4[1];
        pos[0]=a0.x; pos[1]=a0.y; pos[2]=a0.z; pos[3]=a0.w;
        pos[4]=a1.x; pos[5]=a1.y; pos[6]=a1.z; pos[7]=a1.w;
        a0 = n4[0]; a1 = n4[1];
        ng[0]=a0.x; ng[1]=a0.y; ng[2]=a0.z; ng[3]=a0.w;
        ng[4]=a1.x; ng[5]=a1.y; ng[6]=a1.z; ng[7]=a1.w;
        a0 = m4[0]; a1 = m4[1];
        ml[0]=a0.x; ml[1]=a0.y; ml[2]=a0.z; ml[3]=a0.w;
        ml[4]=a1.x; ml[5]=a1.y; ml[6]=a1.z; ml[7]=a1.w;
    }

    uint4 hv, lv;
    bf16* hp = (bf16*)&hv;
    bf16* lp = (bf16*)&lv;
    float lx[CH];
    #pragma unroll
    for (int c = 0; c < CH; c++) {
        float dp = dln_f(pos[c], sMn[c]);
        float xv = (dp + dln_f(ng[c], sMn[8 + c])) * dln_f(ml[c], sMn[16 + c]);
        bf16 h = __float2bfloat16(xv);
        hp[c] = h;
        lp[c] = __float2bfloat16(xv - __bfloat162float(h));
        lx[c] = __logf(fabsf(xv) + 1.0f);
    }
    size_t base = (size_t)b * OH * OH + p;
    ((uint4*)g_xph)[base] = hv;
    ((uint4*)g_xpl)[base] = lv;
    float4* lxd = (float4*)(g_lxp + base * 8);
    lxd[0] = make_float4(lx[0], lx[1], lx[2], lx[3]);
    lxd[1] = make_float4(lx[4], lx[5], lx[6], lx[7]);
}

// ---------------- xumake: bilinear upsample lxp(H) -> xuh/xul(2H), bf16 split ----------------
template<int H>
__global__ __launch_bounds__(256) void k_xumake() {
    constexpr int OH = 2 * H;
    int b = blockIdx.y;
    int p = blockIdx.x * 256 + threadIdx.x;
    if (p >= OH * OH) return;
    int Y = p / OH, X = p - Y * OH;
    int iy = Y >> 1, ix = X >> 1;
    int yo = (Y & 1) ? min(iy + 1, H - 1) : max(iy - 1, 0);
    int xo = (X & 1) ? min(ix + 1, H - 1) : max(ix - 1, 0);
    const float* L = g_lxp + (size_t)b * H * H * 8;
    const float4* A = (const float4*)(L + (size_t)(iy * H + ix) * 8);
    const float4* Bq = (const float4*)(L + (size_t)(iy * H + xo) * 8);
    const float4* Cq = (const float4*)(L + (size_t)(yo * H + ix) * 8);
    const float4* D = (const float4*)(L + (size_t)(yo * H + xo) * 8);
    uint4 hv, lv;
    bf16* hp = (bf16*)&hv;
    bf16* lp = (bf16*)&lv;
    #pragma unroll
    for (int half = 0; half < 2; half++) {
        float4 a = A[half], bb = Bq[half], cc = Cq[half], d = D[half];
        float v[4];
        v[0] = 0.5625f * a.x + 0.1875f * bb.x + 0.1875f * cc.x + 0.0625f * d.x;
        v[1] = 0.5625f * a.y + 0.1875f * bb.y + 0.1875f * cc.y + 0.0625f * d.y;
        v[2] = 0.5625f * a.z + 0.1875f * bb.z + 0.1875f * cc.z + 0.0625f * d.z;
        v[3] = 0.5625f * a.w + 0.1875f * bb.w + 0.1875f * cc.w + 0.0625f * d.w;
        #pragma unroll
        for (int k = 0; k < 4; k++) {
            bf16 h = __float2bfloat16(v[k]);
            hp[half * 4 + k] = h;
            lp[half * 4 + k] = __float2bfloat16(v[k] - __bfloat162float(h));
        }
    }
    size_t base = (size_t)b * OH * OH + p;
    ((uint4*)g_xuh)[base] = hv;
    ((uint4*)g_xul)[base] = lv;
}

// ---------------- final combine + 1x1 conv (pixel-major in) ----------------
__global__ __launch_bounds__(256) void k_comfinal(float* __restrict__ out) {
    constexpr int H = 128, OH = 256;
    constexpr int stage = 3;
    int b = blockIdx.y;
    int p = blockIdx.x * 256 + threadIdx.x;
    int Y = p >> 8, X = p & 255;
    int pp = (Y >> 1) * H + (X >> 1);
    __shared__ float sMn[3 * CH];
    __shared__ float sWo[3 * CH];
    __shared__ float sBo[3];
    if (threadIdx.x < 3 * CH) {
        int c = threadIdx.x & 7, which = threadIdx.x >> 3;
        const unsigned* src = which == 0 ? g_minpos : (which == 1 ? g_minneg : g_minmul);
        sMn[threadIdx.x] = __uint_as_float(src[stage * BATCH * CH + b * CH + c]);
        sWo[threadIdx.x] = g_wo[b * 24 + threadIdx.x];
    }
    if (threadIdx.x >= 32 && threadIdx.x < 35) sBo[threadIdx.x - 32] = g_bo[b * 3 + threadIdx.x - 32];
    __syncthreads();

    const float4* p4 = (const float4*)(g_pos + ((size_t)b * H * H + pp) * 8);
    const float4* n4 = (const float4*)(g_neg + ((size_t)b * OH * OH + p) * 8);
    const float4* m4 = (const float4*)(g_mul + ((size_t)b * OH * OH + p) * 8);
    float pos[8], ng[8], ml[8];
    float4 a0 = p4[0], a1 = p4[1];
    pos[0]=a0.x; pos[1]=a0.y; pos[2]=a0.z; pos[3]=a0.w; pos[4]=a1.x; pos[5]=a1.y; pos[6]=a1.z; pos[7]=a1.w;
    a0 = n4[0]; a1 = n4[1];
    ng[0]=a0.x; ng[1]=a0.y; ng[2]=a0.z; ng[3]=a0.w; ng[4]=a1.x; ng[5]=a1.y; ng[6]=a1.z; ng[7]=a1.w;
    a0 = m4[0]; a1 = m4[1];
    ml[0]=a0.x; ml[1]=a0.y; ml[2]=a0.z; ml[3]=a0.w; ml[4]=a1.x; ml[5]=a1.y; ml[6]=a1.z; ml[7]=a1.w;

    float acc[3] = {sBo[0], sBo[1], sBo[2]};
    #pragma unroll
    for (int c = 0; c < CH; c++) {
        float dp = dln_f(pos[c], sMn[c]);
        float xv = (dp + dln_f(ng[c], sMn[8 + c])) * dln_f(ml[c], sMn[16 + c]);
        #pragma unroll
        for (int o = 0; o < 3; o++) acc[o] += sWo[o * CH + c] * xv;
    }
    #pragma unroll
    for (int o = 0; o < 3; o++)
        out[((size_t)b * 3 + o) * OH * OH + p] = acc[o];
}

// ---------------- launcher ----------------
extern "C" void kernel_launch(void* const* d_in, const int* in_sizes, int n_in,
                              void* d_out, int out_size) {
    const int*   ids = (const int*)  d_in[0];
    const float* cc  = (const float*)d_in[1];
    const float* lat = (const float*)d_in[2];
    const float* Wr = (const float*)d_in[3];
    const float* Ur = (const float*)d_in[4];
    const float* Vr = (const float*)d_in[5];
    const float* Br = (const float*)d_in[6];
    const float* Wt = (const float*)d_in[7];
    const float* Ut = (const float*)d_in[8];
    const float* Vt = (const float*)d_in[9];
    const float* Bt = (const float*)d_in[10];
    const float* Wm = (const float*)d_in[11];
    const float* Um = (const float*)d_in[12];
    const float* Vm = (const float*)d_in[13];
    const float* Bm = (const float*)d_in[14];
    const float* Wo = (const float*)d_in[15];
    const float* Uo = (const float*)d_in[16];
    const float* Vo = (const float*)d_in[17];
    const float* Bo = (const float*)d_in[18];

    k_gather<<<64, 256>>>(ids, cc, lat);
    k_weights<<<dim3(13, 64), 128>>>(Wr, Ur, Vr, Br, Wt, Ut, Vt, Bt,
                                     Wm, Um, Vm, Bm, Wo, Uo, Vo, Bo);
    k_mininit<<<(NSTAGE * BATCH * CH + 255) / 256, 256>>>();

    // stage 0: H=16
    k_xumake<16><<<dim3(4, 64), 256>>>();
    k_mma<16><<<dim3(1, 4, 192), 256>>>(0);
    k_combineP<16><<<dim3(4, 64), 256>>>(0);
    // stage 1: H=32
    k_xumake<32><<<dim3(16, 64), 256>>>();
    k_mma<32><<<dim3(2, 8, 192), 256>>>(1);
    k_combineP<32><<<dim3(16, 64), 256>>>(1);
    // stage 2: H=64
    k_xumake<64><<<dim3(64, 64), 256>>>();
    k_mma<64><<<dim3(4, 16, 192), 256>>>(2);
    k_combineP<64><<<dim3(64, 64), 256>>>(2);
    // stage 3: H=128
    k_xumake<128><<<dim3(256, 64), 256>>>();
    k_mma<128><<<dim3(8, 32, 192), 256>>>(3);
    k_comfinal<<<dim3(256, 64), 256>>>((float*)d_out);
}

// round 11
// speedup vs baseline: 2.1791x; 1.0583x over previous
#include <cuda_runtime.h>
#include <cuda_bf16.h>
#include <cstdint>

#define BATCH 64
#define CH 8
#define NSTAGE 4

typedef uint32_t u32;
typedef __nv_bfloat16 bf16;

// ---------------- device scratch ----------------
__device__ float g_ctx[BATCH*32];
__device__ float g_wr[NSTAGE*BATCH*CH*CH*9];
__device__ float g_wt[NSTAGE*BATCH*CH*CH*16];
__device__ float g_wm[NSTAGE*BATCH*CH*CH*25];
__device__ bf16 g_wmbh[NSTAGE*BATCH*8*27*8];
__device__ bf16 g_wmbl[NSTAGE*BATCH*8*27*8];
__device__ bf16 g_wrbh[NSTAGE*BATCH*8*10*8];
__device__ bf16 g_wrbl[NSTAGE*BATCH*8*10*8];
__device__ bf16 g_wtbh[NSTAGE*BATCH*1024];
__device__ bf16 g_wtbl[NSTAGE*BATCH*1024];
__device__ float g_wo[BATCH*3*CH];
__device__ float g_br[NSTAGE*BATCH*CH];
__device__ float g_bt[NSTAGE*BATCH*CH];
__device__ float g_bm[NSTAGE*BATCH*CH];
__device__ float g_bo[BATCH*3];
__device__ __align__(16) float g_pos[BATCH*128*128*CH];   // pixel-major
__device__ __align__(16) float g_neg[BATCH*256*256*CH];
__device__ __align__(16) float g_mul[BATCH*256*256*CH];
__device__ __align__(16) bf16 g_xph[BATCH*128*128*CH];    // pixel-major x hi
__device__ __align__(16) bf16 g_xpl[BATCH*128*128*CH];
__device__ __align__(16) float g_lxp[BATCH*128*128*CH];   // pixel-major log(|x|+1)
__device__ unsigned g_minpos[NSTAGE*BATCH*CH];
__device__ unsigned g_minneg[NSTAGE*BATCH*CH];
__device__ unsigned g_minmul[NSTAGE*BATCH*CH];

__device__ __forceinline__ float dln_f(float v, float mn) {
    float s = (v > 0.0f) ? 1.0f : -1.0f;
    float a = fabsf(v) - mn;
    return s * __logf(__logf(a + 2.718281828459045f) + 0.01f);
}

__device__ __forceinline__ void mma16816(float* c, u32 a0, u32 a1, u32 a2, u32 a3,
                                         u32 b0, u32 b1) {
    asm("mma.sync.aligned.m16n8k16.row.col.f32.bf16.bf16.f32 "
        "{%0,%1,%2,%3},{%4,%5,%6,%7},{%8,%9},{%0,%1,%2,%3};"
        : "+f"(c[0]), "+f"(c[1]), "+f"(c[2]), "+f"(c[3])
        : "r"(a0), "r"(a1), "r"(a2), "r"(a3), "r"(b0), "r"(b1));
}

// ---------------- gather: ctx + latents -> pixel-major xph/xpl/lxp @16 ----------------
__global__ __launch_bounds__(256) void k_gather(const int* __restrict__ ids,
                                                const float* __restrict__ cc,
                                                const float* __restrict__ lat) {
    int t = blockIdx.x * 256 + threadIdx.x;
    if (t < BATCH * 32) g_ctx[t] = cc[ids[t >> 5] * 32 + (t & 31)];
    int b = t >> 8, p = t & 255;
    const float* lb = lat + (size_t)ids[b] * (CH * 256);
    uint4 hv, lv;
    bf16* hp = (bf16*)&hv;
    bf16* lp = (bf16*)&lv;
    float lx[CH];
    #pragma unroll
    for (int c = 0; c < CH; c++) {
        float v = lb[c * 256 + p];
        bf16 h = __float2bfloat16(v);
        hp[c] = h;
        lp[c] = __float2bfloat16(v - __bfloat162float(h));
        lx[c] = __logf(fabsf(v) + 1.0f);
    }
    size_t base = (size_t)b * 256 + p;
    ((uint4*)g_xph)[base] = hv;
    ((uint4*)g_xpl)[base] = lv;
    float4* lxd = (float4*)(g_lxp + base * 8);
    lxd[0] = make_float4(lx[0], lx[1], lx[2], lx[3]);
    lxd[1] = make_float4(lx[4], lx[5], lx[6], lx[7]);
}

__global__ void k_mininit() {
    int t = blockIdx.x * blockDim.x + threadIdx.x;
    if (t < NSTAGE * BATCH * CH) {
        g_minpos[t] = 0x7F800000u; g_minneg[t] = 0x7F800000u; g_minmul[t] = 0x7F800000u;
    }
}

// ---------------- dynamic weights ----------------
__global__ void k_weights(
    const float* __restrict__ Wr, const float* __restrict__ Ur, const float* __restrict__ Vr, const float* __restrict__ Br,
    const float* __restrict__ Wt, const float* __restrict__ Ut, const float* __restrict__ Vt, const float* __restrict__ Bt,
    const float* __restrict__ Wm, const float* __restrict__ Um, const float* __restrict__ Vm, const float* __restrict__ Bm,
    const float* __restrict__ Wo, const float* __restrict__ Uo, const float* __restrict__ Vo, const float* __restrict__ Bo)
{
    int inst = blockIdx.x, b = blockIdx.y, tid = threadIdx.x;
    __shared__ float sctx[32];
    __shared__ float su[128];
    __shared__ float sv[3200];
    if (tid < 32) sctx[tid] = g_ctx[b * 32 + tid];
    __syncthreads();

    int O, KK, type = -1, stage = 0;
    const float *U, *V, *W, *Bb;
    float *gw, *gb;
    if (inst < 12) {
        type = inst >> 2; stage = inst & 3;
        O = CH;
        if (type == 0)      { KK = 9;  U = Ur; V = Vr; W = Wr; Bb = Br; gw = g_wr; gb = g_br; }
        else if (type == 1) { KK = 16; U = Ut; V = Vt; W = Wt; Bb = Bt; gw = g_wt; gb = g_bt; }
        else                { KK = 25; U = Um; V = Vm; W = Wm; Bb = Bm; gw = g_wm; gb = g_bm; }
        int uL = 16 * O, vL = 16 * CH * KK;
        U += (size_t)stage * 32 * uL; V += (size_t)stage * 32 * vL;
        W += (size_t)stage * O * CH * KK; Bb += (size_t)stage * 32 * O;
        gw += (size_t)(stage * BATCH + b) * O * CH * KK;
        gb += (size_t)(stage * BATCH + b) * O;
    } else {
        O = 3; KK = 1;
        U = Uo; V = Vo; W = Wo; Bb = Bo;
        gw = g_wo + b * 3 * CH; gb = g_bo + b * 3;
    }
    int uLen = 16 * O, vLen = 16 * CH * KK, IKK = CH * KK, wN = O * IKK;
    int sb = stage * BATCH + b;

    for (int j = tid; j < uLen; j += blockDim.x) {
        float s = 0.f;
        #pragma unroll
        for (int l = 0; l < 32; l++) s += sctx[l] * U[l * uLen + j];
        su[j] = s;
    }
    for (int j = tid; j < vLen; j += blockDim.x) {
        float s = 0.f;
        #pragma unroll
        for (int l = 0; l < 32; l++) s += sctx[l] * V[l * vLen + j];
        sv[j] = s;
    }
    __syncthreads();

    for (int widx = tid; widx < wN; widx += blockDim.x) {
        int o = widx / IKK, k = widx - o * IKK;
        float m = 0.f;
        #pragma unroll
        for (int r = 0; r < 16; r++) m += su[r * O + o] * sv[r * IKK + k];
        float w = W[widx] * (1.0f + m + 1e-3f);
        gw[widx] = w;
        if (type == 2) {
            int i = k / 25, t = k - i * 25;
            size_t d = (size_t)(sb * 8 + o) * 216 + t * 8 + i;
            bf16 h = __float2bfloat16(w);
            g_wmbh[d] = h;
            g_wmbl[d] = __float2bfloat16(w - __bfloat162float(h));
        } else if (type == 0) {
            int i = k / 9, t = k - i * 9;
            size_t d = (size_t)sb * 640 + (o * 10 + t) * 8 + i;
            bf16 h = __float2bfloat16(w);
            g_wrbh[d] = h;
            g_wrbl[d] = __float2bfloat16(w - __bfloat162float(h));
        } else if (type == 1) {
            int i = k / 16, t = k - i * 16;
            int ky = t >> 2, kx = t & 3;
            int py = (3 - ky) & 1, dy = (3 - ky) >> 1;
            int px = (3 - kx) & 1, dx = (3 - kx) >> 1;
            float wn = -w;
            size_t d = (size_t)sb * 1024 +
                       ((((size_t)(py * 2 + px) * 8 + o) * 2 + dy) * 2 + dx) * 8 + i;
            bf16 h = __float2bfloat16(wn);
            g_wtbh[d] = h;
            g_wtbl[d] = __float2bfloat16(wn - __bfloat162float(h));
        }
    }
    if (type == 2 && tid < 128) {
        int o = tid >> 4, t = 25 + ((tid >> 3) & 1), i = tid & 7;
        size_t d = (size_t)(sb * 8 + o) * 216 + t * 8 + i;
        g_wmbh[d] = __float2bfloat16(0.f);
        g_wmbl[d] = __float2bfloat16(0.f);
    }
    if (type == 0 && tid < 64) {
        int o = tid >> 3, i = tid & 7;
        size_t d = (size_t)sb * 640 + (o * 10 + 9) * 8 + i;
        g_wrbh[d] = __float2bfloat16(0.f);
        g_wrbl[d] = __float2bfloat16(0.f);
    }
    if (tid < O) {
        float s = 0.f;
        #pragma unroll
        for (int l = 0; l < 32; l++) s += sctx[l] * Bb[l * O + tid];
        gb[tid] = s;
    }
}

// ---------------- mma superkernel (all stages), pixel-major I/O ----------------
template<int H>
__global__ __launch_bounds__(256) void k_mma(int stage) {
    constexpr int OH = 2 * H;
    __shared__ __align__(16) u32 sm[6500];
    int role = blockIdx.z >> 6;
    int b = blockIdx.z & 63;
    int tid = threadIdx.x;
    int bx = blockIdx.x, by = blockIdx.y;
    int w_ = tid >> 5, lane = tid & 31, g = lane >> 2, tg = lane & 3;

    if (role == 0) {
        // ---- conv3 mma at H res ----
        constexpr int BX3 = (H >= 32) ? H / 32 : 1;
        constexpr int SQ3 = (H >= 32) ? 2 : 1;
        if (bx >= BX3 || by >= H / 8) return;
        u32* XH = sm;
        u32* XL = sm + 1360;
        u32* WH = sm + 2720;
        u32* WL = sm + 3040;
        float* sB = (float*)(sm + 3360);
        unsigned* sMin = (unsigned*)(sm + 3372);
        int x0 = bx * 32, y0 = by * 8;
        const bf16* wh = g_wrbh + (size_t)(stage * BATCH + b) * 640;
        const bf16* wl = g_wrbl + (size_t)(stage * BATCH + b) * 640;
        bf16* swh = (bf16*)WH;
        bf16* swl = (bf16*)WL;
        for (int j = tid; j < 640; j += 256) { swh[j] = wh[j]; swl[j] = wl[j]; }
        if (tid < 8) { sB[tid] = g_br[(stage * BATCH + b) * CH + tid]; sMin[tid] = 0x7F800000u; }
        const uint4* xh4 = (const uint4*)g_xph + (size_t)b * H * H;
        const uint4* xl4 = (const uint4*)g_xpl + (size_t)b * H * H;
        for (int j = tid; j < 10 * 34; j += 256) {
            int r = j / 34, c = j - 34 * r;
            int gy = y0 - 1 + r, gx = x0 - 1 + c;
            uint4 v = make_uint4(0, 0, 0, 0), w2 = make_uint4(0, 0, 0, 0);
            if ((unsigned)gy < (unsigned)H && (unsigned)gx < (unsigned)H) {
                v = xh4[gy * H + gx]; w2 = xl4[gy * H + gx];
            }
            ((uint4*)XH)[j] = v; ((uint4*)XL)[j] = w2;
        }
        __syncthreads();

        float b0f = sB[2 * tg], b1f = sB[2 * tg + 1];
        float c0[4] = {b0f, b1f, b0f, b1f};
        float c1[4] = {b0f, b1f, b0f, b1f};
        #pragma unroll
        for (int k = 0; k < 5; k++) {
            const int t0 = 2 * k, t1 = 2 * k + 1;
            const int t1c = (t1 < 9) ? t1 : 0;
            const int ky0 = t0 / 3, kx0 = t0 % 3;
            const int ky1 = t1c / 3, kx1 = t1c % 3;
            u32 bh0 = WH[(g * 10 + t0) * 4 + tg], bh1 = WH[(g * 10 + t1) * 4 + tg];
            u32 bl0 = WL[(g * 10 + t0) * 4 + tg], bl1 = WL[(g * 10 + t1) * 4 + tg];
            #pragma unroll
            for (int s = 0; s < SQ3; s++) {
                int xbse = s * 16 + g;
                int p0 = ((w_ + ky0) * 34 + xbse + kx0) * 4 + tg;
                int p1 = ((w_ + ky1) * 34 + xbse + kx1) * 4 + tg;
                u32 a0h = XH[p0], a1h = XH[p0 + 32], a2h = XH[p1], a3h = XH[p1 + 32];
                u32 a0l = XL[p0], a1l = XL[p0 + 32], a2l = XL[p1], a3l = XL[p1 + 32];
                float* cc = s ? c1 : c0;
                mma16816(cc, a0h, a1h, a2h, a3h, bh0, bh1);
                mma16816(cc, a0l, a1l, a2l, a3l, bh0, bh1);
                mma16816(cc, a0h, a1h, a2h, a3h, bl0, bl1);
            }
        }
        int Y = y0 + w_;
        float* outp = g_pos + (size_t)b * H * H * 8;
        float me = 3.4e38f, mo = 3.4e38f;
        #pragma unroll
        for (int s = 0; s < SQ3; s++) {
            float* cc = s ? c1 : c0;
            int X = x0 + s * 16 + g;
            *(float2*)&outp[(size_t)(Y * H + X) * 8 + 2 * tg] = make_float2(cc[0], cc[1]);
            *(float2*)&outp[(size_t)(Y * H + X + 8) * 8 + 2 * tg] = make_float2(cc[2], cc[3]);
            me = fminf(me, fminf(fabsf(cc[0]), fabsf(cc[2])));
            mo = fminf(mo, fminf(fabsf(cc[1]), fabsf(cc[3])));
        }
        #pragma unroll
        for (int off = 16; off >= 4; off >>= 1) {
            me = fminf(me, __shfl_xor_sync(0xFFFFFFFFu, me, off));
            mo = fminf(mo, __shfl_xor_sync(0xFFFFFFFFu, mo, off));
        }
        if (lane < 4) {
            atomicMin(&sMin[2 * tg], __float_as_uint(me));
            atomicMin(&sMin[2 * tg + 1], __float_as_uint(mo));
        }
        __syncthreads();
        if (tid < 8) atomicMin(&g_minpos[stage * BATCH * CH + b * CH + tid], sMin[tid]);

    } else if (role == 1) {
        // ---- convT mma at OH res ----
        u32* XH = sm;
        u32* XL = sm + 432;
        u32* WH = sm + 864;
        u32* WL = sm + 1376;
        float* sB = (float*)(sm + 1888);
        unsigned* sMin = (unsigned*)(sm + 1900);
        int x0 = bx * 32, y0 = by * 8;
        const bf16* wh = g_wtbh + (size_t)(stage * BATCH + b) * 1024;
        const bf16* wl = g_wtbl + (size_t)(stage * BATCH + b) * 1024;
        bf16* swh = (bf16*)WH;
        bf16* swl = (bf16*)WL;
        for (int j = tid; j < 1024; j += 256) { swh[j] = wh[j]; swl[j] = wl[j]; }
        if (tid < 8) { sB[tid] = g_bt[(stage * BATCH + b) * CH + tid]; sMin[tid] = 0x7F800000u; }
        int iy0 = y0 / 2 - 1, ix0 = x0 / 2 - 1;
        const uint4* xh4 = (const uint4*)g_xph + (size_t)b * H * H;
        const uint4* xl4 = (const uint4*)g_xpl + (size_t)b * H * H;
        for (int j = tid; j < 6 * 18; j += 256) {
            int r = j / 18, c = j - 18 * r;
            int gy = iy0 + r, gx = ix0 + c;
            uint4 v = make_uint4(0, 0, 0, 0), w2 = make_uint4(0, 0, 0, 0);
            if ((unsigned)gy < (unsigned)H && (unsigned)gx < (unsigned)H) {
                v = xh4[gy * H + gx]; w2 = xl4[gy * H + gx];
            }
            ((uint4*)XH)[j] = v; ((uint4*)XL)[j] = w2;
        }
        __syncthreads();

        int py = w_ & 1;
        int r0 = (w_ >> 1) + py;
        float b0f = sB[2 * tg], b1f = sB[2 * tg + 1];
        int Y = y0 + w_;
        float* outp = g_neg + (size_t)b * OH * OH * 8;
        float me = 3.4e38f, mo = 3.4e38f;
        #pragma unroll
        for (int px = 0; px < 2; px++) {
            float cc[4] = {b0f, b1f, b0f, b1f};
            #pragma unroll
            for (int dy = 0; dy < 2; dy++) {
                int wb = ((((py * 2 + px) * 8 + g) * 2 + dy) * 2) * 4 + tg;
                u32 bh0 = WH[wb], bh1 = WH[wb + 4];
                u32 bl0 = WL[wb], bl1 = WL[wb + 4];
                int base0 = ((r0 + dy) * 18 + g + px) * 4 + tg;
                u32 a0h = XH[base0], a1h = XH[base0 + 32], a2h = XH[base0 + 4], a3h = XH[base0 + 36];
                u32 a0l = XL[base0], a1l = XL[base0 + 32], a2l = XL[base0 + 4], a3l = XL[base0 + 36];
                mma16816(cc, a0h, a1h, a2h, a3h, bh0, bh1);
                mma16816(cc, a0l, a1l, a2l, a3l, bh0, bh1);
                mma16816(cc, a0h, a1h, a2h, a3h, bl0, bl1);
            }
            int X0 = x0 + 2 * g + px;
            int X1 = x0 + 2 * (g + 8) + px;
            *(float2*)&outp[(size_t)(Y * OH + X0) * 8 + 2 * tg] = make_float2(cc[0], cc[1]);
            *(float2*)&outp[(size_t)(Y * OH + X1) * 8 + 2 * tg] = make_float2(cc[2], cc[3]);
            me = fminf(me, fminf(fabsf(cc[0]), fabsf(cc[2])));
            mo = fminf(mo, fminf(fabsf(cc[1]), fabsf(cc[3])));
        }
        #pragma unroll
        for (int off = 16; off >= 4; off >>= 1) {
            me = fminf(me, __shfl_xor_sync(0xFFFFFFFFu, me, off));
            mo = fminf(mo, __shfl_xor_sync(0xFFFFFFFFu, mo, off));
        }
        if (lane < 4) {
            atomicMin(&sMin[2 * tg], __float_as_uint(me));
            atomicMin(&sMin[2 * tg + 1], __float_as_uint(mo));
        }
        __syncthreads();
        if (tid < 8) atomicMin(&g_minneg[stage * BATCH * CH + b * CH + tid], sMin[tid]);

    } else {
        // ---- conv5 mma at OH res; in-block bilinear from lxp (f32, H res) ----
        constexpr int LH = 8, LW = 20;
        float* sLx = (float*)sm;                    // 1280 f32 (pixel-major [r][c][ch])
        u32* XuH = sm + 1280;                       // 1728
        u32* XuL = sm + 3008;                       // 1728
        u32* WH = sm + 4736;                        // 864
        u32* WL = sm + 5600;                        // 864
        float* sB = (float*)(sm + 6464);
        unsigned* sMin = (unsigned*)(sm + 6476);
        int x0 = bx * 32, y0 = by * 8;
        const bf16* wh = g_wmbh + (size_t)((stage * BATCH + b) * 8) * 216;
        const bf16* wl = g_wmbl + (size_t)((stage * BATCH + b) * 8) * 216;
        bf16* swh = (bf16*)WH;
        bf16* swl = (bf16*)WL;
        for (int j = tid; j < 8 * 216; j += 256) { swh[j] = wh[j]; swl[j] = wl[j]; }
        if (tid < 8) { sB[tid] = g_bm[(stage * BATCH + b) * CH + tid]; sMin[tid] = 0x7F800000u; }

        int gyLo = ((y0 - 2) >> 1) - 1;
        int gxLo = ((x0 - 2) >> 1) - 1;
        const float4* lx4 = (const float4*)g_lxp + (size_t)b * H * H * 2;
        for (int j = tid; j < LH * LW; j += 256) {
            int r = j / LW, c = j - LW * r;
            int gy = gyLo + r, gx = gxLo + c;
            float4 v0 = make_float4(0, 0, 0, 0), v1 = make_float4(0, 0, 0, 0);
            if ((unsigned)gy < (unsigned)H && (unsigned)gx < (unsigned)H) {
                v0 = lx4[(gy * H + gx) * 2];
                v1 = lx4[(gy * H + gx) * 2 + 1];
            }
            ((float4*)sLx)[j * 2] = v0;
            ((float4*)sLx)[j * 2 + 1] = v1;
        }
        __syncthreads();
        // build xu tile [12][36][ch] bf16 hi/lo via clamped 2x bilinear
        bf16* xuh = (bf16*)XuH;
        bf16* xul = (bf16*)XuL;
        for (int j = tid; j < 12 * 36; j += 256) {
            int r = j / 36, c = j - 36 * r;
            int Y = y0 - 2 + r, X = x0 - 2 + c;
            if ((unsigned)Y < (unsigned)OH && (unsigned)X < (unsigned)OH) {
                int iy = Y >> 1, ix = X >> 1;
                int yo = (Y & 1) ? min(iy + 1, H - 1) : max(iy - 1, 0);
                int xo = (X & 1) ? min(ix + 1, H - 1) : max(ix - 1, 0);
                int ry = iy - gyLo, ryo = yo - gyLo;
                int cx = ix - gxLo, cxo = xo - gxLo;
                const float4* A  = (const float4*)(sLx + (ry * LW + cx) * 8);
                const float4* Bq = (const float4*)(sLx + (ry * LW + cxo) * 8);
                const float4* Cq = (const float4*)(sLx + (ryo * LW + cx) * 8);
                const float4* D  = (const float4*)(sLx + (ryo * LW + cxo) * 8);
                #pragma unroll
                for (int half = 0; half < 2; half++) {
                    float4 a = A[half], bb = Bq[half], cc2 = Cq[half], d = D[half];
                    float v[4];
                    v[0] = 0.5625f * a.x + 0.1875f * bb.x + 0.1875f * cc2.x + 0.0625f * d.x;
                    v[1] = 0.5625f * a.y + 0.1875f * bb.y + 0.1875f * cc2.y + 0.0625f * d.y;
                    v[2] = 0.5625f * a.z + 0.1875f * bb.z + 0.1875f * cc2.z + 0.0625f * d.z;
                    v[3] = 0.5625f * a.w + 0.1875f * bb.w + 0.1875f * cc2.w + 0.0625f * d.w;
                    #pragma unroll
                    for (int k = 0; k < 4; k++) {
                        bf16 h = __float2bfloat16(v[k]);
                        xuh[j * 8 + half * 4 + k] = h;
                        xul[j * 8 + half * 4 + k] = __float2bfloat16(v[k] - __bfloat162float(h));
                    }
                }
            } else {
                ((uint4*)XuH)[j] = make_uint4(0, 0, 0, 0);
                ((uint4*)XuL)[j] = make_uint4(0, 0, 0, 0);
            }
        }
        __syncthreads();

        float b0f = sB[2 * tg], b1f = sB[2 * tg + 1];
        float c0[4] = {b0f, b1f, b0f, b1f};
        float c1[4] = {b0f, b1f, b0f, b1f};
        #pragma unroll
        for (int k = 0; k < 13; k++) {
            const int t0 = 2 * k, t1 = 2 * k + 1;
            const int ky0 = t0 / 5, kx0 = t0 % 5;
            const int ky1 = (t1 < 25) ? t1 / 5 : 0, kx1 = (t1 < 25) ? t1 % 5 : 0;
            u32 bh0 = WH[(g * 27 + t0) * 4 + tg], bh1 = WH[(g * 27 + t1) * 4 + tg];
            u32 bl0 = WL[(g * 27 + t0) * 4 + tg], bl1 = WL[(g * 27 + t1) * 4 + tg];
            #pragma unroll
            for (int s = 0; s < 2; s++) {
                int xbse = s * 16 + g;
                int p0 = ((w_ + ky0) * 36 + xbse + kx0) * 4 + tg;
                int p1 = ((w_ + ky1) * 36 + xbse + kx1) * 4 + tg;
                u32 a0h = XuH[p0], a1h = XuH[p0 + 32], a2h = XuH[p1], a3h = XuH[p1 + 32];
                u32 a0l = XuL[p0], a1l = XuL[p0 + 32], a2l = XuL[p1], a3l = XuL[p1 + 32];
                float* cc = s ? c1 : c0;
                mma16816(cc, a0h, a1h, a2h, a3h, bh0, bh1);
                mma16816(cc, a0l, a1l, a2l, a3l, bh0, bh1);
                mma16816(cc, a0h, a1h, a2h, a3h, bl0, bl1);
            }
        }
        int Y = y0 + w_;
        float* mulb = g_mul + (size_t)b * OH * OH * 8;
        float me = 3.4e38f, mo = 3.4e38f;
        #pragma unroll
        for (int s = 0; s < 2; s++) {
            float* cc = s ? c1 : c0;
            int X = x0 + s * 16 + g;
            *(float2*)&mulb[(size_t)(Y * OH + X) * 8 + 2 * tg] = make_float2(cc[0], cc[1]);
            *(float2*)&mulb[(size_t)(Y * OH + X + 8) * 8 + 2 * tg] = make_float2(cc[2], cc[3]);
            me = fminf(me, fminf(fabsf(cc[0]), fabsf(cc[2])));
            mo = fminf(mo, fminf(fabsf(cc[1]), fabsf(cc[3])));
        }
        #pragma unroll
        for (int off = 16; off >= 4; off >>= 1) {
            me = fminf(me, __shfl_xor_sync(0xFFFFFFFFu, me, off));
            mo = fminf(mo, __shfl_xor_sync(0xFFFFFFFFu, mo, off));
        }
        if (lane < 4) {
            atomicMin(&sMin[2 * tg], __float_as_uint(me));
            atomicMin(&sMin[2 * tg + 1], __float_as_uint(mo));
        }
        __syncthreads();
        if (tid < 8) atomicMin(&g_minmul[stage * BATCH * CH + b * CH + tid], sMin[tid]);
    }
}

// ---------------- combine to pixel-major xph/xpl/lxp ----------------
template<int H>
__global__ __launch_bounds__(256) void k_combineP(int stage) {
    constexpr int OH = 2 * H;
    int b = blockIdx.y;
    int p = blockIdx.x * 256 + threadIdx.x;
    if (p >= OH * OH) return;
    int Y = p / OH, X = p - Y * OH;
    int pp = (Y >> 1) * H + (X >> 1);
    __shared__ float sMn[3 * CH];
    if (threadIdx.x < 3 * CH) {
        int c = threadIdx.x & 7, which = threadIdx.x >> 3;
        const unsigned* src = which == 0 ? g_minpos : (which == 1 ? g_minneg : g_minmul);
        sMn[threadIdx.x] = __uint_as_float(src[stage * BATCH * CH + b * CH + c]);
    }
    __syncthreads();

    float pos[CH], ng[CH], ml[CH];
    {
        const float4* p4 = (const float4*)(g_pos + ((size_t)b * H * H + pp) * 8);
        const float4* n4 = (const float4*)(g_neg + ((size_t)b * OH * OH + p) * 8);
        const float4* m4 = (const float4*)(g_mul + ((size_t)b * OH * OH + p) * 8);
        float4 a0 = p4[0], a1 = p4[1];
        pos[0]=a0.x; pos[1]=a0.y; pos[2]=a0.z; pos[3]=a0.w;
        pos[4]=a1.x; pos[5]=a1.y; pos[6]=a1.z; pos[7]=a1.w;
        a0 = n4[0]; a1 = n4[1];
        ng[0]=a0.x; ng[1]=a0.y; ng[2]=a0.z; ng[3]=a0.w;
        ng[4]=a1.x; ng[5]=a1.y; ng[6]=a1.z; ng[7]=a1.w;
        a0 = m4[0]; a1 = m4[1];
        ml[0]=a0.x; ml[1]=a0.y; ml[2]=a0.z; ml[3]=a0.w;
        ml[4]=a1.x; ml[5]=a1.y; ml[6]=a1.z; ml[7]=a1.w;
    }

    uint4 hv, lv;
    bf16* hp = (bf16*)&hv;
    bf16* lp = (bf16*)&lv;
    float lx[CH];
    #pragma unroll
    for (int c = 0; c < CH; c++) {
        float dp = dln_f(pos[c], sMn[c]);
        float xv = (dp + dln_f(ng[c], sMn[8 + c])) * dln_f(ml[c], sMn[16 + c]);
        bf16 h = __float2bfloat16(xv);
        hp[c] = h;
        lp[c] = __float2bfloat16(xv - __bfloat162float(h));
        lx[c] = __logf(fabsf(xv) + 1.0f);
    }
    size_t base = (size_t)b * OH * OH + p;
    ((uint4*)g_xph)[base] = hv;
    ((uint4*)g_xpl)[base] = lv;
    float4* lxd = (float4*)(g_lxp + base * 8);
    lxd[0] = make_float4(lx[0], lx[1], lx[2], lx[3]);
    lxd[1] = make_float4(lx[4], lx[5], lx[6], lx[7]);
}

// ---------------- final combine + 1x1 conv ----------------
__global__ __launch_bounds__(256) void k_comfinal(float* __restrict__ out) {
    constexpr int H = 128, OH = 256;
    constexpr int stage = 3;
    int b = blockIdx.y;
    int p = blockIdx.x * 256 + threadIdx.x;
    int Y = p >> 8, X = p & 255;
    int pp = (Y >> 1) * H + (X >> 1);
    __shared__ float sMn[3 * CH];
    __shared__ float sWo[3 * CH];
    __shared__ float sBo[3];
    if (threadIdx.x < 3 * CH) {
        int c = threadIdx.x & 7, which = threadIdx.x >> 3;
        const unsigned* src = which == 0 ? g_minpos : (which == 1 ? g_minneg : g_minmul);
        sMn[threadIdx.x] = __uint_as_float(src[stage * BATCH * CH + b * CH + c]);
        sWo[threadIdx.x] = g_wo[b * 24 + threadIdx.x];
    }
    if (threadIdx.x >= 32 && threadIdx.x < 35) sBo[threadIdx.x - 32] = g_bo[b * 3 + threadIdx.x - 32];
    __syncthreads();

    const float4* p4 = (const float4*)(g_pos + ((size_t)b * H * H + pp) * 8);
    const float4* n4 = (const float4*)(g_neg + ((size_t)b * OH * OH + p) * 8);
    const float4* m4 = (const float4*)(g_mul + ((size_t)b * OH * OH + p) * 8);
    float pos[8], ng[8], ml[8];
    float4 a0 = p4[0], a1 = p4[1];
    pos[0]=a0.x; pos[1]=a0.y; pos[2]=a0.z; pos[3]=a0.w; pos[4]=a1.x; pos[5]=a1.y; pos[6]=a1.z; pos[7]=a1.w;
    a0 = n4[0]; a1 = n4[1];
    ng[0]=a0.x; ng[1]=a0.y; ng[2]=a0.z; ng[3]=a0.w; ng[4]=a1.x; ng[5]=a1.y; ng[6]=a1.z; ng[7]=a1.w;
    a0 = m4[0]; a1 = m4[1];
    ml[0]=a0.x; ml[1]=a0.y; ml[2]=a0.z; ml[3]=a0.w; ml[4]=a1.x; ml[5]=a1.y; ml[6]=a1.z; ml[7]=a1.w;

    float acc[3] = {sBo[0], sBo[1], sBo[2]};
    #pragma unroll
    for (int c = 0; c < CH; c++) {
        float dp = dln_f(pos[c], sMn[c]);
        float xv = (dp + dln_f(ng[c], sMn[8 + c])) * dln_f(ml[c], sMn[16 + c]);
        #pragma unroll
        for (int o = 0; o < 3; o++) acc[o] += sWo[o * CH + c] * xv;
    }
    #pragma unroll
    for (int o = 0; o < 3; o++)
        out[((size_t)b * 3 + o) * OH * OH + p] = acc[o];
}

// ---------------- launcher ----------------
extern "C" void kernel_launch(void* const* d_in, const int* in_sizes, int n_in,
                              void* d_out, int out_size) {
    const int*   ids = (const int*)  d_in[0];
    const float* cc  = (const float*)d_in[1];
    const float* lat = (const float*)d_in[2];
    const float* Wr = (const float*)d_in[3];
    const float* Ur = (const float*)d_in[4];
    const float* Vr = (const float*)d_in[5];
    const float* Br = (const float*)d_in[6];
    const float* Wt = (const float*)d_in[7];
    const float* Ut = (const float*)d_in[8];
    const float* Vt = (const float*)d_in[9];
    const float* Bt = (const float*)d_in[10];
    const float* Wm = (const float*)d_in[11];
    const float* Um = (const float*)d_in[12];
    const float* Vm = (const float*)d_in[13];
    const float* Bm = (const float*)d_in[14];
    const float* Wo = (const float*)d_in[15];
    const float* Uo = (const float*)d_in[16];
    const float* Vo = (const float*)d_in[17];
    const float* Bo = (const float*)d_in[18];

    k_gather<<<64, 256>>>(ids, cc, lat);
    k_weights<<<dim3(13, 64), 128>>>(Wr, Ur, Vr, Br, Wt, Ut, Vt, Bt,
                                     Wm, Um, Vm, Bm, Wo, Uo, Vo, Bo);
    k_mininit<<<(NSTAGE * BATCH * CH + 255) / 256, 256>>>();

    // stage 0: H=16
    k_mma<16><<<dim3(1, 4, 192), 256>>>(0);
    k_combineP<16><<<dim3(4, 64), 256>>>(0);
    // stage 1: H=32
    k_mma<32><<<dim3(2, 8, 192), 256>>>(1);
    k_combineP<32><<<dim3(16, 64), 256>>>(1);
    // stage 2: H=64
    k_mma<64><<<dim3(4, 16, 192), 256>>>(2);
    k_combineP<64><<<dim3(64, 64), 256>>>(2);
    // stage 3: H=128
    k_mma<128><<<dim3(8, 32, 192), 256>>>(3);
    k_comfinal<<<dim3(256, 64), 256>>>((float*)d_out);
}

// round 12
// speedup vs baseline: 2.3210x; 1.0651x over previous
#include <cuda_runtime.h>
#include <cuda_bf16.h>
#include <cstdint>

#define BATCH 64
#define CH 8
#define NSTAGE 4

typedef uint32_t u32;
typedef __nv_bfloat16 bf16;

// ---------------- device scratch ----------------
__device__ float g_ctx[BATCH*32];
__device__ float g_wr[NSTAGE*BATCH*CH*CH*9];
__device__ float g_wt[NSTAGE*BATCH*CH*CH*16];
__device__ float g_wm[NSTAGE*BATCH*CH*CH*25];
__device__ __align__(16) bf16 g_wmbh[NSTAGE*BATCH*8*27*8];
__device__ __align__(16) bf16 g_wmbl[NSTAGE*BATCH*8*27*8];
__device__ __align__(16) bf16 g_wrbh[NSTAGE*BATCH*8*10*8];
__device__ __align__(16) bf16 g_wrbl[NSTAGE*BATCH*8*10*8];
__device__ __align__(16) bf16 g_wtbh[NSTAGE*BATCH*1024];
__device__ __align__(16) bf16 g_wtbl[NSTAGE*BATCH*1024];
__device__ float g_wo[BATCH*3*CH];
__device__ float g_br[NSTAGE*BATCH*CH];
__device__ float g_bt[NSTAGE*BATCH*CH];
__device__ float g_bm[NSTAGE*BATCH*CH];
__device__ float g_bo[BATCH*3];
__device__ __align__(16) float g_pos[BATCH*128*128*CH];   // pixel-major
__device__ __align__(16) float g_neg[BATCH*256*256*CH];
__device__ __align__(16) float g_mul[BATCH*256*256*CH];
__device__ __align__(16) bf16 g_xph[BATCH*128*128*CH];    // pixel-major x hi
__device__ __align__(16) bf16 g_xpl[BATCH*128*128*CH];
__device__ __align__(16) float g_lxp[BATCH*128*128*CH];   // pixel-major log(|x|+1)
__device__ unsigned g_minpos[NSTAGE*BATCH*CH];
__device__ unsigned g_minneg[NSTAGE*BATCH*CH];
__device__ unsigned g_minmul[NSTAGE*BATCH*CH];

__device__ __forceinline__ float dln_f(float v, float mn) {
    float s = (v > 0.0f) ? 1.0f : -1.0f;
    float a = fabsf(v) - mn;
    return s * __logf(__logf(a + 2.718281828459045f) + 0.01f);
}

__device__ __forceinline__ void mma16816(float* c, u32 a0, u32 a1, u32 a2, u32 a3,
                                         u32 b0, u32 b1) {
    asm("mma.sync.aligned.m16n8k16.row.col.f32.bf16.bf16.f32 "
        "{%0,%1,%2,%3},{%4,%5,%6,%7},{%8,%9},{%0,%1,%2,%3};"
        : "+f"(c[0]), "+f"(c[1]), "+f"(c[2]), "+f"(c[3])
        : "r"(a0), "r"(a1), "r"(a2), "r"(a3), "r"(b0), "r"(b1));
}

__device__ __forceinline__ void ldsm4(u32& r0, u32& r1, u32& r2, u32& r3, u32 addr) {
    asm volatile("ldmatrix.sync.aligned.m8n8.x4.shared.b16 {%0,%1,%2,%3},[%4];"
                 : "=r"(r0), "=r"(r1), "=r"(r2), "=r"(r3) : "r"(addr));
}

// ---------------- gather: ctx + latents -> pixel-major xph/xpl/lxp @16 ----------------
__global__ __launch_bounds__(256) void k_gather(const int* __restrict__ ids,
                                                const float* __restrict__ cc,
                                                const float* __restrict__ lat) {
    int t = blockIdx.x * 256 + threadIdx.x;
    if (t < BATCH * 32) g_ctx[t] = cc[ids[t >> 5] * 32 + (t & 31)];
    int b = t >> 8, p = t & 255;
    const float* lb = lat + (size_t)ids[b] * (CH * 256);
    uint4 hv, lv;
    bf16* hp = (bf16*)&hv;
    bf16* lp = (bf16*)&lv;
    float lx[CH];
    #pragma unroll
    for (int c = 0; c < CH; c++) {
        float v = lb[c * 256 + p];
        bf16 h = __float2bfloat16(v);
        hp[c] = h;
        lp[c] = __float2bfloat16(v - __bfloat162float(h));
        lx[c] = __logf(fabsf(v) + 1.0f);
    }
    size_t base = (size_t)b * 256 + p;
    ((uint4*)g_xph)[base] = hv;
    ((uint4*)g_xpl)[base] = lv;
    float4* lxd = (float4*)(g_lxp + base * 8);
    lxd[0] = make_float4(lx[0], lx[1], lx[2], lx[3]);
    lxd[1] = make_float4(lx[4], lx[5], lx[6], lx[7]);
}

__global__ void k_mininit() {
    int t = blockIdx.x * blockDim.x + threadIdx.x;
    if (t < NSTAGE * BATCH * CH) {
        g_minpos[t] = 0x7F800000u; g_minneg[t] = 0x7F800000u; g_minmul[t] = 0x7F800000u;
    }
}

// ---------------- dynamic weights ----------------
__global__ void k_weights(
    const float* __restrict__ Wr, const float* __restrict__ Ur, const float* __restrict__ Vr, const float* __restrict__ Br,
    const float* __restrict__ Wt, const float* __restrict__ Ut, const float* __restrict__ Vt, const float* __restrict__ Bt,
    const float* __restrict__ Wm, const float* __restrict__ Um, const float* __restrict__ Vm, const float* __restrict__ Bm,
    const float* __restrict__ Wo, const float* __restrict__ Uo, const float* __restrict__ Vo, const float* __restrict__ Bo)
{
    int inst = blockIdx.x, b = blockIdx.y, tid = threadIdx.x;
    __shared__ float sctx[32];
    __shared__ float su[128];
    __shared__ float sv[3200];
    if (tid < 32) sctx[tid] = g_ctx[b * 32 + tid];
    __syncthreads();

    int O, KK, type = -1, stage = 0;
    const float *U, *V, *W, *Bb;
    float *gw, *gb;
    if (inst < 12) {
        type = inst >> 2; stage = inst & 3;
        O = CH;
        if (type == 0)      { KK = 9;  U = Ur; V = Vr; W = Wr; Bb = Br; gw = g_wr; gb = g_br; }
        else if (type == 1) { KK = 16; U = Ut; V = Vt; W = Wt; Bb = Bt; gw = g_wt; gb = g_bt; }
        else                { KK = 25; U = Um; V = Vm; W = Wm; Bb = Bm; gw = g_wm; gb = g_bm; }
        int uL = 16 * O, vL = 16 * CH * KK;
        U += (size_t)stage * 32 * uL; V += (size_t)stage * 32 * vL;
        W += (size_t)stage * O * CH * KK; Bb += (size_t)stage * 32 * O;
        gw += (size_t)(stage * BATCH + b) * O * CH * KK;
        gb += (size_t)(stage * BATCH + b) * O;
    } else {
        O = 3; KK = 1;
        U = Uo; V = Vo; W = Wo; Bb = Bo;
        gw = g_wo + b * 3 * CH; gb = g_bo + b * 3;
    }
    int uLen = 16 * O, vLen = 16 * CH * KK, IKK = CH * KK, wN = O * IKK;
    int sb = stage * BATCH + b;

    for (int j = tid; j < uLen; j += blockDim.x) {
        float s = 0.f;
        #pragma unroll
        for (int l = 0; l < 32; l++) s += sctx[l] * U[l * uLen + j];
        su[j] = s;
    }
    for (int j = tid; j < vLen; j += blockDim.x) {
        float s = 0.f;
        #pragma unroll
        for (int l = 0; l < 32; l++) s += sctx[l] * V[l * vLen + j];
        sv[j] = s;
    }
    __syncthreads();

    for (int widx = tid; widx < wN; widx += blockDim.x) {
        int o = widx / IKK, k = widx - o * IKK;
        float m = 0.f;
        #pragma unroll
        for (int r = 0; r < 16; r++) m += su[r * O + o] * sv[r * IKK + k];
        float w = W[widx] * (1.0f + m + 1e-3f);
        gw[widx] = w;
        if (type == 2) {
            int i = k / 25, t = k - i * 25;
            size_t d = (size_t)(sb * 8 + o) * 216 + t * 8 + i;
            bf16 h = __float2bfloat16(w);
            g_wmbh[d] = h;
            g_wmbl[d] = __float2bfloat16(w - __bfloat162float(h));
        } else if (type == 0) {
            int i = k / 9, t = k - i * 9;
            size_t d = (size_t)sb * 640 + (o * 10 + t) * 8 + i;
            bf16 h = __float2bfloat16(w);
            g_wrbh[d] = h;
            g_wrbl[d] = __float2bfloat16(w - __bfloat162float(h));
        } else if (type == 1) {
            int i = k / 16, t = k - i * 16;
            int ky = t >> 2, kx = t & 3;
            int py = (3 - ky) & 1, dy = (3 - ky) >> 1;
            int px = (3 - kx) & 1, dx = (3 - kx) >> 1;
            float wn = -w;
            size_t d = (size_t)sb * 1024 +
                       ((((size_t)(py * 2 + px) * 8 + o) * 2 + dy) * 2 + dx) * 8 + i;
            bf16 h = __float2bfloat16(wn);
            g_wtbh[d] = h;
            g_wtbl[d] = __float2bfloat16(wn - __bfloat162float(h));
        }
    }
    if (type == 2 && tid < 128) {
        int o = tid >> 4, t = 25 + ((tid >> 3) & 1), i = tid & 7;
        size_t d = (size_t)(sb * 8 + o) * 216 + t * 8 + i;
        g_wmbh[d] = __float2bfloat16(0.f);
        g_wmbl[d] = __float2bfloat16(0.f);
    }
    if (type == 0 && tid < 64) {
        int o = tid >> 3, i = tid & 7;
        size_t d = (size_t)sb * 640 + (o * 10 + 9) * 8 + i;
        g_wrbh[d] = __float2bfloat16(0.f);
        g_wrbl[d] = __float2bfloat16(0.f);
    }
    if (tid < O) {
        float s = 0.f;
        #pragma unroll
        for (int l = 0; l < 32; l++) s += sctx[l] * Bb[l * O + tid];
        gb[tid] = s;
    }
}

// ---------------- mma superkernel (all stages), pixel-major I/O ----------------
template<int H>
__global__ __launch_bounds__(256) void k_mma(int stage) {
    constexpr int OH = 2 * H;
    __shared__ __align__(16) u32 sm[6500];
    int role = blockIdx.z >> 6;
    int b = blockIdx.z & 63;
    int tid = threadIdx.x;
    int bx = blockIdx.x, by = blockIdx.y;
    int w_ = tid >> 5, lane = tid & 31, g = lane >> 2, tg = lane & 3;

    if (role == 0) {
        // ---- conv3 mma at H res ----
        constexpr int BX3 = (H >= 32) ? H / 32 : 1;
        constexpr int SQ3 = (H >= 32) ? 2 : 1;
        if (bx >= BX3 || by >= H / 8) return;
        u32* XH = sm;
        u32* XL = sm + 1360;
        u32* WH = sm + 2720;
        u32* WL = sm + 3040;
        float* sB = (float*)(sm + 3360);
        unsigned* sMin = (unsigned*)(sm + 3372);
        int x0 = bx * 32, y0 = by * 8;
        const uint4* w4h = (const uint4*)(g_wrbh + (size_t)(stage * BATCH + b) * 640);
        const uint4* w4l = (const uint4*)(g_wrbl + (size_t)(stage * BATCH + b) * 640);
        if (tid < 80) { ((uint4*)WH)[tid] = w4h[tid]; ((uint4*)WL)[tid] = w4l[tid]; }
        if (tid < 8) { sB[tid] = g_br[(stage * BATCH + b) * CH + tid]; sMin[tid] = 0x7F800000u; }
        const uint4* xh4 = (const uint4*)g_xph + (size_t)b * H * H;
        const uint4* xl4 = (const uint4*)g_xpl + (size_t)b * H * H;
        for (int j = tid; j < 10 * 34; j += 256) {
            int r = j / 34, c = j - 34 * r;
            int gy = y0 - 1 + r, gx = x0 - 1 + c;
            uint4 v = make_uint4(0, 0, 0, 0), w2 = make_uint4(0, 0, 0, 0);
            if ((unsigned)gy < (unsigned)H && (unsigned)gx < (unsigned)H) {
                v = xh4[gy * H + gx]; w2 = xl4[gy * H + gx];
            }
            ((uint4*)XH)[j] = v; ((uint4*)XL)[j] = w2;
        }
        __syncthreads();

        u32 baseH = (u32)__cvta_generic_to_shared(XH);
        u32 baseL = (u32)__cvta_generic_to_shared(XL);
        int pix16 = (lane & 7) + ((lane >> 3) & 1) * 8;
        int qsel = lane >> 4;
        u32 laneBase = (u32)((w_ * 34 + pix16) * 16);

        float b0f = sB[2 * tg], b1f = sB[2 * tg + 1];
        float c0[4] = {b0f, b1f, b0f, b1f};
        float c1[4] = {b0f, b1f, b0f, b1f};
        #pragma unroll
        for (int k = 0; k < 5; k++) {
            const int t0 = 2 * k, t1 = 2 * k + 1;
            const int t1c = (t1 < 9) ? t1 : 0;
            const int ky0 = t0 / 3, kx0 = t0 % 3;
            const int ky1 = t1c / 3, kx1 = t1c % 3;
            u32 bh0 = WH[(g * 10 + t0) * 4 + tg], bh1 = WH[(g * 10 + t1) * 4 + tg];
            u32 bl0 = WL[(g * 10 + t0) * 4 + tg], bl1 = WL[(g * 10 + t1) * 4 + tg];
            const int d0 = (ky0 * 34 + kx0) * 16, d1 = (ky1 * 34 + kx1) * 16;
            u32 off = laneBase + (u32)(qsel ? d1 : d0);
            #pragma unroll
            for (int s = 0; s < SQ3; s++) {
                u32 a0h, a1h, a2h, a3h, a0l, a1l, a2l, a3l;
                ldsm4(a0h, a1h, a2h, a3h, baseH + off + s * 256);
                ldsm4(a0l, a1l, a2l, a3l, baseL + off + s * 256);
                float* cc = s ? c1 : c0;
                mma16816(cc, a0h, a1h, a2h, a3h, bh0, bh1);
                mma16816(cc, a0l, a1l, a2l, a3l, bh0, bh1);
                mma16816(cc, a0h, a1h, a2h, a3h, bl0, bl1);
            }
        }
        int Y = y0 + w_;
        float* outp = g_pos + (size_t)b * H * H * 8;
        float me = 3.4e38f, mo = 3.4e38f;
        #pragma unroll
        for (int s = 0; s < SQ3; s++) {
            float* cc = s ? c1 : c0;
            int X = x0 + s * 16 + g;
            *(float2*)&outp[(size_t)(Y * H + X) * 8 + 2 * tg] = make_float2(cc[0], cc[1]);
            *(float2*)&outp[(size_t)(Y * H + X + 8) * 8 + 2 * tg] = make_float2(cc[2], cc[3]);
            me = fminf(me, fminf(fabsf(cc[0]), fabsf(cc[2])));
            mo = fminf(mo, fminf(fabsf(cc[1]), fabsf(cc[3])));
        }
        #pragma unroll
        for (int off2 = 16; off2 >= 4; off2 >>= 1) {
            me = fminf(me, __shfl_xor_sync(0xFFFFFFFFu, me, off2));
            mo = fminf(mo, __shfl_xor_sync(0xFFFFFFFFu, mo, off2));
        }
        if (lane < 4) {
            atomicMin(&sMin[2 * tg], __float_as_uint(me));
            atomicMin(&sMin[2 * tg + 1], __float_as_uint(mo));
        }
        __syncthreads();
        if (tid < 8) atomicMin(&g_minpos[stage * BATCH * CH + b * CH + tid], sMin[tid]);

    } else if (role == 1) {
        // ---- convT mma at OH res ----
        u32* XH = sm;
        u32* XL = sm + 432;
        u32* WH = sm + 864;
        u32* WL = sm + 1376;
        float* sB = (float*)(sm + 1888);
        unsigned* sMin = (unsigned*)(sm + 1900);
        int x0 = bx * 32, y0 = by * 8;
        const uint4* w4h = (const uint4*)(g_wtbh + (size_t)(stage * BATCH + b) * 1024);
        const uint4* w4l = (const uint4*)(g_wtbl + (size_t)(stage * BATCH + b) * 1024);
        if (tid < 128) { ((uint4*)WH)[tid] = w4h[tid]; ((uint4*)WL)[tid] = w4l[tid]; }
        if (tid < 8) { sB[tid] = g_bt[(stage * BATCH + b) * CH + tid]; sMin[tid] = 0x7F800000u; }
        int iy0 = y0 / 2 - 1, ix0 = x0 / 2 - 1;
        const uint4* xh4 = (const uint4*)g_xph + (size_t)b * H * H;
        const uint4* xl4 = (const uint4*)g_xpl + (size_t)b * H * H;
        for (int j = tid; j < 6 * 18; j += 256) {
            int r = j / 18, c = j - 18 * r;
            int gy = iy0 + r, gx = ix0 + c;
            uint4 v = make_uint4(0, 0, 0, 0), w2 = make_uint4(0, 0, 0, 0);
            if ((unsigned)gy < (unsigned)H && (unsigned)gx < (unsigned)H) {
                v = xh4[gy * H + gx]; w2 = xl4[gy * H + gx];
            }
            ((uint4*)XH)[j] = v; ((uint4*)XL)[j] = w2;
        }
        __syncthreads();

        int py = w_ & 1;
        int r0 = (w_ >> 1) + py;
        float b0f = sB[2 * tg], b1f = sB[2 * tg + 1];
        int Y = y0 + w_;
        float* outp = g_neg + (size_t)b * OH * OH * 8;
        float me = 3.4e38f, mo = 3.4e38f;
        #pragma unroll
        for (int px = 0; px < 2; px++) {
            float cc[4] = {b0f, b1f, b0f, b1f};
            #pragma unroll
            for (int dy = 0; dy < 2; dy++) {
                int wb = ((((py * 2 + px) * 8 + g) * 2 + dy) * 2) * 4 + tg;
                u32 bh0 = WH[wb], bh1 = WH[wb + 4];
                u32 bl0 = WL[wb], bl1 = WL[wb + 4];
                int base0 = ((r0 + dy) * 18 + g + px) * 4 + tg;
                u32 a0h = XH[base0], a1h = XH[base0 + 32], a2h = XH[base0 + 4], a3h = XH[base0 + 36];
                u32 a0l = XL[base0], a1l = XL[base0 + 32], a2l = XL[base0 + 4], a3l = XL[base0 + 36];
                mma16816(cc, a0h, a1h, a2h, a3h, bh0, bh1);
                mma16816(cc, a0l, a1l, a2l, a3l, bh0, bh1);
                mma16816(cc, a0h, a1h, a2h, a3h, bl0, bl1);
            }
            int X0 = x0 + 2 * g + px;
            int X1 = x0 + 2 * (g + 8) + px;
            *(float2*)&outp[(size_t)(Y * OH + X0) * 8 + 2 * tg] = make_float2(cc[0], cc[1]);
            *(float2*)&outp[(size_t)(Y * OH + X1) * 8 + 2 * tg] = make_float2(cc[2], cc[3]);
            me = fminf(me, fminf(fabsf(cc[0]), fabsf(cc[2])));
            mo = fminf(mo, fminf(fabsf(cc[1]), fabsf(cc[3])));
        }
        #pragma unroll
        for (int off2 = 16; off2 >= 4; off2 >>= 1) {
            me = fminf(me, __shfl_xor_sync(0xFFFFFFFFu, me, off2));
            mo = fminf(mo, __shfl_xor_sync(0xFFFFFFFFu, mo, off2));
        }
        if (lane < 4) {
            atomicMin(&sMin[2 * tg], __float_as_uint(me));
            atomicMin(&sMin[2 * tg + 1], __float_as_uint(mo));
        }
        __syncthreads();
        if (tid < 8) atomicMin(&g_minneg[stage * BATCH * CH + b * CH + tid], sMin[tid]);

    } else {
        // ---- conv5 mma at OH res; in-block bilinear from lxp (f32, H res) ----
        constexpr int LH = 8, LW = 20;
        float* sLx = (float*)sm;                    // 1280 f32
        u32* XuH = sm + 1280;                       // 1728
        u32* XuL = sm + 3008;                       // 1728
        u32* WH = sm + 4736;                        // 864
        u32* WL = sm + 5600;                        // 864
        float* sB = (float*)(sm + 6464);
        unsigned* sMin = (unsigned*)(sm + 6476);
        int x0 = bx * 32, y0 = by * 8;
        const uint4* w4h = (const uint4*)(g_wmbh + (size_t)((stage * BATCH + b) * 8) * 216);
        const uint4* w4l = (const uint4*)(g_wmbl + (size_t)((stage * BATCH + b) * 8) * 216);
        if (tid < 216) { ((uint4*)WH)[tid] = w4h[tid]; ((uint4*)WL)[tid] = w4l[tid]; }
        if (tid < 8) { sB[tid] = g_bm[(stage * BATCH + b) * CH + tid]; sMin[tid] = 0x7F800000u; }

        int gyLo = ((y0 - 2) >> 1) - 1;
        int gxLo = ((x0 - 2) >> 1) - 1;
        const float4* lx4 = (const float4*)g_lxp + (size_t)b * H * H * 2;
        for (int j = tid; j < LH * LW; j += 256) {
            int r = j / LW, c = j - LW * r;
            int gy = gyLo + r, gx = gxLo + c;
            float4 v0 = make_float4(0, 0, 0, 0), v1 = make_float4(0, 0, 0, 0);
            if ((unsigned)gy < (unsigned)H && (unsigned)gx < (unsigned)H) {
                v0 = lx4[(gy * H + gx) * 2];
                v1 = lx4[(gy * H + gx) * 2 + 1];
            }
            ((float4*)sLx)[j * 2] = v0;
            ((float4*)sLx)[j * 2 + 1] = v1;
        }
        __syncthreads();
        bf16* xuh = (bf16*)XuH;
        bf16* xul = (bf16*)XuL;
        for (int j = tid; j < 12 * 36; j += 256) {
            int r = j / 36, c = j - 36 * r;
            int Y = y0 - 2 + r, X = x0 - 2 + c;
            if ((unsigned)Y < (unsigned)OH && (unsigned)X < (unsigned)OH) {
                int iy = Y >> 1, ix = X >> 1;
                int yo = (Y & 1) ? min(iy + 1, H - 1) : max(iy - 1, 0);
                int xo = (X & 1) ? min(ix + 1, H - 1) : max(ix - 1, 0);
                int ry = iy - gyLo, ryo = yo - gyLo;
                int cx = ix - gxLo, cxo = xo - gxLo;
                const float4* A  = (const float4*)(sLx + (ry * LW + cx) * 8);
                const float4* Bq = (const float4*)(sLx + (ry * LW + cxo) * 8);
                const float4* Cq = (const float4*)(sLx + (ryo * LW + cx) * 8);
                const float4* D  = (const float4*)(sLx + (ryo * LW + cxo) * 8);
                #pragma unroll
                for (int half = 0; half < 2; half++) {
                    float4 a = A[half], bb = Bq[half], cc2 = Cq[half], d = D[half];
                    float v[4];
                    v[0] = 0.5625f * a.x + 0.1875f * bb.x + 0.1875f * cc2.x + 0.0625f * d.x;
                    v[1] = 0.5625f * a.y + 0.1875f * bb.y + 0.1875f * cc2.y + 0.0625f * d.y;
                    v[2] = 0.5625f * a.z + 0.1875f * bb.z + 0.1875f * cc2.z + 0.0625f * d.z;
                    v[3] = 0.5625f * a.w + 0.1875f * bb.w + 0.1875f * cc2.w + 0.0625f * d.w;
                    #pragma unroll
                    for (int k = 0; k < 4; k++) {
                        bf16 h = __float2bfloat16(v[k]);
                        xuh[j * 8 + half * 4 + k] = h;
                        xul[j * 8 + half * 4 + k] = __float2bfloat16(v[k] - __bfloat162float(h));
                    }
                }
            } else {
                ((uint4*)XuH)[j] = make_uint4(0, 0, 0, 0);
                ((uint4*)XuL)[j] = make_uint4(0, 0, 0, 0);
            }
        }
        __syncthreads();

        u32 baseH = (u32)__cvta_generic_to_shared(XuH);
        u32 baseL = (u32)__cvta_generic_to_shared(XuL);
        int pix16 = (lane & 7) + ((lane >> 3) & 1) * 8;
        int qsel = lane >> 4;
        u32 laneBase = (u32)((w_ * 36 + pix16) * 16);

        float b0f = sB[2 * tg], b1f = sB[2 * tg + 1];
        float c0[4] = {b0f, b1f, b0f, b1f};
        float c1[4] = {b0f, b1f, b0f, b1f};
        #pragma unroll
        for (int k = 0; k < 13; k++) {
            const int t0 = 2 * k, t1 = 2 * k + 1;
            const int ky0 = t0 / 5, kx0 = t0 % 5;
            const int ky1 = (t1 < 25) ? t1 / 5 : 0, kx1 = (t1 < 25) ? t1 % 5 : 0;
            u32 bh0 = WH[(g * 27 + t0) * 4 + tg], bh1 = WH[(g * 27 + t1) * 4 + tg];
            u32 bl0 = WL[(g * 27 + t0) * 4 + tg], bl1 = WL[(g * 27 + t1) * 4 + tg];
            const int d0 = (ky0 * 36 + kx0) * 16, d1 = (ky1 * 36 + kx1) * 16;
            u32 off = laneBase + (u32)(qsel ? d1 : d0);
            #pragma unroll
            for (int s = 0; s < 2; s++) {
                u32 a0h, a1h, a2h, a3h, a0l, a1l, a2l, a3l;
                ldsm4(a0h, a1h, a2h, a3h, baseH + off + s * 256);
                ldsm4(a0l, a1l, a2l, a3l, baseL + off + s * 256);
                float* cc = s ? c1 : c0;
                mma16816(cc, a0h, a1h, a2h, a3h, bh0, bh1);
                mma16816(cc, a0l, a1l, a2l, a3l, bh0, bh1);
                mma16816(cc, a0h, a1h, a2h, a3h, bl0, bl1);
            }
        }
        int Y = y0 + w_;
        float* mulb = g_mul + (size_t)b * OH * OH * 8;
        float me = 3.4e38f, mo = 3.4e38f;
        #pragma unroll
        for (int s = 0; s < 2; s++) {
            float* cc = s ? c1 : c0;
            int X = x0 + s * 16 + g;
            *(float2*)&mulb[(size_t)(Y * OH + X) * 8 + 2 * tg] = make_float2(cc[0], cc[1]);
            *(float2*)&mulb[(size_t)(Y * OH + X + 8) * 8 + 2 * tg] = make_float2(cc[2], cc[3]);
            me = fminf(me, fminf(fabsf(cc[0]), fabsf(cc[2])));
            mo = fminf(mo, fminf(fabsf(cc[1]), fabsf(cc[3])));
        }
        #pragma unroll
        for (int off2 = 16; off2 >= 4; off2 >>= 1) {
            me = fminf(me, __shfl_xor_sync(0xFFFFFFFFu, me, off2));
            mo = fminf(mo, __shfl_xor_sync(0xFFFFFFFFu, mo, off2));
        }
        if (lane < 4) {
            atomicMin(&sMin[2 * tg], __float_as_uint(me));
            atomicMin(&sMin[2 * tg + 1], __float_as_uint(mo));
        }
        __syncthreads();
        if (tid < 8) atomicMin(&g_minmul[stage * BATCH * CH + b * CH + tid], sMin[tid]);
    }
}

// ---------------- combine to pixel-major xph/xpl/lxp (dp shared across even/odd pair) ----------------
template<int H>
__global__ __launch_bounds__(256) void k_combineP(int stage) {
    constexpr int OH = 2 * H;
    int b = blockIdx.y;
    int p = blockIdx.x * 256 + threadIdx.x;
    if (p >= OH * OH) return;
    int lane = threadIdx.x & 31;
    int Y = p / OH, X = p - Y * OH;
    int pp = (Y >> 1) * H + (X >> 1);
    __shared__ float sMn[3 * CH];
    if (threadIdx.x < 3 * CH) {
        int c = threadIdx.x & 7, which = threadIdx.x >> 3;
        const unsigned* src = which == 0 ? g_minpos : (which == 1 ? g_minneg : g_minmul);
        sMn[threadIdx.x] = __uint_as_float(src[stage * BATCH * CH + b * CH + c]);
    }
    __syncthreads();

    // dln(pos): computed by even lanes only (pair shares pos pixel), shuffled to odd
    float dpv[CH];
    {
        float mydp[CH];
        if ((lane & 1) == 0) {
            const float4* p4 = (const float4*)(g_pos + ((size_t)b * H * H + pp) * 8);
            float4 a0 = p4[0], a1 = p4[1];
            float pv[8] = {a0.x, a0.y, a0.z, a0.w, a1.x, a1.y, a1.z, a1.w};
            #pragma unroll
            for (int c = 0; c < CH; c++) mydp[c] = dln_f(pv[c], sMn[c]);
        } else {
            #pragma unroll
            for (int c = 0; c < CH; c++) mydp[c] = 0.f;
        }
        #pragma unroll
        for (int c = 0; c < CH; c++)
            dpv[c] = __shfl_sync(0xFFFFFFFFu, mydp[c], lane & ~1);
    }

    float ng[CH], ml[CH];
    {
        const float4* n4 = (const float4*)(g_neg + ((size_t)b * OH * OH + p) * 8);
        const float4* m4 = (const float4*)(g_mul + ((size_t)b * OH * OH + p) * 8);
        float4 a0 = n4[0], a1 = n4[1];
        ng[0]=a0.x; ng[1]=a0.y; ng[2]=a0.z; ng[3]=a0.w;
        ng[4]=a1.x; ng[5]=a1.y; ng[6]=a1.z; ng[7]=a1.w;
        a0 = m4[0]; a1 = m4[1];
        ml[0]=a0.x; ml[1]=a0.y; ml[2]=a0.z; ml[3]=a0.w;
        ml[4]=a1.x; ml[5]=a1.y; ml[6]=a1.z; ml[7]=a1.w;
    }

    uint4 hv, lv;
    bf16* hp = (bf16*)&hv;
    bf16* lp = (bf16*)&lv;
    float lx[CH];
    #pragma unroll
    for (int c = 0; c < CH; c++) {
        float xv = (dpv[c] + dln_f(ng[c], sMn[8 + c])) * dln_f(ml[c], sMn[16 + c]);
        bf16 h = __float2bfloat16(xv);
        hp[c] = h;
        lp[c] = __float2bfloat16(xv - __bfloat162float(h));
        lx[c] = __logf(fabsf(xv) + 1.0f);
    }
    size_t base = (size_t)b * OH * OH + p;
    ((uint4*)g_xph)[base] = hv;
    ((uint4*)g_xpl)[base] = lv;
    float4* lxd = (float4*)(g_lxp + base * 8);
    lxd[0] = make_float4(lx[0], lx[1], lx[2], lx[3]);
    lxd[1] = make_float4(lx[4], lx[5], lx[6], lx[7]);
}

// ---------------- final combine + 1x1 conv (dp shared across even/odd pair) ----------------
__global__ __launch_bounds__(256) void k_comfinal(float* __restrict__ out) {
    constexpr int H = 128, OH = 256;
    constexpr int stage = 3;
    int b = blockIdx.y;
    int p = blockIdx.x * 256 + threadIdx.x;
    int lane = threadIdx.x & 31;
    int Y = p >> 8, X = p & 255;
    int pp = (Y >> 1) * H + (X >> 1);
    __shared__ float sMn[3 * CH];
    __shared__ float sWo[3 * CH];
    __shared__ float sBo[3];
    if (threadIdx.x < 3 * CH) {
        int c = threadIdx.x & 7, which = threadIdx.x >> 3;
        const unsigned* src = which == 0 ? g_minpos : (which == 1 ? g_minneg : g_minmul);
        sMn[threadIdx.x] = __uint_as_float(src[stage * BATCH * CH + b * CH + c]);
        sWo[threadIdx.x] = g_wo[b * 24 + threadIdx.x];
    }
    if (threadIdx.x >= 32 && threadIdx.x < 35) sBo[threadIdx.x - 32] = g_bo[b * 3 + threadIdx.x - 32];
    __syncthreads();

    float dpv[CH];
    {
        float mydp[CH];
        if ((lane & 1) == 0) {
            const float4* p4 = (const float4*)(g_pos + ((size_t)b * H * H + pp) * 8);
            float4 a0 = p4[0], a1 = p4[1];
            float pv[8] = {a0.x, a0.y, a0.z, a0.w, a1.x, a1.y, a1.z, a1.w};
            #pragma unroll
            for (int c = 0; c < CH; c++) mydp[c] = dln_f(pv[c], sMn[c]);
        } else {
            #pragma unroll
            for (int c = 0; c < CH; c++) mydp[c] = 0.f;
        }
        #pragma unroll
        for (int c = 0; c < CH; c++)
            dpv[c] = __shfl_sync(0xFFFFFFFFu, mydp[c], lane & ~1);
    }

    const float4* n4 = (const float4*)(g_neg + ((size_t)b * OH * OH + p) * 8);
    const float4* m4 = (const float4*)(g_mul + ((size_t)b * OH * OH + p) * 8);
    float ng[8], ml[8];
    float4 a0 = n4[0], a1 = n4[1];
    ng[0]=a0.x; ng[1]=a0.y; ng[2]=a0.z; ng[3]=a0.w; ng[4]=a1.x; ng[5]=a1.y; ng[6]=a1.z; ng[7]=a1.w;
    a0 = m4[0]; a1 = m4[1];
    ml[0]=a0.x; ml[1]=a0.y; ml[2]=a0.z; ml[3]=a0.w; ml[4]=a1.x; ml[5]=a1.y; ml[6]=a1.z; ml[7]=a1.w;

    float acc[3] = {sBo[0], sBo[1], sBo[2]};
    #pragma unroll
    for (int c = 0; c < CH; c++) {
        float xv = (dpv[c] + dln_f(ng[c], sMn[8 + c])) * dln_f(ml[c], sMn[16 + c]);
        #pragma unroll
        for (int o = 0; o < 3; o++) acc[o] += sWo[o * CH + c] * xv;
    }
    #pragma unroll
    for (int o = 0; o < 3; o++)
        out[((size_t)b * 3 + o) * OH * OH + p] = acc[o];
}

// ---------------- launcher ----------------
extern "C" void kernel_launch(void* const* d_in, const int* in_sizes, int n_in,
                              void* d_out, int out_size) {
    const int*   ids = (const int*)  d_in[0];
    const float* cc  = (const float*)d_in[1];
    const float* lat = (const float*)d_in[2];
    const float* Wr = (const float*)d_in[3];
    const float* Ur = (const float*)d_in[4];
    const float* Vr = (const float*)d_in[5];
    const float* Br = (const float*)d_in[6];
    const float* Wt = (const float*)d_in[7];
    const float* Ut = (const float*)d_in[8];
    const float* Vt = (const float*)d_in[9];
    const float* Bt = (const float*)d_in[10];
    const float* Wm = (const float*)d_in[11];
    const float* Um = (const float*)d_in[12];
    const float* Vm = (const float*)d_in[13];
    const float* Bm = (const float*)d_in[14];
    const float* Wo = (const float*)d_in[15];
    const float* Uo = (const float*)d_in[16];
    const float* Vo = (const float*)d_in[17];
    const float* Bo = (const float*)d_in[18];

    k_gather<<<64, 256>>>(ids, cc, lat);
    k_weights<<<dim3(13, 64), 128>>>(Wr, Ur, Vr, Br, Wt, Ut, Vt, Bt,
                                     Wm, Um, Vm, Bm, Wo, Uo, Vo, Bo);
    k_mininit<<<(NSTAGE * BATCH * CH + 255) / 256, 256>>>();

    // stage 0: H=16
    k_mma<16><<<dim3(1, 4, 192), 256>>>(0);
    k_combineP<16><<<dim3(4, 64), 256>>>(0);
    // stage 1: H=32
    k_mma<32><<<dim3(2, 8, 192), 256>>>(1);
    k_combineP<32><<<dim3(16, 64), 256>>>(1);
    // stage 2: H=64
    k_mma<64><<<dim3(4, 16, 192), 256>>>(2);
    k_combineP<64><<<dim3(64, 64), 256>>>(2);
    // stage 3: H=128
    k_mma<128><<<dim3(8, 32, 192), 256>>>(3);
    k_comfinal<<<dim3(256, 64), 256>>>((float*)d_out);
}

// round 13
// speedup vs baseline: 2.4794x; 1.0683x over previous
#include <cuda_runtime.h>
#include <cuda_bf16.h>
#include <cstdint>

#define BATCH 64
#define CH 8
#define NSTAGE 4

typedef uint32_t u32;
typedef __nv_bfloat16 bf16;

// ---------------- device scratch ----------------
__device__ float g_ctx[BATCH*32];
__device__ float g_wr[NSTAGE*BATCH*CH*CH*9];
__device__ float g_wt[NSTAGE*BATCH*CH*CH*16];
__device__ float g_wm[NSTAGE*BATCH*CH*CH*25];
__device__ __align__(16) bf16 g_wmbh[NSTAGE*BATCH*8*27*8];
__device__ __align__(16) bf16 g_wmbl[NSTAGE*BATCH*8*27*8];
__device__ __align__(16) bf16 g_wrbh[NSTAGE*BATCH*8*10*8];
__device__ __align__(16) bf16 g_wrbl[NSTAGE*BATCH*8*10*8];
__device__ __align__(16) bf16 g_wtbh[NSTAGE*BATCH*1024];
__device__ __align__(16) bf16 g_wtbl[NSTAGE*BATCH*1024];
__device__ float g_wo[BATCH*3*CH];
__device__ float g_br[NSTAGE*BATCH*CH];
__device__ float g_bt[NSTAGE*BATCH*CH];
__device__ float g_bm[NSTAGE*BATCH*CH];
__device__ float g_bo[BATCH*3];
__device__ __align__(16) float g_pos[BATCH*128*128*CH];   // pixel-major
__device__ __align__(16) float g_neg[BATCH*256*256*CH];
__device__ __align__(16) float g_mul[BATCH*256*256*CH];
__device__ __align__(16) bf16 g_xph[BATCH*128*128*CH];    // pixel-major x hi
__device__ __align__(16) bf16 g_xpl[BATCH*128*128*CH];
__device__ __align__(16) float g_lxp[BATCH*128*128*CH];   // pixel-major log(|x|+1)
__device__ unsigned g_minpos[NSTAGE*BATCH*CH];
__device__ unsigned g_minneg[NSTAGE*BATCH*CH];
__device__ unsigned g_minmul[NSTAGE*BATCH*CH];

__device__ __forceinline__ float dln_f(float v, float mn) {
    float s = (v > 0.0f) ? 1.0f : -1.0f;
    float a = fabsf(v) - mn;
    return s * __logf(__logf(a + 2.718281828459045f) + 0.01f);
}

__device__ __forceinline__ void mma16816(float* c, u32 a0, u32 a1, u32 a2, u32 a3,
                                         u32 b0, u32 b1) {
    asm("mma.sync.aligned.m16n8k16.row.col.f32.bf16.bf16.f32 "
        "{%0,%1,%2,%3},{%4,%5,%6,%7},{%8,%9},{%0,%1,%2,%3};"
        : "+f"(c[0]), "+f"(c[1]), "+f"(c[2]), "+f"(c[3])
        : "r"(a0), "r"(a1), "r"(a2), "r"(a3), "r"(b0), "r"(b1));
}

__device__ __forceinline__ void ldsm4(u32& r0, u32& r1, u32& r2, u32& r3, u32 addr) {
    asm volatile("ldmatrix.sync.aligned.m8n8.x4.shared.b16 {%0,%1,%2,%3},[%4];"
                 : "=r"(r0), "=r"(r1), "=r"(r2), "=r"(r3) : "r"(addr));
}

// ---------------- gather ----------------
__global__ __launch_bounds__(256) void k_gather(const int* __restrict__ ids,
                                                const float* __restrict__ cc,
                                                const float* __restrict__ lat) {
    int t = blockIdx.x * 256 + threadIdx.x;
    if (t < BATCH * 32) g_ctx[t] = cc[ids[t >> 5] * 32 + (t & 31)];
    int b = t >> 8, p = t & 255;
    const float* lb = lat + (size_t)ids[b] * (CH * 256);
    uint4 hv, lv;
    bf16* hp = (bf16*)&hv;
    bf16* lp = (bf16*)&lv;
    float lx[CH];
    #pragma unroll
    for (int c = 0; c < CH; c++) {
        float v = lb[c * 256 + p];
        bf16 h = __float2bfloat16(v);
        hp[c] = h;
        lp[c] = __float2bfloat16(v - __bfloat162float(h));
        lx[c] = __logf(fabsf(v) + 1.0f);
    }
    size_t base = (size_t)b * 256 + p;
    ((uint4*)g_xph)[base] = hv;
    ((uint4*)g_xpl)[base] = lv;
    float4* lxd = (float4*)(g_lxp + base * 8);
    lxd[0] = make_float4(lx[0], lx[1], lx[2], lx[3]);
    lxd[1] = make_float4(lx[4], lx[5], lx[6], lx[7]);
}

__global__ void k_mininit() {
    int t = blockIdx.x * blockDim.x + threadIdx.x;
    if (t < NSTAGE * BATCH * CH) {
        g_minpos[t] = 0x7F800000u; g_minneg[t] = 0x7F800000u; g_minmul[t] = 0x7F800000u;
    }
}

// ---------------- dynamic weights ----------------
__global__ void k_weights(
    const float* __restrict__ Wr, const float* __restrict__ Ur, const float* __restrict__ Vr, const float* __restrict__ Br,
    const float* __restrict__ Wt, const float* __restrict__ Ut, const float* __restrict__ Vt, const float* __restrict__ Bt,
    const float* __restrict__ Wm, const float* __restrict__ Um, const float* __restrict__ Vm, const float* __restrict__ Bm,
    const float* __restrict__ Wo, const float* __restrict__ Uo, const float* __restrict__ Vo, const float* __restrict__ Bo)
{
    int inst = blockIdx.x, b = blockIdx.y, tid = threadIdx.x;
    __shared__ float sctx[32];
    __shared__ float su[128];
    __shared__ float sv[3200];
    if (tid < 32) sctx[tid] = g_ctx[b * 32 + tid];
    __syncthreads();

    int O, KK, type = -1, stage = 0;
    const float *U, *V, *W, *Bb;
    float *gw, *gb;
    if (inst < 12) {
        type = inst >> 2; stage = inst & 3;
        O = CH;
        if (type == 0)      { KK = 9;  U = Ur; V = Vr; W = Wr; Bb = Br; gw = g_wr; gb = g_br; }
        else if (type == 1) { KK = 16; U = Ut; V = Vt; W = Wt; Bb = Bt; gw = g_wt; gb = g_bt; }
        else                { KK = 25; U = Um; V = Vm; W = Wm; Bb = Bm; gw = g_wm; gb = g_bm; }
        int uL = 16 * O, vL = 16 * CH * KK;
        U += (size_t)stage * 32 * uL; V += (size_t)stage * 32 * vL;
        W += (size_t)stage * O * CH * KK; Bb += (size_t)stage * 32 * O;
        gw += (size_t)(stage * BATCH + b) * O * CH * KK;
        gb += (size_t)(stage * BATCH + b) * O;
    } else {
        O = 3; KK = 1;
        U = Uo; V = Vo; W = Wo; Bb = Bo;
        gw = g_wo + b * 3 * CH; gb = g_bo + b * 3;
    }
    int uLen = 16 * O, vLen = 16 * CH * KK, IKK = CH * KK, wN = O * IKK;
    int sb = stage * BATCH + b;

    for (int j = tid; j < uLen; j += blockDim.x) {
        float s = 0.f;
        #pragma unroll
        for (int l = 0; l < 32; l++) s += sctx[l] * U[l * uLen + j];
        su[j] = s;
    }
    for (int j = tid; j < vLen; j += blockDim.x) {
        float s = 0.f;
        #pragma unroll
        for (int l = 0; l < 32; l++) s += sctx[l] * V[l * vLen + j];
        sv[j] = s;
    }
    __syncthreads();

    for (int widx = tid; widx < wN; widx += blockDim.x) {
        int o = widx / IKK, k = widx - o * IKK;
        float m = 0.f;
        #pragma unroll
        for (int r = 0; r < 16; r++) m += su[r * O + o] * sv[r * IKK + k];
        float w = W[widx] * (1.0f + m + 1e-3f);
        gw[widx] = w;
        if (type == 2) {
            int i = k / 25, t = k - i * 25;
            size_t d = (size_t)(sb * 8 + o) * 216 + t * 8 + i;
            bf16 h = __float2bfloat16(w);
            g_wmbh[d] = h;
            g_wmbl[d] = __float2bfloat16(w - __bfloat162float(h));
        } else if (type == 0) {
            int i = k / 9, t = k - i * 9;
            size_t d = (size_t)sb * 640 + (o * 10 + t) * 8 + i;
            bf16 h = __float2bfloat16(w);
            g_wrbh[d] = h;
            g_wrbl[d] = __float2bfloat16(w - __bfloat162float(h));
        } else if (type == 1) {
            int i = k / 16, t = k - i * 16;
            int ky = t >> 2, kx = t & 3;
            int py = (3 - ky) & 1, dy = (3 - ky) >> 1;
            int px = (3 - kx) & 1, dx = (3 - kx) >> 1;
            float wn = -w;
            size_t d = (size_t)sb * 1024 +
                       ((((size_t)(py * 2 + px) * 8 + o) * 2 + dy) * 2 + dx) * 8 + i;
            bf16 h = __float2bfloat16(wn);
            g_wtbh[d] = h;
            g_wtbl[d] = __float2bfloat16(wn - __bfloat162float(h));
        }
    }
    if (type == 2 && tid < 128) {
        int o = tid >> 4, t = 25 + ((tid >> 3) & 1), i = tid & 7;
        size_t d = (size_t)(sb * 8 + o) * 216 + t * 8 + i;
        g_wmbh[d] = __float2bfloat16(0.f);
        g_wmbl[d] = __float2bfloat16(0.f);
    }
    if (type == 0 && tid < 64) {
        int o = tid >> 3, i = tid & 7;
        size_t d = (size_t)sb * 640 + (o * 10 + 9) * 8 + i;
        g_wrbh[d] = __float2bfloat16(0.f);
        g_wrbl[d] = __float2bfloat16(0.f);
    }
    if (tid < O) {
        float s = 0.f;
        #pragma unroll
        for (int l = 0; l < 32; l++) s += sctx[l] * Bb[l * O + tid];
        gb[tid] = s;
    }
}

// ---------------- mma superkernel (all stages), pixel-major I/O, TH=16 tiles ----------------
template<int H>
__global__ __launch_bounds__(256) void k_mma(int stage) {
    constexpr int OH = 2 * H;
    __shared__ __align__(16) u32 sm[9440];
    int role = blockIdx.z >> 6;
    int b = blockIdx.z & 63;
    int tid = threadIdx.x;
    int bx = blockIdx.x, by = blockIdx.y;
    int w_ = tid >> 5, lane = tid & 31, g = lane >> 2, tg = lane & 3;
    int pix16 = (lane & 7) + ((lane >> 3) & 1) * 8;
    int qsel = lane >> 4;

    if (role == 0) {
        // ---- conv3 mma at H res; tile 32x16 (TH=16, 2 rows per warp) ----
        constexpr int BX3 = (H >= 32) ? H / 32 : 1;
        constexpr int SQ3 = (H >= 32) ? 2 : 1;
        if (bx >= BX3 || by >= H / 16) return;
        u32* XH = sm;                 // 18*34 uint4 = 2448 u32
        u32* XL = sm + 2448;
        u32* WH = sm + 4896;          // 320
        u32* WL = sm + 5216;
        float* sB = (float*)(sm + 5536);
        unsigned* sMin = (unsigned*)(sm + 5548);
        int x0 = bx * 32, y0 = by * 16;
        const uint4* w4h = (const uint4*)(g_wrbh + (size_t)(stage * BATCH + b) * 640);
        const uint4* w4l = (const uint4*)(g_wrbl + (size_t)(stage * BATCH + b) * 640);
        if (tid < 80) { ((uint4*)WH)[tid] = w4h[tid]; ((uint4*)WL)[tid] = w4l[tid]; }
        if (tid < 8) { sB[tid] = g_br[(stage * BATCH + b) * CH + tid]; sMin[tid] = 0x7F800000u; }
        const uint4* xh4 = (const uint4*)g_xph + (size_t)b * H * H;
        const uint4* xl4 = (const uint4*)g_xpl + (size_t)b * H * H;
        for (int j = tid; j < 18 * 34; j += 256) {
            int r = j / 34, c = j - 34 * r;
            int gy = y0 - 1 + r, gx = x0 - 1 + c;
            uint4 v = make_uint4(0, 0, 0, 0), w2 = make_uint4(0, 0, 0, 0);
            if ((unsigned)gy < (unsigned)H && (unsigned)gx < (unsigned)H) {
                v = xh4[gy * H + gx]; w2 = xl4[gy * H + gx];
            }
            ((uint4*)XH)[j] = v; ((uint4*)XL)[j] = w2;
        }
        __syncthreads();

        u32 baseH = (u32)__cvta_generic_to_shared(XH);
        u32 baseL = (u32)__cvta_generic_to_shared(XL);
        u32 lb0 = (u32)((w_ * 34 + pix16) * 16);
        u32 lb1 = (u32)(((w_ + 8) * 34 + pix16) * 16);

        float b0f = sB[2 * tg], b1f = sB[2 * tg + 1];
        float cA0[4] = {b0f, b1f, b0f, b1f}, cA1[4] = {b0f, b1f, b0f, b1f};
        float cB0[4] = {b0f, b1f, b0f, b1f}, cB1[4] = {b0f, b1f, b0f, b1f};
        #pragma unroll
        for (int k = 0; k < 5; k++) {
            const int t0 = 2 * k, t1 = 2 * k + 1;
            const int t1c = (t1 < 9) ? t1 : 0;
            const int ky0 = t0 / 3, kx0 = t0 % 3;
            const int ky1 = t1c / 3, kx1 = t1c % 3;
            u32 bh0 = WH[(g * 10 + t0) * 4 + tg], bh1 = WH[(g * 10 + t1) * 4 + tg];
            u32 bl0 = WL[(g * 10 + t0) * 4 + tg], bl1 = WL[(g * 10 + t1) * 4 + tg];
            const int d0 = (ky0 * 34 + kx0) * 16, d1 = (ky1 * 34 + kx1) * 16;
            u32 dd = (u32)(qsel ? d1 : d0);
            #pragma unroll
            for (int s = 0; s < SQ3; s++) {
                u32 a0h, a1h, a2h, a3h, a0l, a1l, a2l, a3l;
                // row group 0
                ldsm4(a0h, a1h, a2h, a3h, baseH + lb0 + dd + s * 256);
                ldsm4(a0l, a1l, a2l, a3l, baseL + lb0 + dd + s * 256);
                float* cc = s ? cA1 : cA0;
                mma16816(cc, a0h, a1h, a2h, a3h, bh0, bh1);
                mma16816(cc, a0l, a1l, a2l, a3l, bh0, bh1);
                mma16816(cc, a0h, a1h, a2h, a3h, bl0, bl1);
                // row group 1
                ldsm4(a0h, a1h, a2h, a3h, baseH + lb1 + dd + s * 256);
                ldsm4(a0l, a1l, a2l, a3l, baseL + lb1 + dd + s * 256);
                float* cd = s ? cB1 : cB0;
                mma16816(cd, a0h, a1h, a2h, a3h, bh0, bh1);
                mma16816(cd, a0l, a1l, a2l, a3l, bh0, bh1);
                mma16816(cd, a0h, a1h, a2h, a3h, bl0, bl1);
            }
        }
        float* outp = g_pos + (size_t)b * H * H * 8;
        float me = 3.4e38f, mo = 3.4e38f;
        #pragma unroll
        for (int rgi = 0; rgi < 2; rgi++) {
            int Y = y0 + w_ + rgi * 8;
            #pragma unroll
            for (int s = 0; s < SQ3; s++) {
                float* cc = rgi ? (s ? cB1 : cB0) : (s ? cA1 : cA0);
                int X = x0 + s * 16 + g;
                *(float2*)&outp[(size_t)(Y * H + X) * 8 + 2 * tg] = make_float2(cc[0], cc[1]);
                *(float2*)&outp[(size_t)(Y * H + X + 8) * 8 + 2 * tg] = make_float2(cc[2], cc[3]);
                me = fminf(me, fminf(fabsf(cc[0]), fabsf(cc[2])));
                mo = fminf(mo, fminf(fabsf(cc[1]), fabsf(cc[3])));
            }
        }
        #pragma unroll
        for (int off2 = 16; off2 >= 4; off2 >>= 1) {
            me = fminf(me, __shfl_xor_sync(0xFFFFFFFFu, me, off2));
            mo = fminf(mo, __shfl_xor_sync(0xFFFFFFFFu, mo, off2));
        }
        if (lane < 4) {
            atomicMin(&sMin[2 * tg], __float_as_uint(me));
            atomicMin(&sMin[2 * tg + 1], __float_as_uint(mo));
        }
        __syncthreads();
        if (tid < 8) atomicMin(&g_minpos[stage * BATCH * CH + b * CH + tid], sMin[tid]);

    } else if (role == 1) {
        // ---- convT mma at OH res (TH=8, unchanged) ----
        u32* XH = sm;
        u32* XL = sm + 432;
        u32* WH = sm + 864;
        u32* WL = sm + 1376;
        float* sB = (float*)(sm + 1888);
        unsigned* sMin = (unsigned*)(sm + 1900);
        int x0 = bx * 32, y0 = by * 8;
        const uint4* w4h = (const uint4*)(g_wtbh + (size_t)(stage * BATCH + b) * 1024);
        const uint4* w4l = (const uint4*)(g_wtbl + (size_t)(stage * BATCH + b) * 1024);
        if (tid < 128) { ((uint4*)WH)[tid] = w4h[tid]; ((uint4*)WL)[tid] = w4l[tid]; }
        if (tid < 8) { sB[tid] = g_bt[(stage * BATCH + b) * CH + tid]; sMin[tid] = 0x7F800000u; }
        int iy0 = y0 / 2 - 1, ix0 = x0 / 2 - 1;
        const uint4* xh4 = (const uint4*)g_xph + (size_t)b * H * H;
        const uint4* xl4 = (const uint4*)g_xpl + (size_t)b * H * H;
        for (int j = tid; j < 6 * 18; j += 256) {
            int r = j / 18, c = j - 18 * r;
            int gy = iy0 + r, gx = ix0 + c;
            uint4 v = make_uint4(0, 0, 0, 0), w2 = make_uint4(0, 0, 0, 0);
            if ((unsigned)gy < (unsigned)H && (unsigned)gx < (unsigned)H) {
                v = xh4[gy * H + gx]; w2 = xl4[gy * H + gx];
            }
            ((uint4*)XH)[j] = v; ((uint4*)XL)[j] = w2;
        }
        __syncthreads();

        int py = w_ & 1;
        int r0 = (w_ >> 1) + py;
        float b0f = sB[2 * tg], b1f = sB[2 * tg + 1];
        int Y = y0 + w_;
        float* outp = g_neg + (size_t)b * OH * OH * 8;
        float me = 3.4e38f, mo = 3.4e38f;
        #pragma unroll
        for (int px = 0; px < 2; px++) {
            float cc[4] = {b0f, b1f, b0f, b1f};
            #pragma unroll
            for (int dy = 0; dy < 2; dy++) {
                int wb = ((((py * 2 + px) * 8 + g) * 2 + dy) * 2) * 4 + tg;
                u32 bh0 = WH[wb], bh1 = WH[wb + 4];
                u32 bl0 = WL[wb], bl1 = WL[wb + 4];
                int base0 = ((r0 + dy) * 18 + g + px) * 4 + tg;
                u32 a0h = XH[base0], a1h = XH[base0 + 32], a2h = XH[base0 + 4], a3h = XH[base0 + 36];
                u32 a0l = XL[base0], a1l = XL[base0 + 32], a2l = XL[base0 + 4], a3l = XL[base0 + 36];
                mma16816(cc, a0h, a1h, a2h, a3h, bh0, bh1);
                mma16816(cc, a0l, a1l, a2l, a3l, bh0, bh1);
                mma16816(cc, a0h, a1h, a2h, a3h, bl0, bl1);
            }
            int X0 = x0 + 2 * g + px;
            int X1 = x0 + 2 * (g + 8) + px;
            *(float2*)&outp[(size_t)(Y * OH + X0) * 8 + 2 * tg] = make_float2(cc[0], cc[1]);
            *(float2*)&outp[(size_t)(Y * OH + X1) * 8 + 2 * tg] = make_float2(cc[2], cc[3]);
            me = fminf(me, fminf(fabsf(cc[0]), fabsf(cc[2])));
            mo = fminf(mo, fminf(fabsf(cc[1]), fabsf(cc[3])));
        }
        #pragma unroll
        for (int off2 = 16; off2 >= 4; off2 >>= 1) {
            me = fminf(me, __shfl_xor_sync(0xFFFFFFFFu, me, off2));
            mo = fminf(mo, __shfl_xor_sync(0xFFFFFFFFu, mo, off2));
        }
        if (lane < 4) {
            atomicMin(&sMin[2 * tg], __float_as_uint(me));
            atomicMin(&sMin[2 * tg + 1], __float_as_uint(mo));
        }
        __syncthreads();
        if (tid < 8) atomicMin(&g_minneg[stage * BATCH * CH + b * CH + tid], sMin[tid]);

    } else {
        // ---- conv5 mma at OH res; tile 32x16; in-block bilinear from lxp ----
        constexpr int LH = 12, LW = 20;
        if (by >= OH / 16) return;
        float* sLx = (float*)sm;                    // 12*20*8 = 1920 f32
        u32* XuH = sm + 1920;                       // 20*36 uint4 = 2880 u32
        u32* XuL = sm + 4800;
        u32* WH = sm + 7680;                        // 864
        u32* WL = sm + 8544;
        float* sB = (float*)(sm + 9408);
        unsigned* sMin = (unsigned*)(sm + 9420);
        int x0 = bx * 32, y0 = by * 16;
        const uint4* w4h = (const uint4*)(g_wmbh + (size_t)((stage * BATCH + b) * 8) * 216);
        const uint4* w4l = (const uint4*)(g_wmbl + (size_t)((stage * BATCH + b) * 8) * 216);
        if (tid < 216) { ((uint4*)WH)[tid] = w4h[tid]; ((uint4*)WL)[tid] = w4l[tid]; }
        if (tid < 8) { sB[tid] = g_bm[(stage * BATCH + b) * CH + tid]; sMin[tid] = 0x7F800000u; }

        int gyLo = (y0 >> 1) - 2;
        int gxLo = ((x0 - 2) >> 1) - 1;
        const float4* lx4 = (const float4*)g_lxp + (size_t)b * H * H * 2;
        for (int j = tid; j < LH * LW; j += 256) {
            int r = j / LW, c = j - LW * r;
            int gy = gyLo + r, gx = gxLo + c;
            float4 v0 = make_float4(0, 0, 0, 0), v1 = make_float4(0, 0, 0, 0);
            if ((unsigned)gy < (unsigned)H && (unsigned)gx < (unsigned)H) {
                v0 = lx4[(gy * H + gx) * 2];
                v1 = lx4[(gy * H + gx) * 2 + 1];
            }
            ((float4*)sLx)[j * 2] = v0;
            ((float4*)sLx)[j * 2 + 1] = v1;
        }
        __syncthreads();
        bf16* xuh = (bf16*)XuH;
        bf16* xul = (bf16*)XuL;
        for (int j = tid; j < 20 * 36; j += 256) {
            int r = j / 36, c = j - 36 * r;
            int Y = y0 - 2 + r, X = x0 - 2 + c;
            if ((unsigned)Y < (unsigned)OH && (unsigned)X < (unsigned)OH) {
                int iy = Y >> 1, ix = X >> 1;
                int yo = (Y & 1) ? min(iy + 1, H - 1) : max(iy - 1, 0);
                int xo = (X & 1) ? min(ix + 1, H - 1) : max(ix - 1, 0);
                int ry = iy - gyLo, ryo = yo - gyLo;
                int cx = ix - gxLo, cxo = xo - gxLo;
                const float4* A  = (const float4*)(sLx + (ry * LW + cx) * 8);
                const float4* Bq = (const float4*)(sLx + (ry * LW + cxo) * 8);
                const float4* Cq = (const float4*)(sLx + (ryo * LW + cx) * 8);
                const float4* D  = (const float4*)(sLx + (ryo * LW + cxo) * 8);
                #pragma unroll
                for (int half = 0; half < 2; half++) {
                    float4 a = A[half], bb = Bq[half], cc2 = Cq[half], d = D[half];
                    float v[4];
                    v[0] = 0.5625f * a.x + 0.1875f * bb.x + 0.1875f * cc2.x + 0.0625f * d.x;
                    v[1] = 0.5625f * a.y + 0.1875f * bb.y + 0.1875f * cc2.y + 0.0625f * d.y;
                    v[2] = 0.5625f * a.z + 0.1875f * bb.z + 0.1875f * cc2.z + 0.0625f * d.z;
                    v[3] = 0.5625f * a.w + 0.1875f * bb.w + 0.1875f * cc2.w + 0.0625f * d.w;
                    #pragma unroll
                    for (int k = 0; k < 4; k++) {
                        bf16 h = __float2bfloat16(v[k]);
                        xuh[j * 8 + half * 4 + k] = h;
                        xul[j * 8 + half * 4 + k] = __float2bfloat16(v[k] - __bfloat162float(h));
                    }
                }
            } else {
                ((uint4*)XuH)[j] = make_uint4(0, 0, 0, 0);
                ((uint4*)XuL)[j] = make_uint4(0, 0, 0, 0);
            }
        }
        __syncthreads();

        u32 baseH = (u32)__cvta_generic_to_shared(XuH);
        u32 baseL = (u32)__cvta_generic_to_shared(XuL);
        u32 lb0 = (u32)((w_ * 36 + pix16) * 16);
        u32 lb1 = (u32)(((w_ + 8) * 36 + pix16) * 16);

        float b0f = sB[2 * tg], b1f = sB[2 * tg + 1];
        float cA0[4] = {b0f, b1f, b0f, b1f}, cA1[4] = {b0f, b1f, b0f, b1f};
        float cB0[4] = {b0f, b1f, b0f, b1f}, cB1[4] = {b0f, b1f, b0f, b1f};
        #pragma unroll
        for (int k = 0; k < 13; k++) {
            const int t0 = 2 * k, t1 = 2 * k + 1;
            const int ky0 = t0 / 5, kx0 = t0 % 5;
            const int ky1 = (t1 < 25) ? t1 / 5 : 0, kx1 = (t1 < 25) ? t1 % 5 : 0;
            u32 bh0 = WH[(g * 27 + t0) * 4 + tg], bh1 = WH[(g * 27 + t1) * 4 + tg];
            u32 bl0 = WL[(g * 27 + t0) * 4 + tg], bl1 = WL[(g * 27 + t1) * 4 + tg];
            const int d0 = (ky0 * 36 + kx0) * 16, d1 = (ky1 * 36 + kx1) * 16;
            u32 dd = (u32)(qsel ? d1 : d0);
            #pragma unroll
            for (int s = 0; s < 2; s++) {
                u32 a0h, a1h, a2h, a3h, a0l, a1l, a2l, a3l;
                ldsm4(a0h, a1h, a2h, a3h, baseH + lb0 + dd + s * 256);
                ldsm4(a0l, a1l, a2l, a3l, baseL + lb0 + dd + s * 256);
                float* cc = s ? cA1 : cA0;
                mma16816(cc, a0h, a1h, a2h, a3h, bh0, bh1);
                mma16816(cc, a0l, a1l, a2l, a3l, bh0, bh1);
                mma16816(cc, a0h, a1h, a2h, a3h, bl0, bl1);
                ldsm4(a0h, a1h, a2h, a3h, baseH + lb1 + dd + s * 256);
                ldsm4(a0l, a1l, a2l, a3l, baseL + lb1 + dd + s * 256);
                float* cd = s ? cB1 : cB0;
                mma16816(cd, a0h, a1h, a2h, a3h, bh0, bh1);
                mma16816(cd, a0l, a1l, a2l, a3l, bh0, bh1);
                mma16816(cd, a0h, a1h, a2h, a3h, bl0, bl1);
            }
        }
        float* mulb = g_mul + (size_t)b * OH * OH * 8;
        float me = 3.4e38f, mo = 3.4e38f;
        #pragma unroll
        for (int rgi = 0; rgi < 2; rgi++) {
            int Y = y0 + w_ + rgi * 8;
            #pragma unroll
            for (int s = 0; s < 2; s++) {
                float* cc = rgi ? (s ? cB1 : cB0) : (s ? cA1 : cA0);
                int X = x0 + s * 16 + g;
                *(float2*)&mulb[(size_t)(Y * OH + X) * 8 + 2 * tg] = make_float2(cc[0], cc[1]);
                *(float2*)&mulb[(size_t)(Y * OH + X + 8) * 8 + 2 * tg] = make_float2(cc[2], cc[3]);
                me = fminf(me, fminf(fabsf(cc[0]), fabsf(cc[2])));
                mo = fminf(mo, fminf(fabsf(cc[1]), fabsf(cc[3])));
            }
        }
        #pragma unroll
        for (int off2 = 16; off2 >= 4; off2 >>= 1) {
            me = fminf(me, __shfl_xor_sync(0xFFFFFFFFu, me, off2));
            mo = fminf(mo, __shfl_xor_sync(0xFFFFFFFFu, mo, off2));
        }
        if (lane < 4) {
            atomicMin(&sMin[2 * tg], __float_as_uint(me));
            atomicMin(&sMin[2 * tg + 1], __float_as_uint(mo));
        }
        __syncthreads();
        if (tid < 8) atomicMin(&g_minmul[stage * BATCH * CH + b * CH + tid], sMin[tid]);
    }
}

// ---------------- combine to pixel-major xph/xpl/lxp (dp shared across even/odd pair) ----------------
template<int H>
__global__ __launch_bounds__(256) void k_combineP(int stage) {
    constexpr int OH = 2 * H;
    int b = blockIdx.y;
    int p = blockIdx.x * 256 + threadIdx.x;
    if (p >= OH * OH) return;
    int lane = threadIdx.x & 31;
    int Y = p / OH, X = p - Y * OH;
    int pp = (Y >> 1) * H + (X >> 1);
    __shared__ float sMn[3 * CH];
    if (threadIdx.x < 3 * CH) {
        int c = threadIdx.x & 7, which = threadIdx.x >> 3;
        const unsigned* src = which == 0 ? g_minpos : (which == 1 ? g_minneg : g_minmul);
        sMn[threadIdx.x] = __uint_as_float(src[stage * BATCH * CH + b * CH + c]);
    }
    __syncthreads();

    float dpv[CH];
    {
        float mydp[CH];
        if ((lane & 1) == 0) {
            const float4* p4 = (const float4*)(g_pos + ((size_t)b * H * H + pp) * 8);
            float4 a0 = p4[0], a1 = p4[1];
            float pv[8] = {a0.x, a0.y, a0.z, a0.w, a1.x, a1.y, a1.z, a1.w};
            #pragma unroll
            for (int c = 0; c < CH; c++) mydp[c] = dln_f(pv[c], sMn[c]);
        } else {
            #pragma unroll
            for (int c = 0; c < CH; c++) mydp[c] = 0.f;
        }
        #pragma unroll
        for (int c = 0; c < CH; c++)
            dpv[c] = __shfl_sync(0xFFFFFFFFu, mydp[c], lane & ~1);
    }

    float ng[CH], ml[CH];
    {
        const float4* n4 = (const float4*)(g_neg + ((size_t)b * OH * OH + p) * 8);
        const float4* m4 = (const float4*)(g_mul + ((size_t)b * OH * OH + p) * 8);
        float4 a0 = n4[0], a1 = n4[1];
        ng[0]=a0.x; ng[1]=a0.y; ng[2]=a0.z; ng[3]=a0.w;
        ng[4]=a1.x; ng[5]=a1.y; ng[6]=a1.z; ng[7]=a1.w;
        a0 = m4[0]; a1 = m4[1];
        ml[0]=a0.x; ml[1]=a0.y; ml[2]=a0.z; ml[3]=a0.w;
        ml[4]=a1.x; ml[5]=a1.y; ml[6]=a1.z; ml[7]=a1.w;
    }

    uint4 hv, lv;
    bf16* hp = (bf16*)&hv;
    bf16* lp = (bf16*)&lv;
    float lx[CH];
    #pragma unroll
    for (int c = 0; c < CH; c++) {
        float xv = (dpv[c] + dln_f(ng[c], sMn[8 + c])) * dln_f(ml[c], sMn[16 + c]);
        bf16 h = __float2bfloat16(xv);
        hp[c] = h;
        lp[c] = __float2bfloat16(xv - __bfloat162float(h));
        lx[c] = __logf(fabsf(xv) + 1.0f);
    }
    size_t base = (size_t)b * OH * OH + p;
    ((uint4*)g_xph)[base] = hv;
    ((uint4*)g_xpl)[base] = lv;
    float4* lxd = (float4*)(g_lxp + base * 8);
    lxd[0] = make_float4(lx[0], lx[1], lx[2], lx[3]);
    lxd[1] = make_float4(lx[4], lx[5], lx[6], lx[7]);
}

// ---------------- final combine + 1x1 conv ----------------
__global__ __launch_bounds__(256) void k_comfinal(float* __restrict__ out) {
    constexpr int H = 128, OH = 256;
    constexpr int stage = 3;
    int b = blockIdx.y;
    int p = blockIdx.x * 256 + threadIdx.x;
    int lane = threadIdx.x & 31;
    int Y = p >> 8, X = p & 255;
    int pp = (Y >> 1) * H + (X >> 1);
    __shared__ float sMn[3 * CH];
    __shared__ float sWo[3 * CH];
    __shared__ float sBo[3];
    if (threadIdx.x < 3 * CH) {
        int c = threadIdx.x & 7, which = threadIdx.x >> 3;
        const unsigned* src = which == 0 ? g_minpos : (which == 1 ? g_minneg : g_minmul);
        sMn[threadIdx.x] = __uint_as_float(src[stage * BATCH * CH + b * CH + c]);
        sWo[threadIdx.x] = g_wo[b * 24 + threadIdx.x];
    }
    if (threadIdx.x >= 32 && threadIdx.x < 35) sBo[threadIdx.x - 32] = g_bo[b * 3 + threadIdx.x - 32];
    __syncthreads();

    float dpv[CH];
    {
        float mydp[CH];
        if ((lane & 1) == 0) {
            const float4* p4 = (const float4*)(g_pos + ((size_t)b * H * H + pp) * 8);
            float4 a0 = p4[0], a1 = p4[1];
            float pv[8] = {a0.x, a0.y, a0.z, a0.w, a1.x, a1.y, a1.z, a1.w};
            #pragma unroll
            for (int c = 0; c < CH; c++) mydp[c] = dln_f(pv[c], sMn[c]);
        } else {
            #pragma unroll
            for (int c = 0; c < CH; c++) mydp[c] = 0.f;
        }
        #pragma unroll
        for (int c = 0; c < CH; c++)
            dpv[c] = __shfl_sync(0xFFFFFFFFu, mydp[c], lane & ~1);
    }

    const float4* n4 = (const float4*)(g_neg + ((size_t)b * OH * OH + p) * 8);
    const float4* m4 = (const float4*)(g_mul + ((size_t)b * OH * OH + p) * 8);
    float ng[8], ml[8];
    float4 a0 = n4[0], a1 = n4[1];
    ng[0]=a0.x; ng[1]=a0.y; ng[2]=a0.z; ng[3]=a0.w; ng[4]=a1.x; ng[5]=a1.y; ng[6]=a1.z; ng[7]=a1.w;
    a0 = m4[0]; a1 = m4[1];
    ml[0]=a0.x; ml[1]=a0.y; ml[2]=a0.z; ml[3]=a0.w; ml[4]=a1.x; ml[5]=a1.y; ml[6]=a1.z; ml[7]=a1.w;

    float acc[3] = {sBo[0], sBo[1], sBo[2]};
    #pragma unroll
    for (int c = 0; c < CH; c++) {
        float xv = (dpv[c] + dln_f(ng[c], sMn[8 + c])) * dln_f(ml[c], sMn[16 + c]);
        #pragma unroll
        for (int o = 0; o < 3; o++) acc[o] += sWo[o * CH + c] * xv;
    }
    #pragma unroll
    for (int o = 0; o < 3; o++)
        out[((size_t)b * 3 + o) * OH * OH + p] = acc[o];
}

// ---------------- launcher ----------------
extern "C" void kernel_launch(void* const* d_in, const int* in_sizes, int n_in,
                              void* d_out, int out_size) {
    const int*   ids = (const int*)  d_in[0];
    const float* cc  = (const float*)d_in[1];
    const float* lat = (const float*)d_in[2];
    const float* Wr = (const float*)d_in[3];
    const float* Ur = (const float*)d_in[4];
    const float* Vr = (const float*)d_in[5];
    const float* Br = (const float*)d_in[6];
    const float* Wt = (const float*)d_in[7];
    const float* Ut = (const float*)d_in[8];
    const float* Vt = (const float*)d_in[9];
    const float* Bt = (const float*)d_in[10];
    const float* Wm = (const float*)d_in[11];
    const float* Um = (const float*)d_in[12];
    const float* Vm = (const float*)d_in[13];
    const float* Bm = (const float*)d_in[14];
    const float* Wo = (const float*)d_in[15];
    const float* Uo = (const float*)d_in[16];
    const float* Vo = (const float*)d_in[17];
    const float* Bo = (const float*)d_in[18];

    k_gather<<<64, 256>>>(ids, cc, lat);
    k_weights<<<dim3(13, 64), 128>>>(Wr, Ur, Vr, Br, Wt, Ut, Vt, Bt,
                                     Wm, Um, Vm, Bm, Wo, Uo, Vo, Bo);
    k_mininit<<<(NSTAGE * BATCH * CH + 255) / 256, 256>>>();

    // stage 0: H=16
    k_mma<16><<<dim3(1, 4, 192), 256>>>(0);
    k_combineP<16><<<dim3(4, 64), 256>>>(0);
    // stage 1: H=32
    k_mma<32><<<dim3(2, 8, 192), 256>>>(1);
    k_combineP<32><<<dim3(16, 64), 256>>>(1);
    // stage 2: H=64
    k_mma<64><<<dim3(4, 16, 192), 256>>>(2);
    k_combineP<64><<<dim3(64, 64), 256>>>(2);
    // stage 3: H=128
    k_mma<128><<<dim3(8, 32, 192), 256>>>(3);
    k_comfinal<<<dim3(256, 64), 256>>>((float*)d_out);
}

// round 14
// speedup vs baseline: 2.6267x; 1.0594x over previous
#include <cuda_runtime.h>
#include <cuda_bf16.h>
#include <cstdint>

#define BATCH 64
#define CH 8
#define NSTAGE 4

typedef uint32_t u32;
typedef __nv_bfloat16 bf16;

// ---------------- device scratch ----------------
__device__ float g_ctx[BATCH*32];
__device__ float g_wr[NSTAGE*BATCH*CH*CH*9];
__device__ float g_wt[NSTAGE*BATCH*CH*CH*16];
__device__ float g_wm[NSTAGE*BATCH*CH*CH*25];
__device__ __align__(16) bf16 g_wmbh[NSTAGE*BATCH*8*27*8];
__device__ __align__(16) bf16 g_wmbl[NSTAGE*BATCH*8*27*8];
__device__ __align__(16) bf16 g_wrbh[NSTAGE*BATCH*8*10*8];
__device__ __align__(16) bf16 g_wrbl[NSTAGE*BATCH*8*10*8];
__device__ __align__(16) bf16 g_wtbh[NSTAGE*BATCH*1024];
__device__ __align__(16) bf16 g_wtbl[NSTAGE*BATCH*1024];
__device__ float g_wo[BATCH*3*CH];
__device__ float g_br[NSTAGE*BATCH*CH];
__device__ float g_bt[NSTAGE*BATCH*CH];
__device__ float g_bm[NSTAGE*BATCH*CH];
__device__ float g_bo[BATCH*3];
__device__ __align__(16) float g_pos[BATCH*128*128*CH];   // pixel-major
__device__ __align__(16) float g_neg[BATCH*256*256*CH];
__device__ __align__(16) float g_mul[BATCH*256*256*CH];
__device__ __align__(16) bf16 g_xph[BATCH*128*128*CH];
__device__ __align__(16) bf16 g_xpl[BATCH*128*128*CH];
__device__ __align__(16) float g_lxp[BATCH*128*128*CH];
__device__ unsigned g_minpos[NSTAGE*BATCH*CH];
__device__ unsigned g_minneg[NSTAGE*BATCH*CH];
__device__ unsigned g_minmul[NSTAGE*BATCH*CH];

__device__ __forceinline__ float dln_f(float v, float mn) {
    float s = (v > 0.0f) ? 1.0f : -1.0f;
    float a = fabsf(v) - mn;
    return s * __logf(__logf(a + 2.718281828459045f) + 0.01f);
}

__device__ __forceinline__ void mma16816(float* c, u32 a0, u32 a1, u32 a2, u32 a3,
                                         u32 b0, u32 b1) {
    asm("mma.sync.aligned.m16n8k16.row.col.f32.bf16.bf16.f32 "
        "{%0,%1,%2,%3},{%4,%5,%6,%7},{%8,%9},{%0,%1,%2,%3};"
        : "+f"(c[0]), "+f"(c[1]), "+f"(c[2]), "+f"(c[3])
        : "r"(a0), "r"(a1), "r"(a2), "r"(a3), "r"(b0), "r"(b1));
}

__device__ __forceinline__ void ldsm4(u32& r0, u32& r1, u32& r2, u32& r3, u32 addr) {
    asm volatile("ldmatrix.sync.aligned.m8n8.x4.shared.b16 {%0,%1,%2,%3},[%4];"
                 : "=r"(r0), "=r"(r1), "=r"(r2), "=r"(r3) : "r"(addr));
}

// ---------------- gather (+ min init) ----------------
__global__ __launch_bounds__(256) void k_gather(const int* __restrict__ ids,
                                                const float* __restrict__ cc,
                                                const float* __restrict__ lat) {
    int t = blockIdx.x * 256 + threadIdx.x;
    if (t < NSTAGE * BATCH * CH) {
        g_minpos[t] = 0x7F800000u; g_minneg[t] = 0x7F800000u; g_minmul[t] = 0x7F800000u;
    }
    if (t < BATCH * 32) g_ctx[t] = cc[ids[t >> 5] * 32 + (t & 31)];
    int b = t >> 8, p = t & 255;
    const float* lb = lat + (size_t)ids[b] * (CH * 256);
    uint4 hv, lv;
    bf16* hp = (bf16*)&hv;
    bf16* lp = (bf16*)&lv;
    float lx[CH];
    #pragma unroll
    for (int c = 0; c < CH; c++) {
        float v = lb[c * 256 + p];
        bf16 h = __float2bfloat16(v);
        hp[c] = h;
        lp[c] = __float2bfloat16(v - __bfloat162float(h));
        lx[c] = __logf(fabsf(v) + 1.0f);
    }
    size_t base = (size_t)b * 256 + p;
    ((uint4*)g_xph)[base] = hv;
    ((uint4*)g_xpl)[base] = lv;
    float4* lxd = (float4*)(g_lxp + base * 8);
    lxd[0] = make_float4(lx[0], lx[1], lx[2], lx[3]);
    lxd[1] = make_float4(lx[4], lx[5], lx[6], lx[7]);
}

// ---------------- dynamic weights ----------------
__global__ void k_weights(
    const float* __restrict__ Wr, const float* __restrict__ Ur, const float* __restrict__ Vr, const float* __restrict__ Br,
    const float* __restrict__ Wt, const float* __restrict__ Ut, const float* __restrict__ Vt, const float* __restrict__ Bt,
    const float* __restrict__ Wm, const float* __restrict__ Um, const float* __restrict__ Vm, const float* __restrict__ Bm,
    const float* __restrict__ Wo, const float* __restrict__ Uo, const float* __restrict__ Vo, const float* __restrict__ Bo)
{
    int inst = blockIdx.x, b = blockIdx.y, tid = threadIdx.x;
    __shared__ float sctx[32];
    __shared__ float su[128];
    __shared__ float sv[3200];
    if (tid < 32) sctx[tid] = g_ctx[b * 32 + tid];
    __syncthreads();

    int O, KK, type = -1, stage = 0;
    const float *U, *V, *W, *Bb;
    float *gw, *gb;
    if (inst < 12) {
        type = inst >> 2; stage = inst & 3;
        O = CH;
        if (type == 0)      { KK = 9;  U = Ur; V = Vr; W = Wr; Bb = Br; gw = g_wr; gb = g_br; }
        else if (type == 1) { KK = 16; U = Ut; V = Vt; W = Wt; Bb = Bt; gw = g_wt; gb = g_bt; }
        else                { KK = 25; U = Um; V = Vm; W = Wm; Bb = Bm; gw = g_wm; gb = g_bm; }
        int uL = 16 * O, vL = 16 * CH * KK;
        U += (size_t)stage * 32 * uL; V += (size_t)stage * 32 * vL;
        W += (size_t)stage * O * CH * KK; Bb += (size_t)stage * 32 * O;
        gw += (size_t)(stage * BATCH + b) * O * CH * KK;
        gb += (size_t)(stage * BATCH + b) * O;
    } else {
        O = 3; KK = 1;
        U = Uo; V = Vo; W = Wo; Bb = Bo;
        gw = g_wo + b * 3 * CH; gb = g_bo + b * 3;
    }
    int uLen = 16 * O, vLen = 16 * CH * KK, IKK = CH * KK, wN = O * IKK;
    int sb = stage * BATCH + b;

    for (int j = tid; j < uLen; j += blockDim.x) {
        float s = 0.f;
        #pragma unroll
        for (int l = 0; l < 32; l++) s += sctx[l] * U[l * uLen + j];
        su[j] = s;
    }
    for (int j = tid; j < vLen; j += blockDim.x) {
        float s = 0.f;
        #pragma unroll
        for (int l = 0; l < 32; l++) s += sctx[l] * V[l * vLen + j];
        sv[j] = s;
    }
    __syncthreads();

    for (int widx = tid; widx < wN; widx += blockDim.x) {
        int o = widx / IKK, k = widx - o * IKK;
        float m = 0.f;
        #pragma unroll
        for (int r = 0; r < 16; r++) m += su[r * O + o] * sv[r * IKK + k];
        float w = W[widx] * (1.0f + m + 1e-3f);
        gw[widx] = w;
        if (type == 2) {
            int i = k / 25, t = k - i * 25;
            size_t d = (size_t)(sb * 8 + o) * 216 + t * 8 + i;
            bf16 h = __float2bfloat16(w);
            g_wmbh[d] = h;
            g_wmbl[d] = __float2bfloat16(w - __bfloat162float(h));
        } else if (type == 0) {
            int i = k / 9, t = k - i * 9;
            size_t d = (size_t)sb * 640 + (o * 10 + t) * 8 + i;
            bf16 h = __float2bfloat16(w);
            g_wrbh[d] = h;
            g_wrbl[d] = __float2bfloat16(w - __bfloat162float(h));
        } else if (type == 1) {
            int i = k / 16, t = k - i * 16;
            int ky = t >> 2, kx = t & 3;
            int py = (3 - ky) & 1, dy = (3 - ky) >> 1;
            int px = (3 - kx) & 1, dx = (3 - kx) >> 1;
            float wn = -w;
            size_t d = (size_t)sb * 1024 +
                       ((((size_t)(py * 2 + px) * 8 + o) * 2 + dy) * 2 + dx) * 8 + i;
            bf16 h = __float2bfloat16(wn);
            g_wtbh[d] = h;
            g_wtbl[d] = __float2bfloat16(wn - __bfloat162float(h));
        }
    }
    if (type == 2 && tid < 128) {
        int o = tid >> 4, t = 25 + ((tid >> 3) & 1), i = tid & 7;
        size_t d = (size_t)(sb * 8 + o) * 216 + t * 8 + i;
        g_wmbh[d] = __float2bfloat16(0.f);
        g_wmbl[d] = __float2bfloat16(0.f);
    }
    if (type == 0 && tid < 64) {
        int o = tid >> 3, i = tid & 7;
        size_t d = (size_t)sb * 640 + (o * 10 + 9) * 8 + i;
        g_wrbh[d] = __float2bfloat16(0.f);
        g_wrbl[d] = __float2bfloat16(0.f);
    }
    if (tid < O) {
        float s = 0.f;
        #pragma unroll
        for (int l = 0; l < 32; l++) s += sctx[l] * Bb[l * O + tid];
        gb[tid] = s;
    }
}

// ---------------- mma superkernel; TH=16 tiles at H>=64, TH=8 below ----------------
template<int H>
__global__ __launch_bounds__(256) void k_mma(int stage) {
    constexpr int OH = 2 * H;
    constexpr bool TH16 = (H >= 64);
    constexpr int TH = TH16 ? 16 : 8;
    constexpr int RG = TH / 8;
    constexpr int SMSZ = TH16 ? 9440 : 6500;
    __shared__ __align__(16) u32 sm[SMSZ];
    int role = blockIdx.z >> 6;
    int b = blockIdx.z & 63;
    int tid = threadIdx.x;
    int bx = blockIdx.x, by = blockIdx.y;
    int w_ = tid >> 5, lane = tid & 31, g = lane >> 2, tg = lane & 3;
    int pix16 = (lane & 7) + ((lane >> 3) & 1) * 8;
    int qsel = lane >> 4;

    if (role == 0) {
        // ---- conv3 mma at H res; tile 32xTH ----
        constexpr int BX3 = (H >= 32) ? H / 32 : 1;
        constexpr int SQ3 = (H >= 32) ? 2 : 1;
        constexpr int IH = TH + 2;
        constexpr int XSZ = IH * 34 * 4;
        if (bx >= BX3 || by >= H / TH) return;
        u32* XH = sm;
        u32* XL = sm + XSZ;
        u32* WH = sm + 2 * XSZ;
        u32* WL = WH + 320;
        float* sB = (float*)(WL + 320);
        unsigned* sMin = (unsigned*)(sB + 8);
        int x0 = bx * 32, y0 = by * TH;
        const uint4* w4h = (const uint4*)(g_wrbh + (size_t)(stage * BATCH + b) * 640);
        const uint4* w4l = (const uint4*)(g_wrbl + (size_t)(stage * BATCH + b) * 640);
        if (tid < 80) { ((uint4*)WH)[tid] = w4h[tid]; ((uint4*)WL)[tid] = w4l[tid]; }
        if (tid < 8) { sB[tid] = g_br[(stage * BATCH + b) * CH + tid]; sMin[tid] = 0x7F800000u; }
        const uint4* xh4 = (const uint4*)g_xph + (size_t)b * H * H;
        const uint4* xl4 = (const uint4*)g_xpl + (size_t)b * H * H;
        for (int j = tid; j < IH * 34; j += 256) {
            int r = j / 34, c = j - 34 * r;
            int gy = y0 - 1 + r, gx = x0 - 1 + c;
            uint4 v = make_uint4(0, 0, 0, 0), w2 = make_uint4(0, 0, 0, 0);
            if ((unsigned)gy < (unsigned)H && (unsigned)gx < (unsigned)H) {
                v = xh4[gy * H + gx]; w2 = xl4[gy * H + gx];
            }
            ((uint4*)XH)[j] = v; ((uint4*)XL)[j] = w2;
        }
        __syncthreads();

        u32 baseH = (u32)__cvta_generic_to_shared(XH);
        u32 baseL = (u32)__cvta_generic_to_shared(XL);
        u32 lb[RG];
        #pragma unroll
        for (int rgi = 0; rgi < RG; rgi++)
            lb[rgi] = (u32)(((w_ + rgi * 8) * 34 + pix16) * 16);

        float b0f = sB[2 * tg], b1f = sB[2 * tg + 1];
        float cacc[RG][2][4];
        #pragma unroll
        for (int rgi = 0; rgi < RG; rgi++)
            #pragma unroll
            for (int s = 0; s < 2; s++) {
                cacc[rgi][s][0] = b0f; cacc[rgi][s][1] = b1f;
                cacc[rgi][s][2] = b0f; cacc[rgi][s][3] = b1f;
            }
        #pragma unroll
        for (int k = 0; k < 5; k++) {
            const int t0 = 2 * k, t1 = 2 * k + 1;
            const int t1c = (t1 < 9) ? t1 : 0;
            const int ky0 = t0 / 3, kx0 = t0 % 3;
            const int ky1 = t1c / 3, kx1 = t1c % 3;
            u32 bh0 = WH[(g * 10 + t0) * 4 + tg], bh1 = WH[(g * 10 + t1) * 4 + tg];
            u32 bl0 = WL[(g * 10 + t0) * 4 + tg], bl1 = WL[(g * 10 + t1) * 4 + tg];
            const int d0 = (ky0 * 34 + kx0) * 16, d1 = (ky1 * 34 + kx1) * 16;
            u32 dd = (u32)(qsel ? d1 : d0);
            #pragma unroll
            for (int rgi = 0; rgi < RG; rgi++) {
                #pragma unroll
                for (int s = 0; s < SQ3; s++) {
                    u32 a0h, a1h, a2h, a3h, a0l, a1l, a2l, a3l;
                    ldsm4(a0h, a1h, a2h, a3h, baseH + lb[rgi] + dd + s * 256);
                    ldsm4(a0l, a1l, a2l, a3l, baseL + lb[rgi] + dd + s * 256);
                    float* cc = cacc[rgi][s];
                    mma16816(cc, a0h, a1h, a2h, a3h, bh0, bh1);
                    mma16816(cc, a0l, a1l, a2l, a3l, bh0, bh1);
                    mma16816(cc, a0h, a1h, a2h, a3h, bl0, bl1);
                }
            }
        }
        float* outp = g_pos + (size_t)b * H * H * 8;
        float me = 3.4e38f, mo = 3.4e38f;
        #pragma unroll
        for (int rgi = 0; rgi < RG; rgi++) {
            int Y = y0 + w_ + rgi * 8;
            #pragma unroll
            for (int s = 0; s < SQ3; s++) {
                float* cc = cacc[rgi][s];
                int X = x0 + s * 16 + g;
                *(float2*)&outp[(size_t)(Y * H + X) * 8 + 2 * tg] = make_float2(cc[0], cc[1]);
                *(float2*)&outp[(size_t)(Y * H + X + 8) * 8 + 2 * tg] = make_float2(cc[2], cc[3]);
                me = fminf(me, fminf(fabsf(cc[0]), fabsf(cc[2])));
                mo = fminf(mo, fminf(fabsf(cc[1]), fabsf(cc[3])));
            }
        }
        #pragma unroll
        for (int off2 = 16; off2 >= 4; off2 >>= 1) {
            me = fminf(me, __shfl_xor_sync(0xFFFFFFFFu, me, off2));
            mo = fminf(mo, __shfl_xor_sync(0xFFFFFFFFu, mo, off2));
        }
        if (lane < 4) {
            atomicMin(&sMin[2 * tg], __float_as_uint(me));
            atomicMin(&sMin[2 * tg + 1], __float_as_uint(mo));
        }
        __syncthreads();
        if (tid < 8) atomicMin(&g_minpos[stage * BATCH * CH + b * CH + tid], sMin[tid]);

    } else if (role == 1) {
        // ---- convT mma at OH res; RGT rows per warp ----
        constexpr int RGT = RG;
        constexpr int IHT = TH16 ? 10 : 6;
        constexpr int XTSZ = IHT * 18 * 4;
        u32* XH = sm;
        u32* XL = sm + XTSZ;
        u32* WH = sm + 2 * XTSZ;
        u32* WL = WH + 512;
        float* sB = (float*)(WL + 512);
        unsigned* sMin = (unsigned*)(sB + 8);
        int x0 = bx * 32, y0 = by * (8 * RGT);
        const uint4* w4h = (const uint4*)(g_wtbh + (size_t)(stage * BATCH + b) * 1024);
        const uint4* w4l = (const uint4*)(g_wtbl + (size_t)(stage * BATCH + b) * 1024);
        if (tid < 128) { ((uint4*)WH)[tid] = w4h[tid]; ((uint4*)WL)[tid] = w4l[tid]; }
        if (tid < 8) { sB[tid] = g_bt[(stage * BATCH + b) * CH + tid]; sMin[tid] = 0x7F800000u; }
        int iy0 = y0 / 2 - 1, ix0 = x0 / 2 - 1;
        const uint4* xh4 = (const uint4*)g_xph + (size_t)b * H * H;
        const uint4* xl4 = (const uint4*)g_xpl + (size_t)b * H * H;
        for (int j = tid; j < IHT * 18; j += 256) {
            int r = j / 18, c = j - 18 * r;
            int gy = iy0 + r, gx = ix0 + c;
            uint4 v = make_uint4(0, 0, 0, 0), w2 = make_uint4(0, 0, 0, 0);
            if ((unsigned)gy < (unsigned)H && (unsigned)gx < (unsigned)H) {
                v = xh4[gy * H + gx]; w2 = xl4[gy * H + gx];
            }
            ((uint4*)XH)[j] = v; ((uint4*)XL)[j] = w2;
        }
        __syncthreads();

        int py = w_ & 1;
        int r0b = (w_ >> 1) + py;
        float b0f = sB[2 * tg], b1f = sB[2 * tg + 1];
        float* outp = g_neg + (size_t)b * OH * OH * 8;
        float me = 3.4e38f, mo = 3.4e38f;
        #pragma unroll
        for (int rgi = 0; rgi < RGT; rgi++) {
            int r0 = r0b + rgi * 4;
            int Y = y0 + w_ + rgi * 8;
            #pragma unroll
            for (int px = 0; px < 2; px++) {
                float cc[4] = {b0f, b1f, b0f, b1f};
                #pragma unroll
                for (int dy = 0; dy < 2; dy++) {
                    int wb = ((((py * 2 + px) * 8 + g) * 2 + dy) * 2) * 4 + tg;
                    u32 bh0 = WH[wb], bh1 = WH[wb + 4];
                    u32 bl0 = WL[wb], bl1 = WL[wb + 4];
                    int base0 = ((r0 + dy) * 18 + g + px) * 4 + tg;
                    u32 a0h = XH[base0], a1h = XH[base0 + 32], a2h = XH[base0 + 4], a3h = XH[base0 + 36];
                    u32 a0l = XL[base0], a1l = XL[base0 + 32], a2l = XL[base0 + 4], a3l = XL[base0 + 36];
                    mma16816(cc, a0h, a1h, a2h, a3h, bh0, bh1);
                    mma16816(cc, a0l, a1l, a2l, a3l, bh0, bh1);
                    mma16816(cc, a0h, a1h, a2h, a3h, bl0, bl1);
                }
                int X0 = x0 + 2 * g + px;
                int X1 = x0 + 2 * (g + 8) + px;
                *(float2*)&outp[(size_t)(Y * OH + X0) * 8 + 2 * tg] = make_float2(cc[0], cc[1]);
                *(float2*)&outp[(size_t)(Y * OH + X1) * 8 + 2 * tg] = make_float2(cc[2], cc[3]);
                me = fminf(me, fminf(fabsf(cc[0]), fabsf(cc[2])));
                mo = fminf(mo, fminf(fabsf(cc[1]), fabsf(cc[3])));
            }
        }
        #pragma unroll
        for (int off2 = 16; off2 >= 4; off2 >>= 1) {
            me = fminf(me, __shfl_xor_sync(0xFFFFFFFFu, me, off2));
            mo = fminf(mo, __shfl_xor_sync(0xFFFFFFFFu, mo, off2));
        }
        if (lane < 4) {
            atomicMin(&sMin[2 * tg], __float_as_uint(me));
            atomicMin(&sMin[2 * tg + 1], __float_as_uint(mo));
        }
        __syncthreads();
        if (tid < 8) atomicMin(&g_minneg[stage * BATCH * CH + b * CH + tid], sMin[tid]);

    } else {
        // ---- conv5 mma at OH res; tile 32xTH; in-block bilinear from lxp ----
        constexpr int LH = TH16 ? 12 : 8, LW = 20;
        constexpr int XR = TH + 4;
        constexpr int LSZ = LH * LW * 8;       // f32 count
        constexpr int XSZ = XR * 36 * 4;       // u32 per buffer
        float* sLx = (float*)sm;
        u32* XuH = sm + LSZ;
        u32* XuL = XuH + XSZ;
        u32* WH = XuL + XSZ;
        u32* WL = WH + 864;
        float* sB = (float*)(WL + 864);
        unsigned* sMin = (unsigned*)(sB + 8);
        int x0 = bx * 32, y0 = by * TH;
        const uint4* w4h = (const uint4*)(g_wmbh + (size_t)((stage * BATCH + b) * 8) * 216);
        const uint4* w4l = (const uint4*)(g_wmbl + (size_t)((stage * BATCH + b) * 8) * 216);
        if (tid < 216) { ((uint4*)WH)[tid] = w4h[tid]; ((uint4*)WL)[tid] = w4l[tid]; }
        if (tid < 8) { sB[tid] = g_bm[(stage * BATCH + b) * CH + tid]; sMin[tid] = 0x7F800000u; }

        int gyLo = (y0 >> 1) - 2;
        int gxLo = ((x0 - 2) >> 1) - 1;
        const float4* lx4 = (const float4*)g_lxp + (size_t)b * H * H * 2;
        for (int j = tid; j < LH * LW; j += 256) {
            int r = j / LW, c = j - LW * r;
            int gy = gyLo + r, gx = gxLo + c;
            float4 v0 = make_float4(0, 0, 0, 0), v1 = make_float4(0, 0, 0, 0);
            if ((unsigned)gy < (unsigned)H && (unsigned)gx < (unsigned)H) {
                v0 = lx4[(gy * H + gx) * 2];
                v1 = lx4[(gy * H + gx) * 2 + 1];
            }
            ((float4*)sLx)[j * 2] = v0;
            ((float4*)sLx)[j * 2 + 1] = v1;
        }
        __syncthreads();
        bf16* xuh = (bf16*)XuH;
        bf16* xul = (bf16*)XuL;
        for (int j = tid; j < XR * 36; j += 256) {
            int r = j / 36, c = j - 36 * r;
            int Y = y0 - 2 + r, X = x0 - 2 + c;
            if ((unsigned)Y < (unsigned)OH && (unsigned)X < (unsigned)OH) {
                int iy = Y >> 1, ix = X >> 1;
                int yo = (Y & 1) ? min(iy + 1, H - 1) : max(iy - 1, 0);
                int xo = (X & 1) ? min(ix + 1, H - 1) : max(ix - 1, 0);
                int ry = iy - gyLo, ryo = yo - gyLo;
                int cx = ix - gxLo, cxo = xo - gxLo;
                const float4* A  = (const float4*)(sLx + (ry * LW + cx) * 8);
                const float4* Bq = (const float4*)(sLx + (ry * LW + cxo) * 8);
                const float4* Cq = (const float4*)(sLx + (ryo * LW + cx) * 8);
                const float4* D  = (const float4*)(sLx + (ryo * LW + cxo) * 8);
                #pragma unroll
                for (int half = 0; half < 2; half++) {
                    float4 a = A[half], bb = Bq[half], cc2 = Cq[half], d = D[half];
                    float v[4];
                    v[0] = 0.5625f * a.x + 0.1875f * bb.x + 0.1875f * cc2.x + 0.0625f * d.x;
                    v[1] = 0.5625f * a.y + 0.1875f * bb.y + 0.1875f * cc2.y + 0.0625f * d.y;
                    v[2] = 0.5625f * a.z + 0.1875f * bb.z + 0.1875f * cc2.z + 0.0625f * d.z;
                    v[3] = 0.5625f * a.w + 0.1875f * bb.w + 0.1875f * cc2.w + 0.0625f * d.w;
                    #pragma unroll
                    for (int k = 0; k < 4; k++) {
                        bf16 h = __float2bfloat16(v[k]);
                        xuh[j * 8 + half * 4 + k] = h;
                        xul[j * 8 + half * 4 + k] = __float2bfloat16(v[k] - __bfloat162float(h));
                    }
                }
            } else {
                ((uint4*)XuH)[j] = make_uint4(0, 0, 0, 0);
                ((uint4*)XuL)[j] = make_uint4(0, 0, 0, 0);
            }
        }
        __syncthreads();

        u32 baseH = (u32)__cvta_generic_to_shared(XuH);
        u32 baseL = (u32)__cvta_generic_to_shared(XuL);
        u32 lb[RG];
        #pragma unroll
        for (int rgi = 0; rgi < RG; rgi++)
            lb[rgi] = (u32)(((w_ + rgi * 8) * 36 + pix16) * 16);

        float b0f = sB[2 * tg], b1f = sB[2 * tg + 1];
        float cacc[RG][2][4];
        #pragma unroll
        for (int rgi = 0; rgi < RG; rgi++)
            #pragma unroll
            for (int s = 0; s < 2; s++) {
                cacc[rgi][s][0] = b0f; cacc[rgi][s][1] = b1f;
                cacc[rgi][s][2] = b0f; cacc[rgi][s][3] = b1f;
            }
        #pragma unroll
        for (int k = 0; k < 13; k++) {
            const int t0 = 2 * k, t1 = 2 * k + 1;
            const int ky0 = t0 / 5, kx0 = t0 % 5;
            const int ky1 = (t1 < 25) ? t1 / 5 : 0, kx1 = (t1 < 25) ? t1 % 5 : 0;
            u32 bh0 = WH[(g * 27 + t0) * 4 + tg], bh1 = WH[(g * 27 + t1) * 4 + tg];
            u32 bl0 = WL[(g * 27 + t0) * 4 + tg], bl1 = WL[(g * 27 + t1) * 4 + tg];
            const int d0 = (ky0 * 36 + kx0) * 16, d1 = (ky1 * 36 + kx1) * 16;
            u32 dd = (u32)(qsel ? d1 : d0);
            #pragma unroll
            for (int rgi = 0; rgi < RG; rgi++) {
                #pragma unroll
                for (int s = 0; s < 2; s++) {
                    u32 a0h, a1h, a2h, a3h, a0l, a1l, a2l, a3l;
                    ldsm4(a0h, a1h, a2h, a3h, baseH + lb[rgi] + dd + s * 256);
                    ldsm4(a0l, a1l, a2l, a3l, baseL + lb[rgi] + dd + s * 256);
                    float* cc = cacc[rgi][s];
                    mma16816(cc, a0h, a1h, a2h, a3h, bh0, bh1);
                    mma16816(cc, a0l, a1l, a2l, a3l, bh0, bh1);
                    mma16816(cc, a0h, a1h, a2h, a3h, bl0, bl1);
                }
            }
        }
        float* mulb = g_mul + (size_t)b * OH * OH * 8;
        float me = 3.4e38f, mo = 3.4e38f;
        #pragma unroll
        for (int rgi = 0; rgi < RG; rgi++) {
            int Y = y0 + w_ + rgi * 8;
            #pragma unroll
            for (int s = 0; s < 2; s++) {
                float* cc = cacc[rgi][s];
                int X = x0 + s * 16 + g;
                *(float2*)&mulb[(size_t)(Y * OH + X) * 8 + 2 * tg] = make_float2(cc[0], cc[1]);
                *(float2*)&mulb[(size_t)(Y * OH + X + 8) * 8 + 2 * tg] = make_float2(cc[2], cc[3]);
                me = fminf(me, fminf(fabsf(cc[0]), fabsf(cc[2])));
                mo = fminf(mo, fminf(fabsf(cc[1]), fabsf(cc[3])));
            }
        }
        #pragma unroll
        for (int off2 = 16; off2 >= 4; off2 >>= 1) {
            me = fminf(me, __shfl_xor_sync(0xFFFFFFFFu, me, off2));
            mo = fminf(mo, __shfl_xor_sync(0xFFFFFFFFu, mo, off2));
        }
        if (lane < 4) {
            atomicMin(&sMin[2 * tg], __float_as_uint(me));
            atomicMin(&sMin[2 * tg + 1], __float_as_uint(mo));
        }
        __syncthreads();
        if (tid < 8) atomicMin(&g_minmul[stage * BATCH * CH + b * CH + tid], sMin[tid]);
    }
}

// ---------------- combine to pixel-major xph/xpl/lxp ----------------
template<int H>
__global__ __launch_bounds__(256) void k_combineP(int stage) {
    constexpr int OH = 2 * H;
    int b = blockIdx.y;
    int p = blockIdx.x * 256 + threadIdx.x;
    if (p >= OH * OH) return;
    int lane = threadIdx.x & 31;
    int Y = p / OH, X = p - Y * OH;
    int pp = (Y >> 1) * H + (X >> 1);
    __shared__ float sMn[3 * CH];
    if (threadIdx.x < 3 * CH) {
        int c = threadIdx.x & 7, which = threadIdx.x >> 3;
        const unsigned* src = which == 0 ? g_minpos : (which == 1 ? g_minneg : g_minmul);
        sMn[threadIdx.x] = __uint_as_float(src[stage * BATCH * CH + b * CH + c]);
    }
    __syncthreads();

    float dpv[CH];
    {
        float mydp[CH];
        if ((lane & 1) == 0) {
            const float4* p4 = (const float4*)(g_pos + ((size_t)b * H * H + pp) * 8);
            float4 a0 = p4[0], a1 = p4[1];
            float pv[8] = {a0.x, a0.y, a0.z, a0.w, a1.x, a1.y, a1.z, a1.w};
            #pragma unroll
            for (int c = 0; c < CH; c++) mydp[c] = dln_f(pv[c], sMn[c]);
        } else {
            #pragma unroll
            for (int c = 0; c < CH; c++) mydp[c] = 0.f;
        }
        #pragma unroll
        for (int c = 0; c < CH; c++)
            dpv[c] = __shfl_sync(0xFFFFFFFFu, mydp[c], lane & ~1);
    }

    float ng[CH], ml[CH];
    {
        const float4* n4 = (const float4*)(g_neg + ((size_t)b * OH * OH + p) * 8);
        const float4* m4 = (const float4*)(g_mul + ((size_t)b * OH * OH + p) * 8);
        float4 a0 = n4[0], a1 = n4[1];
        ng[0]=a0.x; ng[1]=a0.y; ng[2]=a0.z; ng[3]=a0.w;
        ng[4]=a1.x; ng[5]=a1.y; ng[6]=a1.z; ng[7]=a1.w;
        a0 = m4[0]; a1 = m4[1];
        ml[0]=a0.x; ml[1]=a0.y; ml[2]=a0.z; ml[3]=a0.w;
        ml[4]=a1.x; ml[5]=a1.y; ml[6]=a1.z; ml[7]=a1.w;
    }

    uint4 hv, lv;
    bf16* hp = (bf16*)&hv;
    bf16* lp = (bf16*)&lv;
    float lx[CH];
    #pragma unroll
    for (int c = 0; c < CH; c++) {
        float xv = (dpv[c] + dln_f(ng[c], sMn[8 + c])) * dln_f(ml[c], sMn[16 + c]);
        bf16 h = __float2bfloat16(xv);
        hp[c] = h;
        lp[c] = __float2bfloat16(xv - __bfloat162float(h));
        lx[c] = __logf(fabsf(xv) + 1.0f);
    }
    size_t base = (size_t)b * OH * OH + p;
    ((uint4*)g_xph)[base] = hv;
    ((uint4*)g_xpl)[base] = lv;
    float4* lxd = (float4*)(g_lxp + base * 8);
    lxd[0] = make_float4(lx[0], lx[1], lx[2], lx[3]);
    lxd[1] = make_float4(lx[4], lx[5], lx[6], lx[7]);
}

// ---------------- final combine + 1x1 conv ----------------
__global__ __launch_bounds__(256) void k_comfinal(float* __restrict__ out) {
    constexpr int H = 128, OH = 256;
    constexpr int stage = 3;
    int b = blockIdx.y;
    int p = blockIdx.x * 256 + threadIdx.x;
    int lane = threadIdx.x & 31;
    int Y = p >> 8, X = p & 255;
    int pp = (Y >> 1) * H + (X >> 1);
    __shared__ float sMn[3 * CH];
    __shared__ float sWo[3 * CH];
    __shared__ float sBo[3];
    if (threadIdx.x < 3 * CH) {
        int c = threadIdx.x & 7, which = threadIdx.x >> 3;
        const unsigned* src = which == 0 ? g_minpos : (which == 1 ? g_minneg : g_minmul);
        sMn[threadIdx.x] = __uint_as_float(src[stage * BATCH * CH + b * CH + c]);
        sWo[threadIdx.x] = g_wo[b * 24 + threadIdx.x];
    }
    if (threadIdx.x >= 32 && threadIdx.x < 35) sBo[threadIdx.x - 32] = g_bo[b * 3 + threadIdx.x - 32];
    __syncthreads();

    float dpv[CH];
    {
        float mydp[CH];
        if ((lane & 1) == 0) {
            const float4* p4 = (const float4*)(g_pos + ((size_t)b * H * H + pp) * 8);
            float4 a0 = p4[0], a1 = p4[1];
            float pv[8] = {a0.x, a0.y, a0.z, a0.w, a1.x, a1.y, a1.z, a1.w};
            #pragma unroll
            for (int c = 0; c < CH; c++) mydp[c] = dln_f(pv[c], sMn[c]);
        } else {
            #pragma unroll
            for (int c = 0; c < CH; c++) mydp[c] = 0.f;
        }
        #pragma unroll
        for (int c = 0; c < CH; c++)
            dpv[c] = __shfl_sync(0xFFFFFFFFu, mydp[c], lane & ~1);
    }

    const float4* n4 = (const float4*)(g_neg + ((size_t)b * OH * OH + p) * 8);
    const float4* m4 = (const float4*)(g_mul + ((size_t)b * OH * OH + p) * 8);
    float ng[8], ml[8];
    float4 a0 = n4[0], a1 = n4[1];
    ng[0]=a0.x; ng[1]=a0.y; ng[2]=a0.z; ng[3]=a0.w; ng[4]=a1.x; ng[5]=a1.y; ng[6]=a1.z; ng[7]=a1.w;
    a0 = m4[0]; a1 = m4[1];
    ml[0]=a0.x; ml[1]=a0.y; ml[2]=a0.z; ml[3]=a0.w; ml[4]=a1.x; ml[5]=a1.y; ml[6]=a1.z; ml[7]=a1.w;

    float acc[3] = {sBo[0], sBo[1], sBo[2]};
    #pragma unroll
    for (int c = 0; c < CH; c++) {
        float xv = (dpv[c] + dln_f(ng[c], sMn[8 + c])) * dln_f(ml[c], sMn[16 + c]);
        #pragma unroll
        for (int o = 0; o < 3; o++) acc[o] += sWo[o * CH + c] * xv;
    }
    #pragma unroll
    for (int o = 0; o < 3; o++)
        out[((size_t)b * 3 + o) * OH * OH + p] = acc[o];
}

// ---------------- launcher ----------------
extern "C" void kernel_launch(void* const* d_in, const int* in_sizes, int n_in,
                              void* d_out, int out_size) {
    const int*   ids = (const int*)  d_in[0];
    const float* cc  = (const float*)d_in[1];
    const float* lat = (const float*)d_in[2];
    const float* Wr = (const float*)d_in[3];
    const float* Ur = (const float*)d_in[4];
    const float* Vr = (const float*)d_in[5];
    const float* Br = (const float*)d_in[6];
    const float* Wt = (const float*)d_in[7];
    const float* Ut = (const float*)d_in[8];
    const float* Vt = (const float*)d_in[9];
    const float* Bt = (const float*)d_in[10];
    const float* Wm = (const float*)d_in[11];
    const float* Um = (const float*)d_in[12];
    const float* Vm = (const float*)d_in[13];
    const float* Bm = (const float*)d_in[14];
    const float* Wo = (const float*)d_in[15];
    const float* Uo = (const float*)d_in[16];
    const float* Vo = (const float*)d_in[17];
    const float* Bo = (const float*)d_in[18];

    k_gather<<<64, 256>>>(ids, cc, lat);
    k_weights<<<dim3(13, 64), 128>>>(Wr, Ur, Vr, Br, Wt, Ut, Vt, Bt,
                                     Wm, Um, Vm, Bm, Wo, Uo, Vo, Bo);

    // stage 0: H=16 (TH=8)
    k_mma<16><<<dim3(1, 4, 192), 256>>>(0);
    k_combineP<16><<<dim3(4, 64), 256>>>(0);
    // stage 1: H=32 (TH=8)
    k_mma<32><<<dim3(2, 8, 192), 256>>>(1);
    k_combineP<32><<<dim3(16, 64), 256>>>(1);
    // stage 2: H=64 (TH=16)
    k_mma<64><<<dim3(4, 8, 192), 256>>>(2);
    k_combineP<64><<<dim3(64, 64), 256>>>(2);
    // stage 3: H=128 (TH=16)
    k_mma<128><<<dim3(8, 16, 192), 256>>>(3);
    k_comfinal<<<dim3(256, 64), 256>>>((float*)d_out);
}